// round 2
// baseline (speedup 1.0000x reference)
#include <cuda_runtime.h>
#include <mma.h>
#include <math_constants.h>

using namespace nvcuda;

// Problem dims (fixed by the reference)
#define B_   8
#define S_   1024
#define H_   1024
#define NH_  16
#define DH_  64
#define M_   (B_ * S_)   // 8192
#define N_   H_          // 1024
#define K_   H_          // 1024

// Scratch: device globals (no cudaMalloc allowed)
__device__ float g_qh[B_ * NH_ * S_ * DH_];   // [B,NH,S,DH]
__device__ float g_kh[B_ * NH_ * S_ * DH_];
__device__ float g_vh[B_ * NH_ * S_ * DH_];
__device__ float g_ctx[B_ * S_ * H_];         // merged [B,S,H]
__device__ unsigned char g_mask[B_ * S_];     // normalized: 1 = masked

// ---------------------------------------------------------------------------
// Mask dtype detection + normalization.
// The harness may pass the bool mask as uint8 / int32 / float32. Detect by
// the nonzero-byte residue signature of the first 8192 bytes (valid reads for
// every candidate width since element count is 8192):
//   uint8 bool : nonzero bytes spread over all residues mod 4
//   int32      : nonzero only at residue 0 (LSB of value 1)
//   float32    : 1.0f = 00 00 80 3f -> nonzero only at residues 2,3
// Then convert the full 8192 elements with the right stride. One block.
// ---------------------------------------------------------------------------
__global__ void mask_norm_kernel(const unsigned char* __restrict__ raw,
                                 unsigned char* __restrict__ outm)
{
    __shared__ int cnt[4];
    const int tid = threadIdx.x;
    if (tid < 4) cnt[tid] = 0;
    __syncthreads();

    int loc[4] = {0, 0, 0, 0};
    for (int i = tid; i < B_ * S_; i += blockDim.x)   // first 8192 bytes
        if (raw[i]) loc[i & 3]++;
    #pragma unroll
    for (int r = 0; r < 4; r++)
        if (loc[r]) atomicAdd(&cnt[r], loc[r]);
    __syncthreads();

    const int c0 = cnt[0], c1 = cnt[1], c2 = cnt[2], c3 = cnt[3];
    int mode;                       // 0 = uint8, 1 = int32, 2 = float32
    if (c0 > 0 && c1 == 0 && c2 == 0 && c3 == 0)      mode = 1;
    else if (c0 == 0 && c1 == 0 && (c2 > 0 || c3 > 0)) mode = 2;
    else                                               mode = 0;

    if (mode == 0) {
        for (int i = tid; i < B_ * S_; i += blockDim.x)
            outm[i] = raw[i] ? 1 : 0;
    } else if (mode == 1) {
        const int* p = (const int*)raw;
        for (int i = tid; i < B_ * S_; i += blockDim.x)
            outm[i] = p[i] ? 1 : 0;
    } else {
        const float* p = (const float*)raw;
        for (int i = tid; i < B_ * S_; i += blockDim.x)
            outm[i] = (p[i] != 0.0f) ? 1 : 0;
    }
}

// ---------------------------------------------------------------------------
// GEMM: C = A[M,K] @ W[N,K]^T + bias, TF32 wmma, fp32 accumulate.
// split_heads=1 writes C into [B,NH,S,DH] layout; else plain row-major [M,N].
// blockIdx.z selects one of up to 3 (A,W,bias,out) problem sets.
// ---------------------------------------------------------------------------
constexpr int BM = 128, BN = 128, BK = 32;
constexpr int GEMM_THREADS = 256;
constexpr int LDA = BK + 8;   // 40 floats, 16B-aligned rows, bank-stagger

__global__ __launch_bounds__(GEMM_THREADS, 2)
void gemm3_kernel(const float* __restrict__ A0, const float* __restrict__ W0,
                  const float* __restrict__ b0, float* __restrict__ o0,
                  const float* __restrict__ A1, const float* __restrict__ W1,
                  const float* __restrict__ b1, float* __restrict__ o1,
                  const float* __restrict__ A2, const float* __restrict__ W2,
                  const float* __restrict__ b2, float* __restrict__ o2,
                  int split_heads)
{
    __shared__ float As[BM][LDA];
    __shared__ float Ws[BN][LDA];

    const float* A; const float* W; const float* bias; float* out;
    if (blockIdx.z == 0)      { A = A0; W = W0; bias = b0; out = o0; }
    else if (blockIdx.z == 1) { A = A1; W = W1; bias = b1; out = o1; }
    else                      { A = A2; W = W2; bias = b2; out = o2; }

    const int tid  = threadIdx.x;
    const int warp = tid >> 5;
    const int wm   = warp >> 2;   // 0..1 (64-row slabs)
    const int wn   = warp & 3;    // 0..3 (32-col slabs)
    const int bm   = blockIdx.y * BM;
    const int bn   = blockIdx.x * BN;

    // Bias broadcast: 16 identical rows of bias[bn..bn+127], staged in As' memory.
    float* brep = &As[0][0];                 // needs 16*128 = 2048 floats <= 5120
    for (int i = tid; i < 16 * BN; i += GEMM_THREADS)
        brep[i] = bias[bn + (i & (BN - 1))];
    __syncthreads();

    wmma::fragment<wmma::accumulator, 16, 16, 8, float> acc[4][2];
    #pragma unroll
    for (int i = 0; i < 4; i++)
        #pragma unroll
        for (int j = 0; j < 2; j++)
            wmma::load_matrix_sync(acc[i][j], brep + wn * 32 + j * 16, BN,
                                   wmma::mem_row_major);
    __syncthreads();   // done reading brep before As is reused

    const float* Ap = A + bm * K_;
    const float* Wp = W + bn * K_;

    for (int k0 = 0; k0 < K_; k0 += BK) {
        // 128 rows x 32 cols each for A and W: 1024 float4 per tile, 4/thread
        #pragma unroll
        for (int i = 0; i < 4; i++) {
            int idx = tid + i * GEMM_THREADS;     // 0..1023
            int r = idx >> 3;
            int c = (idx & 7) << 2;
            float4 va = *reinterpret_cast<const float4*>(Ap + r * K_ + k0 + c);
            va.x = wmma::__float_to_tf32(va.x);
            va.y = wmma::__float_to_tf32(va.y);
            va.z = wmma::__float_to_tf32(va.z);
            va.w = wmma::__float_to_tf32(va.w);
            *reinterpret_cast<float4*>(&As[r][c]) = va;
            float4 vw = *reinterpret_cast<const float4*>(Wp + r * K_ + k0 + c);
            vw.x = wmma::__float_to_tf32(vw.x);
            vw.y = wmma::__float_to_tf32(vw.y);
            vw.z = wmma::__float_to_tf32(vw.z);
            vw.w = wmma::__float_to_tf32(vw.w);
            *reinterpret_cast<float4*>(&Ws[r][c]) = vw;
        }
        __syncthreads();

        #pragma unroll
        for (int kk = 0; kk < BK; kk += 8) {
            wmma::fragment<wmma::matrix_a, 16, 16, 8, wmma::precision::tf32,
                           wmma::row_major> af[4];
            wmma::fragment<wmma::matrix_b, 16, 16, 8, wmma::precision::tf32,
                           wmma::col_major> bf[2];
            #pragma unroll
            for (int i = 0; i < 4; i++)
                wmma::load_matrix_sync(af[i], &As[wm * 64 + i * 16][kk], LDA);
            #pragma unroll
            for (int j = 0; j < 2; j++)
                wmma::load_matrix_sync(bf[j], &Ws[wn * 32 + j * 16][kk], LDA);
            #pragma unroll
            for (int i = 0; i < 4; i++)
                #pragma unroll
                for (int j = 0; j < 2; j++)
                    wmma::mma_sync(acc[i][j], af[i], bf[j], acc[i][j]);
        }
        __syncthreads();
    }

    // Epilogue: store 16x16 tiles straight to global
    #pragma unroll
    for (int i = 0; i < 4; i++) {
        #pragma unroll
        for (int j = 0; j < 2; j++) {
            int row = bm + wm * 64 + i * 16;
            int col = bn + wn * 32 + j * 16;
            if (split_heads) {
                int b = row >> 10;          // / S_
                int s = row & (S_ - 1);
                int h = col >> 6;           // / DH_
                int d = col & (DH_ - 1);
                float* dst = out + (((b * NH_ + h) * S_) + s) * DH_ + d;
                wmma::store_matrix_sync(dst, acc[i][j], DH_, wmma::mem_row_major);
            } else {
                wmma::store_matrix_sync(out + row * N_ + col, acc[i][j], N_,
                                        wmma::mem_row_major);
            }
        }
    }
}

// ---------------------------------------------------------------------------
// Flash-style attention per (b,h): Q tile 64 rows, iterate K/V in 64-row tiles.
// scores = Q@K^T / 8, mask -> -1e9, online softmax, O += P@V, O /= l.
// 128 threads = 4 warps; warp w owns S/T rows [16w,16w+16).
// Scalar phases: thread t owns row t/2, 32-col half (t&1).
// ---------------------------------------------------------------------------
constexpr int ATTN_LD   = 72;                        // 64 + 8 pad
constexpr int ATTN_TILE = 64 * ATTN_LD;              // floats per smem tile
constexpr int ATTN_SMEM = 5 * ATTN_TILE * (int)sizeof(float);  // 92160 B

__global__ __launch_bounds__(128)
void attn_kernel(const float* __restrict__ qh, const float* __restrict__ kh,
                 const float* __restrict__ vh,
                 const unsigned char* __restrict__ mask,
                 float* __restrict__ ctx)
{
    extern __shared__ float smp[];
    float* Qs = smp;
    float* Ks = Qs + ATTN_TILE;
    float* Vs = Ks + ATTN_TILE;
    float* Ss = Vs + ATTN_TILE;
    float* Ts = Ss + ATTN_TILE;

    const int bh = blockIdx.x;          // b*NH + h
    const int qt = blockIdx.y;          // q tile
    const int b  = bh >> 4;
    const int h  = bh & (NH_ - 1);
    const int tid = threadIdx.x;
    const int w   = tid >> 5;

    const float* Q  = qh + bh * S_ * DH_ + qt * 64 * DH_;
    const float* Kp = kh + bh * S_ * DH_;
    const float* Vp = vh + bh * S_ * DH_;
    const unsigned char* mk = mask + b * S_;

    // Load Q tile once (tf32-rounded)
    #pragma unroll
    for (int i = 0; i < 8; i++) {
        int idx = tid + i * 128;          // 0..1023
        int r = idx >> 4;
        int c = (idx & 15) << 2;
        float4 v = *reinterpret_cast<const float4*>(Q + r * DH_ + c);
        v.x = wmma::__float_to_tf32(v.x);
        v.y = wmma::__float_to_tf32(v.y);
        v.z = wmma::__float_to_tf32(v.z);
        v.w = wmma::__float_to_tf32(v.w);
        *reinterpret_cast<float4*>(Qs + r * ATTN_LD + c) = v;
    }

    const int r  = tid >> 1;            // owned row 0..63
    const int ch = (tid & 1) * 32;      // owned column half
    float O[32];
    #pragma unroll
    for (int c = 0; c < 32; c++) O[c] = 0.f;
    float mrow = -CUDART_INF_F;
    float lrow = 0.f;

    for (int kt = 0; kt < S_ / 64; kt++) {
        // Load K,V tiles (tf32-rounded)
        #pragma unroll
        for (int i = 0; i < 8; i++) {
            int idx = tid + i * 128;
            int rr = idx >> 4;
            int cc = (idx & 15) << 2;
            const float* kp = Kp + (kt * 64 + rr) * DH_ + cc;
            const float* vp = Vp + (kt * 64 + rr) * DH_ + cc;
            float4 vk = *reinterpret_cast<const float4*>(kp);
            vk.x = wmma::__float_to_tf32(vk.x);
            vk.y = wmma::__float_to_tf32(vk.y);
            vk.z = wmma::__float_to_tf32(vk.z);
            vk.w = wmma::__float_to_tf32(vk.w);
            *reinterpret_cast<float4*>(Ks + rr * ATTN_LD + cc) = vk;
            float4 vv = *reinterpret_cast<const float4*>(vp);
            vv.x = wmma::__float_to_tf32(vv.x);
            vv.y = wmma::__float_to_tf32(vv.y);
            vv.z = wmma::__float_to_tf32(vv.z);
            vv.w = wmma::__float_to_tf32(vv.w);
            *reinterpret_cast<float4*>(Vs + rr * ATTN_LD + cc) = vv;
        }
        __syncthreads();

        // S = Q @ K^T  (warp w: rows 16w.., all 64 cols)
        {
            wmma::fragment<wmma::accumulator, 16, 16, 8, float> sacc[4];
            #pragma unroll
            for (int j = 0; j < 4; j++) wmma::fill_fragment(sacc[j], 0.f);
            #pragma unroll
            for (int d = 0; d < DH_; d += 8) {
                wmma::fragment<wmma::matrix_a, 16, 16, 8, wmma::precision::tf32,
                               wmma::row_major> af;
                wmma::load_matrix_sync(af, Qs + (w * 16) * ATTN_LD + d, ATTN_LD);
                #pragma unroll
                for (int j = 0; j < 4; j++) {
                    wmma::fragment<wmma::matrix_b, 16, 16, 8, wmma::precision::tf32,
                                   wmma::col_major> bf;
                    wmma::load_matrix_sync(bf, Ks + (j * 16) * ATTN_LD + d, ATTN_LD);
                    wmma::mma_sync(sacc[j], af, bf, sacc[j]);
                }
            }
            #pragma unroll
            for (int j = 0; j < 4; j++)
                wmma::store_matrix_sync(Ss + (w * 16) * ATTN_LD + j * 16, sacc[j],
                                        ATTN_LD, wmma::mem_row_major);
        }
        __syncthreads();

        // Online softmax (scalar, thread-pair per row)
        {
            float sv[32];
            float vmax = -CUDART_INF_F;
            #pragma unroll
            for (int c = 0; c < 32; c++) {
                int cc = ch + c;
                float s = Ss[r * ATTN_LD + cc] * 0.125f;
                if (mk[kt * 64 + cc]) s = -1e9f;
                sv[c] = s;
                vmax = fmaxf(vmax, s);
            }
            vmax = fmaxf(vmax, __shfl_xor_sync(0xffffffffu, vmax, 1));
            float mnew  = fmaxf(mrow, vmax);
            float alpha = __expf(mrow - mnew);   // exp(-inf)=0 first iter
            float psum = 0.f;
            #pragma unroll
            for (int c = 0; c < 32; c++) {
                float p = __expf(sv[c] - mnew);
                Ss[r * ATTN_LD + ch + c] = wmma::__float_to_tf32(p);
                psum += p;
            }
            psum += __shfl_xor_sync(0xffffffffu, psum, 1);
            lrow = lrow * alpha + psum;
            mrow = mnew;
            #pragma unroll
            for (int c = 0; c < 32; c++) O[c] *= alpha;
        }
        __syncthreads();

        // T = P @ V
        {
            wmma::fragment<wmma::accumulator, 16, 16, 8, float> tacc[4];
            #pragma unroll
            for (int j = 0; j < 4; j++) wmma::fill_fragment(tacc[j], 0.f);
            #pragma unroll
            for (int kk = 0; kk < 64; kk += 8) {
                wmma::fragment<wmma::matrix_a, 16, 16, 8, wmma::precision::tf32,
                               wmma::row_major> af;
                wmma::load_matrix_sync(af, Ss + (w * 16) * ATTN_LD + kk, ATTN_LD);
                #pragma unroll
                for (int j = 0; j < 4; j++) {
                    wmma::fragment<wmma::matrix_b, 16, 16, 8, wmma::precision::tf32,
                                   wmma::row_major> bf;
                    wmma::load_matrix_sync(bf, Vs + kk * ATTN_LD + j * 16, ATTN_LD);
                    wmma::mma_sync(tacc[j], af, bf, tacc[j]);
                }
            }
            #pragma unroll
            for (int j = 0; j < 4; j++)
                wmma::store_matrix_sync(Ts + (w * 16) * ATTN_LD + j * 16, tacc[j],
                                        ATTN_LD, wmma::mem_row_major);
        }
        __syncthreads();

        #pragma unroll
        for (int c = 0; c < 32; c++) O[c] += Ts[r * ATTN_LD + ch + c];
        // no barrier needed: next iter only writes Ks/Vs (disjoint), all prior
        // readers of Ks/Vs/Ss drained at the post-T-store barrier.
    }

    // Normalize and write merged ctx [B,S,H]
    float invl = 1.f / lrow;
    float* dst = ctx + (b * S_ + qt * 64 + r) * H_ + h * DH_ + ch;
    #pragma unroll
    for (int c = 0; c < 32; c++) dst[c] = O[c] * invl;
}

// ---------------------------------------------------------------------------
// Launch
// ---------------------------------------------------------------------------
extern "C" void kernel_launch(void* const* d_in, const int* in_sizes, int n_in,
                              void* d_out, int out_size)
{
    const float* v  = (const float*)d_in[0];
    const float* k  = (const float*)d_in[1];
    const float* q  = (const float*)d_in[2];
    const unsigned char* mask_raw = (const unsigned char*)d_in[3];
    const float* Wq = (const float*)d_in[4];
    const float* bq = (const float*)d_in[5];
    const float* Wk = (const float*)d_in[6];
    const float* bk = (const float*)d_in[7];
    const float* Wv = (const float*)d_in[8];
    const float* bv = (const float*)d_in[9];
    const float* Wm = (const float*)d_in[10];
    const float* bm = (const float*)d_in[11];
    float* out = (float*)d_out;

    float *qh, *kh, *vh, *ctx;
    unsigned char* mnorm;
    cudaGetSymbolAddress((void**)&qh,  g_qh);
    cudaGetSymbolAddress((void**)&kh,  g_kh);
    cudaGetSymbolAddress((void**)&vh,  g_vh);
    cudaGetSymbolAddress((void**)&ctx, g_ctx);
    cudaGetSymbolAddress((void**)&mnorm, g_mask);

    cudaFuncSetAttribute(attn_kernel, cudaFuncAttributeMaxDynamicSharedMemorySize,
                         ATTN_SMEM);

    // 0) normalize mask dtype (uint8 / int32 / float32 -> uint8)
    mask_norm_kernel<<<1, 256>>>(mask_raw, mnorm);

    // 1) fused QKV projections into split-head layout
    dim3 gproj(N_ / BN, M_ / BM, 3);
    gemm3_kernel<<<gproj, GEMM_THREADS>>>(q, Wq, bq, qh,
                                          k, Wk, bk, kh,
                                          v, Wv, bv, vh, 1);

    // 2) attention -> merged ctx
    dim3 gattn(B_ * NH_, S_ / 64);
    attn_kernel<<<gattn, 128, ATTN_SMEM>>>(qh, kh, vh, mnorm, ctx);

    // 3) output projection -> d_out
    dim3 gout(N_ / BN, M_ / BM, 1);
    gemm3_kernel<<<gout, GEMM_THREADS>>>(ctx, Wm, bm, out,
                                         ctx, Wm, bm, out,
                                         ctx, Wm, bm, out, 0);
}

// round 3
// speedup vs baseline: 1.2904x; 1.2904x over previous
#include <cuda_runtime.h>
#include <mma.h>
#include <math_constants.h>

using namespace nvcuda;

#define B_   8
#define S_   1024
#define H_   1024
#define NH_  16
#define DH_  64
#define M_   (B_ * S_)   // 8192
#define N_   H_
#define K_   H_

// Scratch: device globals (no cudaMalloc allowed)
__device__ float g_qh[B_ * NH_ * S_ * DH_];   // [B,NH,S,DH]
__device__ float g_kh[B_ * NH_ * S_ * DH_];
__device__ float g_vh[B_ * NH_ * S_ * DH_];
__device__ float g_ctx[B_ * S_ * H_];         // merged [B,S,H]
__device__ float g_maskf[B_ * S_];            // additive mask: 0 or -1e9

// ---------------------------------------------------------------------------
// Small PTX helpers
// ---------------------------------------------------------------------------
__device__ __forceinline__ unsigned f2tf(float f) {
    unsigned u;
    asm("cvt.rna.tf32.f32 %0, %1;" : "=r"(u) : "f"(f));
    return u;
}
__device__ __forceinline__ float f2tff(float f) {
    return __uint_as_float(f2tf(f));
}
__device__ __forceinline__ void mma8(float c[4], const unsigned a[4],
                                     unsigned b0, unsigned b1) {
    asm volatile(
        "mma.sync.aligned.m16n8k8.row.col.f32.tf32.tf32.f32 "
        "{%0,%1,%2,%3}, {%4,%5,%6,%7}, {%8,%9}, {%0,%1,%2,%3};"
        : "+f"(c[0]), "+f"(c[1]), "+f"(c[2]), "+f"(c[3])
        : "r"(a[0]), "r"(a[1]), "r"(a[2]), "r"(a[3]), "r"(b0), "r"(b1));
}
__device__ __forceinline__ void cp16(float* smem, const float* g) {
    unsigned s = (unsigned)__cvta_generic_to_shared(smem);
    asm volatile("cp.async.cg.shared.global [%0], [%1], 16;" :: "r"(s), "l"(g)
                 : "memory");
}
__device__ __forceinline__ void cp_commit() {
    asm volatile("cp.async.commit_group;" ::: "memory");
}
__device__ __forceinline__ void cp_wait_all() {
    asm volatile("cp.async.wait_group 0;" ::: "memory");
}

// ---------------------------------------------------------------------------
// Mask dtype detection + normalization -> additive float mask (0 / -1e9).
// (Residue-signature detection proven in R2.)
// ---------------------------------------------------------------------------
__global__ void mask_norm_kernel(const unsigned char* __restrict__ raw,
                                 float* __restrict__ outm)
{
    __shared__ int cnt[4];
    const int tid = threadIdx.x;
    if (tid < 4) cnt[tid] = 0;
    __syncthreads();

    int loc[4] = {0, 0, 0, 0};
    for (int i = tid; i < B_ * S_; i += blockDim.x)
        if (raw[i]) loc[i & 3]++;
    #pragma unroll
    for (int r = 0; r < 4; r++)
        if (loc[r]) atomicAdd(&cnt[r], loc[r]);
    __syncthreads();

    const int c0 = cnt[0], c1 = cnt[1], c2 = cnt[2], c3 = cnt[3];
    int mode;                       // 0 = uint8, 1 = int32, 2 = float32
    if (c0 > 0 && c1 == 0 && c2 == 0 && c3 == 0)       mode = 1;
    else if (c0 == 0 && c1 == 0 && (c2 > 0 || c3 > 0)) mode = 2;
    else                                               mode = 0;

    if (mode == 0) {
        for (int i = tid; i < B_ * S_; i += blockDim.x)
            outm[i] = raw[i] ? -1e9f : 0.f;
    } else if (mode == 1) {
        const int* p = (const int*)raw;
        for (int i = tid; i < B_ * S_; i += blockDim.x)
            outm[i] = p[i] ? -1e9f : 0.f;
    } else {
        const float* p = (const float*)raw;
        for (int i = tid; i < B_ * S_; i += blockDim.x)
            outm[i] = (p[i] != 0.0f) ? -1e9f : 0.f;
    }
}

// ---------------------------------------------------------------------------
// GEMM: C = A[M,K] @ W[N,K]^T + bias. TF32 wmma, fp32 accumulate.
// 2-stage cp.async pipeline; TF32 rounding applied in fragment registers.
// split_heads=1 writes [B,NH,S,DH]; else row-major [M,N].
// ---------------------------------------------------------------------------
constexpr int BM = 128, BN = 128, BK = 32;
constexpr int GEMM_THREADS = 256;
constexpr int LDA = BK + 8;                          // 40 floats
constexpr int STG_FLOATS = 2 * BM * LDA;             // As+Ws per stage = 10240
constexpr int GEMM_SMEM  = 2 * STG_FLOATS * (int)sizeof(float);   // 81920 B

__global__ __launch_bounds__(GEMM_THREADS, 2)
void gemm3_kernel(const float* __restrict__ A0, const float* __restrict__ W0,
                  const float* __restrict__ b0, float* __restrict__ o0,
                  const float* __restrict__ A1, const float* __restrict__ W1,
                  const float* __restrict__ b1, float* __restrict__ o1,
                  const float* __restrict__ A2, const float* __restrict__ W2,
                  const float* __restrict__ b2, float* __restrict__ o2,
                  int split_heads)
{
    extern __shared__ float gsm[];

    const float* A; const float* W; const float* bias; float* out;
    if (blockIdx.z == 0)      { A = A0; W = W0; bias = b0; out = o0; }
    else if (blockIdx.z == 1) { A = A1; W = W1; bias = b1; out = o1; }
    else                      { A = A2; W = W2; bias = b2; out = o2; }

    const int tid  = threadIdx.x;
    const int warp = tid >> 5;
    const int wm   = warp >> 2;   // 0..1
    const int wn   = warp & 3;    // 0..3
    const int bm   = blockIdx.y * BM;
    const int bn   = blockIdx.x * BN;

    // Bias broadcast staged in stage-0 memory before the pipeline starts.
    float* brep = gsm;                       // 16 x 128 floats
    for (int i = tid; i < 16 * BN; i += GEMM_THREADS)
        brep[i] = bias[bn + (i & (BN - 1))];
    __syncthreads();

    wmma::fragment<wmma::accumulator, 16, 16, 8, float> acc[4][2];
    #pragma unroll
    for (int i = 0; i < 4; i++)
        #pragma unroll
        for (int j = 0; j < 2; j++)
            wmma::load_matrix_sync(acc[i][j], brep + wn * 32 + j * 16, BN,
                                   wmma::mem_row_major);
    __syncthreads();

    const float* Ap = A + bm * K_;
    const float* Wp = W + bn * K_;

    auto preload = [&](int st, int k0) {
        float* As = gsm + st * STG_FLOATS;
        float* Ws = As + BM * LDA;
        #pragma unroll
        for (int i = 0; i < 4; i++) {
            int idx = tid + i * GEMM_THREADS;      // 0..1023
            int r = idx >> 3;
            int c = (idx & 7) << 2;
            cp16(As + r * LDA + c, Ap + r * K_ + k0 + c);
            cp16(Ws + r * LDA + c, Wp + r * K_ + k0 + c);
        }
        cp_commit();
    };

    preload(0, 0);

    for (int it = 0; it < K_ / BK; it++) {
        int cur = it & 1;
        cp_wait_all();
        __syncthreads();
        if (it + 1 < K_ / BK) preload(1 - cur, (it + 1) * BK);

        float* As = gsm + cur * STG_FLOATS;
        float* Ws = As + BM * LDA;

        #pragma unroll
        for (int kk = 0; kk < BK; kk += 8) {
            wmma::fragment<wmma::matrix_a, 16, 16, 8, wmma::precision::tf32,
                           wmma::row_major> af[4];
            wmma::fragment<wmma::matrix_b, 16, 16, 8, wmma::precision::tf32,
                           wmma::col_major> bf[2];
            #pragma unroll
            for (int i = 0; i < 4; i++) {
                wmma::load_matrix_sync(af[i], As + (wm * 64 + i * 16) * LDA + kk, LDA);
                #pragma unroll
                for (int e = 0; e < af[i].num_elements; e++)
                    af[i].x[e] = wmma::__float_to_tf32(af[i].x[e]);
            }
            #pragma unroll
            for (int j = 0; j < 2; j++) {
                wmma::load_matrix_sync(bf[j], Ws + (wn * 32 + j * 16) * LDA + kk, LDA);
                #pragma unroll
                for (int e = 0; e < bf[j].num_elements; e++)
                    bf[j].x[e] = wmma::__float_to_tf32(bf[j].x[e]);
            }
            #pragma unroll
            for (int i = 0; i < 4; i++)
                #pragma unroll
                for (int j = 0; j < 2; j++)
                    wmma::mma_sync(acc[i][j], af[i], bf[j], acc[i][j]);
        }
    }

    #pragma unroll
    for (int i = 0; i < 4; i++) {
        #pragma unroll
        for (int j = 0; j < 2; j++) {
            int row = bm + wm * 64 + i * 16;
            int col = bn + wn * 32 + j * 16;
            if (split_heads) {
                int b = row >> 10;
                int s = row & (S_ - 1);
                int h = col >> 6;
                int d = col & (DH_ - 1);
                float* dst = g_qh;   // placeholder; real target is 'out'
                dst = out + (((b * NH_ + h) * S_) + s) * DH_ + d;
                wmma::store_matrix_sync(dst, acc[i][j], DH_, wmma::mem_row_major);
            } else {
                wmma::store_matrix_sync(out + row * N_ + col, acc[i][j], N_,
                                        wmma::mem_row_major);
            }
        }
    }
}

// ---------------------------------------------------------------------------
// Flash attention, register-resident. Per block: (b,h) x 64 Q rows.
// 4 warps; warp w owns Q rows [16w,16w+16). mma.m16n8k8 tf32.
// Per-thread (g=lane>>2, q=lane&3): rows r0=16w+g and r0+8.
//   acc c[4]: rows {g,g,g+8,g+8}, cols {2q,2q+1} within each 8-col n-tile.
// S + softmax + O fully in registers; P transits warp-private smem rows.
// K/V double-buffered via cp.async. One __syncthreads per kt iteration.
// ---------------------------------------------------------------------------
constexpr int ALD = 68;                     // 64 + 4 pad (conflict-free)
constexpr int AT  = 64 * ALD;               // floats per tile
constexpr int ATTN_SMEM = 5 * AT * (int)sizeof(float);   // 87040 B

__global__ __launch_bounds__(128, 2)
void attn_kernel(const float* __restrict__ qh, const float* __restrict__ kh,
                 const float* __restrict__ vh,
                 const float* __restrict__ maskf,
                 float* __restrict__ ctx)
{
    extern __shared__ float sm[];
    float* QP = sm;            // Q tile, later reused for P
    float* Ks = sm + AT;       // [2][64][ALD]
    float* Vs = sm + 3 * AT;   // [2][64][ALD]

    const int bh = blockIdx.x;
    const int qt = blockIdx.y;
    const int b  = bh >> 4;
    const int h  = bh & (NH_ - 1);
    const int tid  = threadIdx.x;
    const int w    = tid >> 5;
    const int lane = tid & 31;
    const int g    = lane >> 2;
    const int q    = lane & 3;
    const int r0   = w * 16 + g;

    const float* Qg = qh + (bh * S_ + qt * 64) * DH_;
    const float* Kg = kh + bh * S_ * DH_;
    const float* Vg = vh + bh * S_ * DH_;
    const float* mrow = maskf + b * S_;

    // Load Q tile (raw fp32; rounding happens at fragment extraction)
    #pragma unroll
    for (int i = 0; i < 8; i++) {
        int idx = tid + i * 128;
        int r = idx >> 4;
        int c = (idx & 15) << 2;
        *reinterpret_cast<float4*>(QP + r * ALD + c) =
            *reinterpret_cast<const float4*>(Qg + r * DH_ + c);
    }
    __syncthreads();

    auto kv_load = [&](int st, int kt) {
        #pragma unroll
        for (int i = 0; i < 8; i++) {
            int idx = tid + i * 128;
            int r = idx >> 4;
            int c = (idx & 15) << 2;
            cp16(Ks + st * AT + r * ALD + c, Kg + (kt * 64 + r) * DH_ + c);
            cp16(Vs + st * AT + r * ALD + c, Vg + (kt * 64 + r) * DH_ + c);
        }
        cp_commit();
    };
    kv_load(0, 0);

    // Persistent Q fragments (tf32-rounded), 8 k-steps
    unsigned qa[8][4];
    #pragma unroll
    for (int ks = 0; ks < 8; ks++) {
        qa[ks][0] = f2tf(QP[r0 * ALD + ks * 8 + q]);
        qa[ks][1] = f2tf(QP[(r0 + 8) * ALD + ks * 8 + q]);
        qa[ks][2] = f2tf(QP[r0 * ALD + ks * 8 + q + 4]);
        qa[ks][3] = f2tf(QP[(r0 + 8) * ALD + ks * 8 + q + 4]);
    }
    __syncthreads();   // all Q reads done before QP is reused for P

    float oc[8][4];
    #pragma unroll
    for (int nt = 0; nt < 8; nt++)
        #pragma unroll
        for (int e = 0; e < 4; e++) oc[nt][e] = 0.f;
    float m0 = -CUDART_INF_F, m1 = -CUDART_INF_F;
    float l0 = 0.f, l1 = 0.f;

    for (int kt = 0; kt < S_ / 64; kt++) {
        const int cur = kt & 1;
        cp_wait_all();
        __syncthreads();                       // stage cur ready; prev readers done
        if (kt + 1 < S_ / 64) kv_load(1 - cur, kt + 1);

        const float* Kc = Ks + cur * AT;
        const float* Vc = Vs + cur * AT;

        // S = Q @ K^T (registers)
        float sc[8][4];
        #pragma unroll
        for (int nt = 0; nt < 8; nt++) {
            #pragma unroll
            for (int e = 0; e < 4; e++) sc[nt][e] = 0.f;
            #pragma unroll
            for (int ks = 0; ks < 8; ks++) {
                unsigned kb0 = f2tf(Kc[(nt * 8 + g) * ALD + ks * 8 + q]);
                unsigned kb1 = f2tf(Kc[(nt * 8 + g) * ALD + ks * 8 + q + 4]);
                mma8(sc[nt], qa[ks], kb0, kb1);
            }
        }

        // scale + additive mask + row max
        float vx0 = -CUDART_INF_F, vx1 = -CUDART_INF_F;
        #pragma unroll
        for (int nt = 0; nt < 8; nt++) {
            float2 mf = *reinterpret_cast<const float2*>(
                mrow + kt * 64 + nt * 8 + 2 * q);
            sc[nt][0] = sc[nt][0] * 0.125f + mf.x;
            sc[nt][1] = sc[nt][1] * 0.125f + mf.y;
            sc[nt][2] = sc[nt][2] * 0.125f + mf.x;
            sc[nt][3] = sc[nt][3] * 0.125f + mf.y;
            vx0 = fmaxf(vx0, fmaxf(sc[nt][0], sc[nt][1]));
            vx1 = fmaxf(vx1, fmaxf(sc[nt][2], sc[nt][3]));
        }
        vx0 = fmaxf(vx0, __shfl_xor_sync(0xffffffffu, vx0, 1));
        vx0 = fmaxf(vx0, __shfl_xor_sync(0xffffffffu, vx0, 2));
        vx1 = fmaxf(vx1, __shfl_xor_sync(0xffffffffu, vx1, 1));
        vx1 = fmaxf(vx1, __shfl_xor_sync(0xffffffffu, vx1, 2));

        float mn0 = fmaxf(m0, vx0), mn1 = fmaxf(m1, vx1);
        float al0 = __expf(m0 - mn0), al1 = __expf(m1 - mn1);

        __syncwarp();   // prior PV reads of QP rows done before P overwrite
        float ps0 = 0.f, ps1 = 0.f;
        #pragma unroll
        for (int nt = 0; nt < 8; nt++) {
            float p0 = __expf(sc[nt][0] - mn0);
            float p1 = __expf(sc[nt][1] - mn0);
            float p2 = __expf(sc[nt][2] - mn1);
            float p3 = __expf(sc[nt][3] - mn1);
            ps0 += p0 + p1;
            ps1 += p2 + p3;
            float2 v01 = make_float2(f2tff(p0), f2tff(p1));
            *reinterpret_cast<float2*>(QP + r0 * ALD + nt * 8 + 2 * q) = v01;
            float2 v23 = make_float2(f2tff(p2), f2tff(p3));
            *reinterpret_cast<float2*>(QP + (r0 + 8) * ALD + nt * 8 + 2 * q) = v23;
        }
        ps0 += __shfl_xor_sync(0xffffffffu, ps0, 1);
        ps0 += __shfl_xor_sync(0xffffffffu, ps0, 2);
        ps1 += __shfl_xor_sync(0xffffffffu, ps1, 1);
        ps1 += __shfl_xor_sync(0xffffffffu, ps1, 2);
        l0 = l0 * al0 + ps0;
        l1 = l1 * al1 + ps1;
        m0 = mn0; m1 = mn1;

        #pragma unroll
        for (int nt = 0; nt < 8; nt++) {
            oc[nt][0] *= al0; oc[nt][1] *= al0;
            oc[nt][2] *= al1; oc[nt][3] *= al1;
        }

        __syncwarp();   // P visible to warp before PV loads

        // O += P @ V
        #pragma unroll
        for (int ks = 0; ks < 8; ks++) {
            unsigned pa[4];
            pa[0] = __float_as_uint(QP[r0 * ALD + ks * 8 + q]);
            pa[1] = __float_as_uint(QP[(r0 + 8) * ALD + ks * 8 + q]);
            pa[2] = __float_as_uint(QP[r0 * ALD + ks * 8 + q + 4]);
            pa[3] = __float_as_uint(QP[(r0 + 8) * ALD + ks * 8 + q + 4]);
            #pragma unroll
            for (int nt = 0; nt < 8; nt++) {
                unsigned vb0 = f2tf(Vc[(ks * 8 + q) * ALD + nt * 8 + g]);
                unsigned vb1 = f2tf(Vc[(ks * 8 + q + 4) * ALD + nt * 8 + g]);
                mma8(oc[nt], pa, vb0, vb1);
            }
        }
    }

    // Normalize + write merged ctx [B,S,H]
    const float inv0 = 1.f / l0;
    const float inv1 = 1.f / l1;
    float* dst0 = ctx + (b * S_ + qt * 64 + r0) * H_ + h * DH_;
    float* dst1 = dst0 + 8 * H_;
    #pragma unroll
    for (int nt = 0; nt < 8; nt++) {
        float2 o01 = make_float2(oc[nt][0] * inv0, oc[nt][1] * inv0);
        *reinterpret_cast<float2*>(dst0 + nt * 8 + 2 * q) = o01;
        float2 o23 = make_float2(oc[nt][2] * inv1, oc[nt][3] * inv1);
        *reinterpret_cast<float2*>(dst1 + nt * 8 + 2 * q) = o23;
    }
}

// ---------------------------------------------------------------------------
// Launch
// ---------------------------------------------------------------------------
extern "C" void kernel_launch(void* const* d_in, const int* in_sizes, int n_in,
                              void* d_out, int out_size)
{
    const float* v  = (const float*)d_in[0];
    const float* k  = (const float*)d_in[1];
    const float* q  = (const float*)d_in[2];
    const unsigned char* mask_raw = (const unsigned char*)d_in[3];
    const float* Wq = (const float*)d_in[4];
    const float* bq = (const float*)d_in[5];
    const float* Wk = (const float*)d_in[6];
    const float* bk = (const float*)d_in[7];
    const float* Wv = (const float*)d_in[8];
    const float* bv = (const float*)d_in[9];
    const float* Wm = (const float*)d_in[10];
    const float* bm = (const float*)d_in[11];
    float* out = (float*)d_out;

    float *qh, *kh, *vh, *ctx, *mnorm;
    cudaGetSymbolAddress((void**)&qh,  g_qh);
    cudaGetSymbolAddress((void**)&kh,  g_kh);
    cudaGetSymbolAddress((void**)&vh,  g_vh);
    cudaGetSymbolAddress((void**)&ctx, g_ctx);
    cudaGetSymbolAddress((void**)&mnorm, g_maskf);

    cudaFuncSetAttribute(gemm3_kernel, cudaFuncAttributeMaxDynamicSharedMemorySize,
                         GEMM_SMEM);
    cudaFuncSetAttribute(attn_kernel, cudaFuncAttributeMaxDynamicSharedMemorySize,
                         ATTN_SMEM);

    // 0) normalize mask dtype -> additive float mask
    mask_norm_kernel<<<1, 256>>>(mask_raw, mnorm);

    // 1) fused QKV projections into split-head layout
    dim3 gproj(N_ / BN, M_ / BM, 3);
    gemm3_kernel<<<gproj, GEMM_THREADS, GEMM_SMEM>>>(q, Wq, bq, qh,
                                                     k, Wk, bk, kh,
                                                     v, Wv, bv, vh, 1);

    // 2) attention -> merged ctx
    dim3 gattn(B_ * NH_, S_ / 64);
    attn_kernel<<<gattn, 128, ATTN_SMEM>>>(qh, kh, vh, mnorm, ctx);

    // 3) output projection -> d_out
    dim3 gout(N_ / BN, M_ / BM, 1);
    gemm3_kernel<<<gout, GEMM_THREADS, GEMM_SMEM>>>(ctx, Wm, bm, out,
                                                    ctx, Wm, bm, out,
                                                    ctx, Wm, bm, out, 0);
}

// round 4
// speedup vs baseline: 1.3023x; 1.0092x over previous
#include <cuda_runtime.h>
#include <mma.h>
#include <math_constants.h>

using namespace nvcuda;

#define B_   8
#define S_   1024
#define H_   1024
#define NH_  16
#define DH_  64
#define M_   (B_ * S_)   // 8192
#define N_   H_
#define K_   H_

// Scratch: device globals (no cudaMalloc allowed)
__device__ float g_qh[B_ * NH_ * S_ * DH_];   // [B,NH,S,DH] (tf32-rounded)
__device__ float g_kh[B_ * NH_ * S_ * DH_];
__device__ float g_vh[B_ * NH_ * S_ * DH_];
__device__ float g_ctx[B_ * S_ * H_];         // merged [B,S,H] (tf32-rounded)
__device__ float g_maskf[B_ * S_];            // additive mask: 0 or -1e9
// tf32-rounded copies of inputs
__device__ float g_qc[M_ * K_];
__device__ float g_kc[M_ * K_];
__device__ float g_vc[M_ * K_];
__device__ float g_wq[H_ * H_];
__device__ float g_wk[H_ * H_];
__device__ float g_wv[H_ * H_];
__device__ float g_wm[H_ * H_];

// ---------------------------------------------------------------------------
// PTX helpers
// ---------------------------------------------------------------------------
__device__ __forceinline__ unsigned f2tf(float f) {
    unsigned u;
    asm("cvt.rna.tf32.f32 %0, %1;" : "=r"(u) : "f"(f));
    return u;
}
__device__ __forceinline__ float f2tff(float f) {
    return __uint_as_float(f2tf(f));
}
__device__ __forceinline__ void mma8(float c[4], const unsigned a[4],
                                     unsigned b0, unsigned b1) {
    asm volatile(
        "mma.sync.aligned.m16n8k8.row.col.f32.tf32.tf32.f32 "
        "{%0,%1,%2,%3}, {%4,%5,%6,%7}, {%8,%9}, {%0,%1,%2,%3};"
        : "+f"(c[0]), "+f"(c[1]), "+f"(c[2]), "+f"(c[3])
        : "r"(a[0]), "r"(a[1]), "r"(a[2]), "r"(a[3]), "r"(b0), "r"(b1));
}
__device__ __forceinline__ void cp16(float* smem, const float* g) {
    unsigned s = (unsigned)__cvta_generic_to_shared(smem);
    asm volatile("cp.async.cg.shared.global [%0], [%1], 16;" :: "r"(s), "l"(g)
                 : "memory");
}
__device__ __forceinline__ void cp_commit() {
    asm volatile("cp.async.commit_group;" ::: "memory");
}
__device__ __forceinline__ void cp_wait_all() {
    asm volatile("cp.async.wait_group 0;" ::: "memory");
}

// ---------------------------------------------------------------------------
// TF32 pre-rounding: out[i] = round_rna_tf32(in[i]) (as fp32 bits)
// ---------------------------------------------------------------------------
__global__ void cvt_tf32_kernel(const float* __restrict__ in,
                                float* __restrict__ out, int n4)
{
    int i = blockIdx.x * blockDim.x + threadIdx.x;
    if (i < n4) {
        float4 v = reinterpret_cast<const float4*>(in)[i];
        v.x = f2tff(v.x); v.y = f2tff(v.y);
        v.z = f2tff(v.z); v.w = f2tff(v.w);
        reinterpret_cast<float4*>(out)[i] = v;
    }
}

// ---------------------------------------------------------------------------
// Mask dtype detection + normalization -> additive float mask (0 / -1e9).
// ---------------------------------------------------------------------------
__global__ void mask_norm_kernel(const unsigned char* __restrict__ raw,
                                 float* __restrict__ outm)
{
    __shared__ int cnt[4];
    const int tid = threadIdx.x;
    if (tid < 4) cnt[tid] = 0;
    __syncthreads();

    int loc[4] = {0, 0, 0, 0};
    for (int i = tid; i < B_ * S_; i += blockDim.x)
        if (raw[i]) loc[i & 3]++;
    #pragma unroll
    for (int r = 0; r < 4; r++)
        if (loc[r]) atomicAdd(&cnt[r], loc[r]);
    __syncthreads();

    const int c0 = cnt[0], c1 = cnt[1], c2 = cnt[2], c3 = cnt[3];
    int mode;                       // 0 = uint8, 1 = int32, 2 = float32
    if (c0 > 0 && c1 == 0 && c2 == 0 && c3 == 0)       mode = 1;
    else if (c0 == 0 && c1 == 0 && (c2 > 0 || c3 > 0)) mode = 2;
    else                                               mode = 0;

    if (mode == 0) {
        for (int i = tid; i < B_ * S_; i += blockDim.x)
            outm[i] = raw[i] ? -1e9f : 0.f;
    } else if (mode == 1) {
        const int* p = (const int*)raw;
        for (int i = tid; i < B_ * S_; i += blockDim.x)
            outm[i] = p[i] ? -1e9f : 0.f;
    } else {
        const float* p = (const float*)raw;
        for (int i = tid; i < B_ * S_; i += blockDim.x)
            outm[i] = (p[i] != 0.0f) ? -1e9f : 0.f;
    }
}

// ---------------------------------------------------------------------------
// GEMM: C = A[M,K] @ W[N,K]^T + bias. Inputs pre-rounded to tf32 -> mainloop
// has zero cvt. split_heads=1 writes [B,NH,S,DH] with tf32-rounded values;
// else raw fp32 row-major [M,N].
// ---------------------------------------------------------------------------
constexpr int BM = 128, BN = 128, BK = 32;
constexpr int GEMM_THREADS = 256;
constexpr int LDA = BK + 8;                          // 40 floats
constexpr int STG_FLOATS = 2 * BM * LDA;             // As+Ws per stage = 10240
constexpr int GEMM_SMEM  = 2 * STG_FLOATS * (int)sizeof(float);   // 81920 B

__global__ __launch_bounds__(GEMM_THREADS, 2)
void gemm3_kernel(const float* __restrict__ A0, const float* __restrict__ W0,
                  const float* __restrict__ b0, float* __restrict__ o0,
                  const float* __restrict__ A1, const float* __restrict__ W1,
                  const float* __restrict__ b1, float* __restrict__ o1,
                  const float* __restrict__ A2, const float* __restrict__ W2,
                  const float* __restrict__ b2, float* __restrict__ o2,
                  int split_heads)
{
    extern __shared__ float gsm[];

    const float* A; const float* W; const float* bias; float* out;
    if (blockIdx.z == 0)      { A = A0; W = W0; bias = b0; out = o0; }
    else if (blockIdx.z == 1) { A = A1; W = W1; bias = b1; out = o1; }
    else                      { A = A2; W = W2; bias = b2; out = o2; }

    const int tid  = threadIdx.x;
    const int warp = tid >> 5;
    const int wm   = warp >> 2;   // 0..1
    const int wn   = warp & 3;    // 0..3
    const int bm   = blockIdx.y * BM;
    const int bn   = blockIdx.x * BN;

    // Bias broadcast staged in stage-0 memory before the pipeline starts.
    float* brep = gsm;                       // 16 x 128 floats
    for (int i = tid; i < 16 * BN; i += GEMM_THREADS)
        brep[i] = bias[bn + (i & (BN - 1))];
    __syncthreads();

    wmma::fragment<wmma::accumulator, 16, 16, 8, float> acc[4][2];
    #pragma unroll
    for (int i = 0; i < 4; i++)
        #pragma unroll
        for (int j = 0; j < 2; j++)
            wmma::load_matrix_sync(acc[i][j], brep + wn * 32 + j * 16, BN,
                                   wmma::mem_row_major);
    __syncthreads();

    const float* Ap = A + bm * K_;
    const float* Wp = W + bn * K_;

    auto preload = [&](int st, int k0) {
        float* As = gsm + st * STG_FLOATS;
        float* Ws = As + BM * LDA;
        #pragma unroll
        for (int i = 0; i < 4; i++) {
            int idx = tid + i * GEMM_THREADS;      // 0..1023
            int r = idx >> 3;
            int c = (idx & 7) << 2;
            cp16(As + r * LDA + c, Ap + r * K_ + k0 + c);
            cp16(Ws + r * LDA + c, Wp + r * K_ + k0 + c);
        }
        cp_commit();
    };

    preload(0, 0);

    for (int it = 0; it < K_ / BK; it++) {
        int cur = it & 1;
        cp_wait_all();
        __syncthreads();
        if (it + 1 < K_ / BK) preload(1 - cur, (it + 1) * BK);

        float* As = gsm + cur * STG_FLOATS;
        float* Ws = As + BM * LDA;

        #pragma unroll
        for (int kk = 0; kk < BK; kk += 8) {
            wmma::fragment<wmma::matrix_a, 16, 16, 8, wmma::precision::tf32,
                           wmma::row_major> af[4];
            wmma::fragment<wmma::matrix_b, 16, 16, 8, wmma::precision::tf32,
                           wmma::col_major> bf[2];
            #pragma unroll
            for (int i = 0; i < 4; i++)
                wmma::load_matrix_sync(af[i], As + (wm * 64 + i * 16) * LDA + kk, LDA);
            #pragma unroll
            for (int j = 0; j < 2; j++)
                wmma::load_matrix_sync(bf[j], Ws + (wn * 32 + j * 16) * LDA + kk, LDA);
            #pragma unroll
            for (int i = 0; i < 4; i++)
                #pragma unroll
                for (int j = 0; j < 2; j++)
                    wmma::mma_sync(acc[i][j], af[i], bf[j], acc[i][j]);
        }
    }

    #pragma unroll
    for (int i = 0; i < 4; i++) {
        #pragma unroll
        for (int j = 0; j < 2; j++) {
            int row = bm + wm * 64 + i * 16;
            int col = bn + wn * 32 + j * 16;
            if (split_heads) {
                // round once here so downstream attention needs no cvt
                #pragma unroll
                for (int e = 0; e < acc[i][j].num_elements; e++)
                    acc[i][j].x[e] = f2tff(acc[i][j].x[e]);
                int b = row >> 10;
                int s = row & (S_ - 1);
                int h = col >> 6;
                int d = col & (DH_ - 1);
                float* dst = out + (((b * NH_ + h) * S_) + s) * DH_ + d;
                wmma::store_matrix_sync(dst, acc[i][j], DH_, wmma::mem_row_major);
            } else {
                wmma::store_matrix_sync(out + row * N_ + col, acc[i][j], N_,
                                        wmma::mem_row_major);
            }
        }
    }
}

// ---------------------------------------------------------------------------
// Flash attention, register-resident, cvt-free mainloop (inputs pre-rounded).
// 4 warps; warp w owns Q rows [16w,16w+16). mma.m16n8k8 tf32.
// ---------------------------------------------------------------------------
constexpr int ALD = 68;                     // 64 + 4 pad
constexpr int AT  = 64 * ALD;
constexpr int ATTN_SMEM = 5 * AT * (int)sizeof(float);   // 87040 B

__global__ __launch_bounds__(128, 2)
void attn_kernel(const float* __restrict__ qh, const float* __restrict__ kh,
                 const float* __restrict__ vh,
                 const float* __restrict__ maskf,
                 float* __restrict__ ctx)
{
    extern __shared__ float sm[];
    float* QP = sm;            // Q tile, later reused for P
    float* Ks = sm + AT;       // [2][64][ALD]
    float* Vs = sm + 3 * AT;   // [2][64][ALD]

    const int bh = blockIdx.x;
    const int qt = blockIdx.y;
    const int b  = bh >> 4;
    const int h  = bh & (NH_ - 1);
    const int tid  = threadIdx.x;
    const int w    = tid >> 5;
    const int lane = tid & 31;
    const int g    = lane >> 2;
    const int q    = lane & 3;
    const int r0   = w * 16 + g;

    const float* Qg = qh + (bh * S_ + qt * 64) * DH_;
    const float* Kg = kh + bh * S_ * DH_;
    const float* Vg = vh + bh * S_ * DH_;
    const float* mrow = maskf + b * S_;

    #pragma unroll
    for (int i = 0; i < 8; i++) {
        int idx = tid + i * 128;
        int r = idx >> 4;
        int c = (idx & 15) << 2;
        *reinterpret_cast<float4*>(QP + r * ALD + c) =
            *reinterpret_cast<const float4*>(Qg + r * DH_ + c);
    }
    __syncthreads();

    auto kv_load = [&](int st, int kt) {
        #pragma unroll
        for (int i = 0; i < 8; i++) {
            int idx = tid + i * 128;
            int r = idx >> 4;
            int c = (idx & 15) << 2;
            cp16(Ks + st * AT + r * ALD + c, Kg + (kt * 64 + r) * DH_ + c);
            cp16(Vs + st * AT + r * ALD + c, Vg + (kt * 64 + r) * DH_ + c);
        }
        cp_commit();
    };
    kv_load(0, 0);

    // Persistent Q fragments (already tf32-rounded bits)
    unsigned qa[8][4];
    #pragma unroll
    for (int ks = 0; ks < 8; ks++) {
        qa[ks][0] = __float_as_uint(QP[r0 * ALD + ks * 8 + q]);
        qa[ks][1] = __float_as_uint(QP[(r0 + 8) * ALD + ks * 8 + q]);
        qa[ks][2] = __float_as_uint(QP[r0 * ALD + ks * 8 + q + 4]);
        qa[ks][3] = __float_as_uint(QP[(r0 + 8) * ALD + ks * 8 + q + 4]);
    }
    __syncthreads();   // all Q reads done before QP is reused for P

    float oc[8][4];
    #pragma unroll
    for (int nt = 0; nt < 8; nt++)
        #pragma unroll
        for (int e = 0; e < 4; e++) oc[nt][e] = 0.f;
    float m0 = -CUDART_INF_F, m1 = -CUDART_INF_F;
    float l0 = 0.f, l1 = 0.f;

    for (int kt = 0; kt < S_ / 64; kt++) {
        const int cur = kt & 1;
        cp_wait_all();
        __syncthreads();
        if (kt + 1 < S_ / 64) kv_load(1 - cur, kt + 1);

        const float* Kc = Ks + cur * AT;
        const float* Vc = Vs + cur * AT;

        // S = Q @ K^T
        float sc[8][4];
        #pragma unroll
        for (int nt = 0; nt < 8; nt++) {
            #pragma unroll
            for (int e = 0; e < 4; e++) sc[nt][e] = 0.f;
            #pragma unroll
            for (int ks = 0; ks < 8; ks++) {
                unsigned kb0 = __float_as_uint(Kc[(nt * 8 + g) * ALD + ks * 8 + q]);
                unsigned kb1 = __float_as_uint(Kc[(nt * 8 + g) * ALD + ks * 8 + q + 4]);
                mma8(sc[nt], qa[ks], kb0, kb1);
            }
        }

        // scale + additive mask + row max
        float vx0 = -CUDART_INF_F, vx1 = -CUDART_INF_F;
        #pragma unroll
        for (int nt = 0; nt < 8; nt++) {
            float2 mf = *reinterpret_cast<const float2*>(
                mrow + kt * 64 + nt * 8 + 2 * q);
            sc[nt][0] = sc[nt][0] * 0.125f + mf.x;
            sc[nt][1] = sc[nt][1] * 0.125f + mf.y;
            sc[nt][2] = sc[nt][2] * 0.125f + mf.x;
            sc[nt][3] = sc[nt][3] * 0.125f + mf.y;
            vx0 = fmaxf(vx0, fmaxf(sc[nt][0], sc[nt][1]));
            vx1 = fmaxf(vx1, fmaxf(sc[nt][2], sc[nt][3]));
        }
        vx0 = fmaxf(vx0, __shfl_xor_sync(0xffffffffu, vx0, 1));
        vx0 = fmaxf(vx0, __shfl_xor_sync(0xffffffffu, vx0, 2));
        vx1 = fmaxf(vx1, __shfl_xor_sync(0xffffffffu, vx1, 1));
        vx1 = fmaxf(vx1, __shfl_xor_sync(0xffffffffu, vx1, 2));

        float mn0 = fmaxf(m0, vx0), mn1 = fmaxf(m1, vx1);
        float al0 = __expf(m0 - mn0), al1 = __expf(m1 - mn1);

        __syncwarp();
        float ps0 = 0.f, ps1 = 0.f;
        #pragma unroll
        for (int nt = 0; nt < 8; nt++) {
            float p0 = __expf(sc[nt][0] - mn0);
            float p1 = __expf(sc[nt][1] - mn0);
            float p2 = __expf(sc[nt][2] - mn1);
            float p3 = __expf(sc[nt][3] - mn1);
            ps0 += p0 + p1;
            ps1 += p2 + p3;
            float2 v01 = make_float2(f2tff(p0), f2tff(p1));
            *reinterpret_cast<float2*>(QP + r0 * ALD + nt * 8 + 2 * q) = v01;
            float2 v23 = make_float2(f2tff(p2), f2tff(p3));
            *reinterpret_cast<float2*>(QP + (r0 + 8) * ALD + nt * 8 + 2 * q) = v23;
        }
        ps0 += __shfl_xor_sync(0xffffffffu, ps0, 1);
        ps0 += __shfl_xor_sync(0xffffffffu, ps0, 2);
        ps1 += __shfl_xor_sync(0xffffffffu, ps1, 1);
        ps1 += __shfl_xor_sync(0xffffffffu, ps1, 2);
        l0 = l0 * al0 + ps0;
        l1 = l1 * al1 + ps1;
        m0 = mn0; m1 = mn1;

        #pragma unroll
        for (int nt = 0; nt < 8; nt++) {
            oc[nt][0] *= al0; oc[nt][1] *= al0;
            oc[nt][2] *= al1; oc[nt][3] *= al1;
        }

        __syncwarp();

        // O += P @ V
        #pragma unroll
        for (int ks = 0; ks < 8; ks++) {
            unsigned pa[4];
            pa[0] = __float_as_uint(QP[r0 * ALD + ks * 8 + q]);
            pa[1] = __float_as_uint(QP[(r0 + 8) * ALD + ks * 8 + q]);
            pa[2] = __float_as_uint(QP[r0 * ALD + ks * 8 + q + 4]);
            pa[3] = __float_as_uint(QP[(r0 + 8) * ALD + ks * 8 + q + 4]);
            #pragma unroll
            for (int nt = 0; nt < 8; nt++) {
                unsigned vb0 = __float_as_uint(Vc[(ks * 8 + q) * ALD + nt * 8 + g]);
                unsigned vb1 = __float_as_uint(Vc[(ks * 8 + q + 4) * ALD + nt * 8 + g]);
                mma8(oc[nt], pa, vb0, vb1);
            }
        }
    }

    // Normalize + write merged ctx [B,S,H], tf32-rounded for the next GEMM
    const float inv0 = 1.f / l0;
    const float inv1 = 1.f / l1;
    float* dst0 = ctx + (b * S_ + qt * 64 + r0) * H_ + h * DH_;
    float* dst1 = dst0 + 8 * H_;
    #pragma unroll
    for (int nt = 0; nt < 8; nt++) {
        float2 o01 = make_float2(f2tff(oc[nt][0] * inv0), f2tff(oc[nt][1] * inv0));
        *reinterpret_cast<float2*>(dst0 + nt * 8 + 2 * q) = o01;
        float2 o23 = make_float2(f2tff(oc[nt][2] * inv1), f2tff(oc[nt][3] * inv1));
        *reinterpret_cast<float2*>(dst1 + nt * 8 + 2 * q) = o23;
    }
}

// ---------------------------------------------------------------------------
// Launch
// ---------------------------------------------------------------------------
extern "C" void kernel_launch(void* const* d_in, const int* in_sizes, int n_in,
                              void* d_out, int out_size)
{
    const float* v  = (const float*)d_in[0];
    const float* k  = (const float*)d_in[1];
    const float* q  = (const float*)d_in[2];
    const unsigned char* mask_raw = (const unsigned char*)d_in[3];
    const float* Wq = (const float*)d_in[4];
    const float* bq = (const float*)d_in[5];
    const float* Wk = (const float*)d_in[6];
    const float* bk = (const float*)d_in[7];
    const float* Wv = (const float*)d_in[8];
    const float* bv = (const float*)d_in[9];
    const float* Wm = (const float*)d_in[10];
    const float* bm = (const float*)d_in[11];
    float* out = (float*)d_out;

    float *qh, *kh, *vh, *ctx, *mnorm;
    float *qc, *kc, *vc, *wq, *wk, *wv, *wm;
    cudaGetSymbolAddress((void**)&qh,  g_qh);
    cudaGetSymbolAddress((void**)&kh,  g_kh);
    cudaGetSymbolAddress((void**)&vh,  g_vh);
    cudaGetSymbolAddress((void**)&ctx, g_ctx);
    cudaGetSymbolAddress((void**)&mnorm, g_maskf);
    cudaGetSymbolAddress((void**)&qc, g_qc);
    cudaGetSymbolAddress((void**)&kc, g_kc);
    cudaGetSymbolAddress((void**)&vc, g_vc);
    cudaGetSymbolAddress((void**)&wq, g_wq);
    cudaGetSymbolAddress((void**)&wk, g_wk);
    cudaGetSymbolAddress((void**)&wv, g_wv);
    cudaGetSymbolAddress((void**)&wm, g_wm);

    cudaFuncSetAttribute(gemm3_kernel, cudaFuncAttributeMaxDynamicSharedMemorySize,
                         GEMM_SMEM);
    cudaFuncSetAttribute(attn_kernel, cudaFuncAttributeMaxDynamicSharedMemorySize,
                         ATTN_SMEM);

    // 0) mask + tf32 pre-rounding of all GEMM inputs
    mask_norm_kernel<<<1, 256>>>(mask_raw, mnorm);
    const int big4 = (M_ * K_) / 4, small4 = (H_ * H_) / 4;
    cvt_tf32_kernel<<<(big4 + 255) / 256, 256>>>(q, qc, big4);
    cvt_tf32_kernel<<<(big4 + 255) / 256, 256>>>(k, kc, big4);
    cvt_tf32_kernel<<<(big4 + 255) / 256, 256>>>(v, vc, big4);
    cvt_tf32_kernel<<<(small4 + 255) / 256, 256>>>(Wq, wq, small4);
    cvt_tf32_kernel<<<(small4 + 255) / 256, 256>>>(Wk, wk, small4);
    cvt_tf32_kernel<<<(small4 + 255) / 256, 256>>>(Wv, wv, small4);
    cvt_tf32_kernel<<<(small4 + 255) / 256, 256>>>(Wm, wm, small4);

    // 1) fused QKV projections into split-head layout (outputs tf32-rounded)
    dim3 gproj(N_ / BN, M_ / BM, 3);
    gemm3_kernel<<<gproj, GEMM_THREADS, GEMM_SMEM>>>(qc, wq, bq, qh,
                                                     kc, wk, bk, kh,
                                                     vc, wv, bv, vh, 1);

    // 2) attention -> merged ctx (tf32-rounded)
    dim3 gattn(B_ * NH_, S_ / 64);
    attn_kernel<<<gattn, 128, ATTN_SMEM>>>(qh, kh, vh, mnorm, ctx);

    // 3) output projection -> d_out (raw fp32)
    dim3 gout(N_ / BN, M_ / BM, 1);
    gemm3_kernel<<<gout, GEMM_THREADS, GEMM_SMEM>>>(ctx, wm, bm, out,
                                                    ctx, wm, bm, out,
                                                    ctx, wm, bm, out, 0);
}

// round 6
// speedup vs baseline: 2.1140x; 1.6233x over previous
#include <cuda_runtime.h>
#include <math_constants.h>

#define B_   8
#define S_   1024
#define H_   1024
#define NH_  16
#define DH_  64
#define M_   (B_ * S_)   // 8192
#define N_   H_
#define K_   H_

// Scratch: device globals (no cudaMalloc allowed)
__device__ float g_qh[B_ * NH_ * S_ * DH_];   // [B,NH,S,DH] (tf32-rounded)
__device__ float g_kh[B_ * NH_ * S_ * DH_];
__device__ float g_vh[B_ * NH_ * S_ * DH_];
__device__ float g_ctx[B_ * S_ * H_];         // merged [B,S,H] (tf32-rounded)
__device__ float g_maskf[B_ * S_];            // additive mask: 0 or -1e9
// tf32-rounded copies of inputs
__device__ float g_qc[M_ * K_];
__device__ float g_kc[M_ * K_];
__device__ float g_vc[M_ * K_];
__device__ float g_wq[H_ * H_];
__device__ float g_wk[H_ * H_];
__device__ float g_wv[H_ * H_];
__device__ float g_wm[H_ * H_];

// ---------------------------------------------------------------------------
// PTX helpers
// ---------------------------------------------------------------------------
__device__ __forceinline__ unsigned f2tf(float f) {
    unsigned u;
    asm("cvt.rna.tf32.f32 %0, %1;" : "=r"(u) : "f"(f));
    return u;
}
__device__ __forceinline__ float f2tff(float f) {
    return __uint_as_float(f2tf(f));
}
__device__ __forceinline__ void mma8(float c[4], const unsigned a[4],
                                     unsigned b0, unsigned b1) {
    asm volatile(
        "mma.sync.aligned.m16n8k8.row.col.f32.tf32.tf32.f32 "
        "{%0,%1,%2,%3}, {%4,%5,%6,%7}, {%8,%9}, {%0,%1,%2,%3};"
        : "+f"(c[0]), "+f"(c[1]), "+f"(c[2]), "+f"(c[3])
        : "r"(a[0]), "r"(a[1]), "r"(a[2]), "r"(a[3]), "r"(b0), "r"(b1));
}
__device__ __forceinline__ void cp16(float* smem, const float* g) {
    unsigned s = (unsigned)__cvta_generic_to_shared(smem);
    asm volatile("cp.async.cg.shared.global [%0], [%1], 16;" :: "r"(s), "l"(g)
                 : "memory");
}
__device__ __forceinline__ void cp_commit() {
    asm volatile("cp.async.commit_group;" ::: "memory");
}
__device__ __forceinline__ void cp_wait_all() {
    asm volatile("cp.async.wait_group 0;" ::: "memory");
}

// ---------------------------------------------------------------------------
// TF32 pre-rounding
// ---------------------------------------------------------------------------
__global__ void cvt_tf32_kernel(const float* __restrict__ in,
                                float* __restrict__ out, int n4)
{
    int i = blockIdx.x * blockDim.x + threadIdx.x;
    if (i < n4) {
        float4 v = reinterpret_cast<const float4*>(in)[i];
        v.x = f2tff(v.x); v.y = f2tff(v.y);
        v.z = f2tff(v.z); v.w = f2tff(v.w);
        reinterpret_cast<float4*>(out)[i] = v;
    }
}

// ---------------------------------------------------------------------------
// Mask dtype detection + normalization -> additive float mask (0 / -1e9).
// ---------------------------------------------------------------------------
__global__ void mask_norm_kernel(const unsigned char* __restrict__ raw,
                                 float* __restrict__ outm)
{
    __shared__ int cnt[4];
    const int tid = threadIdx.x;
    if (tid < 4) cnt[tid] = 0;
    __syncthreads();

    int loc[4] = {0, 0, 0, 0};
    for (int i = tid; i < B_ * S_; i += blockDim.x)
        if (raw[i]) loc[i & 3]++;
    #pragma unroll
    for (int r = 0; r < 4; r++)
        if (loc[r]) atomicAdd(&cnt[r], loc[r]);
    __syncthreads();

    const int c0 = cnt[0], c1 = cnt[1], c2 = cnt[2], c3 = cnt[3];
    int mode;                       // 0 = uint8, 1 = int32, 2 = float32
    if (c0 > 0 && c1 == 0 && c2 == 0 && c3 == 0)       mode = 1;
    else if (c0 == 0 && c1 == 0 && (c2 > 0 || c3 > 0)) mode = 2;
    else                                               mode = 0;

    if (mode == 0) {
        for (int i = tid; i < B_ * S_; i += blockDim.x)
            outm[i] = raw[i] ? -1e9f : 0.f;
    } else if (mode == 1) {
        const int* p = (const int*)raw;
        for (int i = tid; i < B_ * S_; i += blockDim.x)
            outm[i] = p[i] ? -1e9f : 0.f;
    } else {
        const float* p = (const float*)raw;
        for (int i = tid; i < B_ * S_; i += blockDim.x)
            outm[i] = (p[i] != 0.0f) ? -1e9f : 0.f;
    }
}

// ---------------------------------------------------------------------------
// GEMM v2: raw mma.m16n8k8, 4 warps, 64x64 warp tile, reg-resident A frags.
// C = A[M,K] @ W[N,K]^T + bias. Inputs pre-rounded tf32.
// split_heads=1 -> [B,NH,S,DH] tf32-rounded; else raw fp32 [M,N].
// ---------------------------------------------------------------------------
constexpr int BM = 128, BN = 128, BK = 32;
constexpr int GEMM_THREADS = 128;
constexpr int GLD = 36;                              // 32 + 4 pad
constexpr int STG_FLOATS = 2 * BM * GLD;             // As+Ws per stage = 9216
constexpr int GEMM_SMEM  = 2 * STG_FLOATS * (int)sizeof(float);   // 73728 B

__global__ __launch_bounds__(GEMM_THREADS, 2)
void gemm3_kernel(const float* __restrict__ A0, const float* __restrict__ W0,
                  const float* __restrict__ b0, float* __restrict__ o0,
                  const float* __restrict__ A1, const float* __restrict__ W1,
                  const float* __restrict__ b1, float* __restrict__ o1,
                  const float* __restrict__ A2, const float* __restrict__ W2,
                  const float* __restrict__ b2, float* __restrict__ o2,
                  int split_heads)
{
    extern __shared__ float gsm[];

    const float* A; const float* W; const float* bias; float* out;
    if (blockIdx.z == 0)      { A = A0; W = W0; bias = b0; out = o0; }
    else if (blockIdx.z == 1) { A = A1; W = W1; bias = b1; out = o1; }
    else                      { A = A2; W = W2; bias = b2; out = o2; }

    const int tid  = threadIdx.x;
    const int warp = tid >> 5;
    const int lane = tid & 31;
    const int g    = lane >> 2;
    const int q    = lane & 3;
    const int wm   = (warp >> 1) * 64;   // warp m-offset within block
    const int wn   = (warp & 1) * 64;    // warp n-offset
    const int bm   = blockIdx.y * BM;
    const int bn   = blockIdx.x * BN;

    // Accumulators: 4 m-tiles x 8 n-tiles, init from bias.
    // acc layout per m16n8 tile: c0=C[g][2q], c1=C[g][2q+1], c2=C[g+8][2q], c3=C[g+8][2q+1]
    float acc[4][8][4];
    #pragma unroll
    for (int ni = 0; ni < 8; ni++) {
        float2 bv = *reinterpret_cast<const float2*>(bias + bn + wn + ni * 8 + 2 * q);
        #pragma unroll
        for (int mi = 0; mi < 4; mi++) {
            acc[mi][ni][0] = bv.x; acc[mi][ni][1] = bv.y;
            acc[mi][ni][2] = bv.x; acc[mi][ni][3] = bv.y;
        }
    }

    const float* Ap = A + bm * K_;
    const float* Wp = W + bn * K_;

    auto preload = [&](int st, int k0) {
        float* As = gsm + st * STG_FLOATS;
        float* Ws = As + BM * GLD;
        #pragma unroll
        for (int i = 0; i < 8; i++) {
            int idx = tid + i * GEMM_THREADS;      // 0..1023
            int r = idx >> 3;
            int c = (idx & 7) << 2;
            cp16(As + r * GLD + c, Ap + r * K_ + k0 + c);
            cp16(Ws + r * GLD + c, Wp + r * K_ + k0 + c);
        }
        cp_commit();
    };

    preload(0, 0);

    for (int it = 0; it < K_ / BK; it++) {
        int cur = it & 1;
        cp_wait_all();
        __syncthreads();
        if (it + 1 < K_ / BK) preload(1 - cur, (it + 1) * BK);

        const float* As = gsm + cur * STG_FLOATS;
        const float* Ws = As + BM * GLD;

        #pragma unroll
        for (int kk = 0; kk < BK; kk += 8) {
            // A fragments: 4 m-tiles, held in registers, reused over 8 n-tiles
            unsigned af[4][4];
            #pragma unroll
            for (int mi = 0; mi < 4; mi++) {
                const float* ab = As + (wm + mi * 16 + g) * GLD + kk + q;
                af[mi][0] = __float_as_uint(ab[0]);
                af[mi][1] = __float_as_uint(ab[8 * GLD]);
                af[mi][2] = __float_as_uint(ab[4]);
                af[mi][3] = __float_as_uint(ab[8 * GLD + 4]);
            }
            #pragma unroll
            for (int ni = 0; ni < 8; ni++) {
                const float* bb = Ws + (wn + ni * 8 + g) * GLD + kk + q;
                unsigned b0 = __float_as_uint(bb[0]);
                unsigned b1 = __float_as_uint(bb[4]);
                #pragma unroll
                for (int mi = 0; mi < 4; mi++)
                    mma8(acc[mi][ni], af[mi], b0, b1);
            }
        }
    }

    // Epilogue: per tile, rows g and g+8, cols 2q,2q+1 (contiguous float2)
    #pragma unroll
    for (int mi = 0; mi < 4; mi++) {
        #pragma unroll
        for (int ni = 0; ni < 8; ni++) {
            int row = bm + wm + mi * 16 + g;
            int col = bn + wn + ni * 8 + 2 * q;
            if (split_heads) {
                int b = row >> 10;
                int s = row & (S_ - 1);
                int h = col >> 6;
                int d = col & (DH_ - 1);
                float* dst = out + (((b * NH_ + h) * S_) + s) * DH_ + d;
                float2 v0 = make_float2(f2tff(acc[mi][ni][0]), f2tff(acc[mi][ni][1]));
                *reinterpret_cast<float2*>(dst) = v0;
                float2 v1 = make_float2(f2tff(acc[mi][ni][2]), f2tff(acc[mi][ni][3]));
                *reinterpret_cast<float2*>(dst + 8 * DH_) = v1;
            } else {
                float* dst = out + row * N_ + col;
                *reinterpret_cast<float2*>(dst) =
                    make_float2(acc[mi][ni][0], acc[mi][ni][1]);
                *reinterpret_cast<float2*>(dst + 8 * N_) =
                    make_float2(acc[mi][ni][2], acc[mi][ni][3]);
            }
        }
    }
}

// ---------------------------------------------------------------------------
// Flash attention (unchanged from R4, passing at ~137 TF/s on the HMMA pipe)
// ---------------------------------------------------------------------------
constexpr int ALD = 68;
constexpr int AT  = 64 * ALD;
constexpr int ATTN_SMEM = 5 * AT * (int)sizeof(float);   // 87040 B

__global__ __launch_bounds__(128, 2)
void attn_kernel(const float* __restrict__ qh, const float* __restrict__ kh,
                 const float* __restrict__ vh,
                 const float* __restrict__ maskf,
                 float* __restrict__ ctx)
{
    extern __shared__ float sm[];
    float* QP = sm;
    float* Ks = sm + AT;
    float* Vs = sm + 3 * AT;

    const int bh = blockIdx.x;
    const int qt = blockIdx.y;
    const int b  = bh >> 4;
    const int h  = bh & (NH_ - 1);
    const int tid  = threadIdx.x;
    const int w    = tid >> 5;
    const int lane = tid & 31;
    const int g    = lane >> 2;
    const int q    = lane & 3;
    const int r0   = w * 16 + g;

    const float* Qg = qh + (bh * S_ + qt * 64) * DH_;
    const float* Kg = kh + bh * S_ * DH_;
    const float* Vg = vh + bh * S_ * DH_;
    const float* mrow = maskf + b * S_;

    #pragma unroll
    for (int i = 0; i < 8; i++) {
        int idx = tid + i * 128;
        int r = idx >> 4;
        int c = (idx & 15) << 2;
        *reinterpret_cast<float4*>(QP + r * ALD + c) =
            *reinterpret_cast<const float4*>(Qg + r * DH_ + c);
    }
    __syncthreads();

    auto kv_load = [&](int st, int kt) {
        #pragma unroll
        for (int i = 0; i < 8; i++) {
            int idx = tid + i * 128;
            int r = idx >> 4;
            int c = (idx & 15) << 2;
            cp16(Ks + st * AT + r * ALD + c, Kg + (kt * 64 + r) * DH_ + c);
            cp16(Vs + st * AT + r * ALD + c, Vg + (kt * 64 + r) * DH_ + c);
        }
        cp_commit();
    };
    kv_load(0, 0);

    unsigned qa[8][4];
    #pragma unroll
    for (int ks = 0; ks < 8; ks++) {
        qa[ks][0] = __float_as_uint(QP[r0 * ALD + ks * 8 + q]);
        qa[ks][1] = __float_as_uint(QP[(r0 + 8) * ALD + ks * 8 + q]);
        qa[ks][2] = __float_as_uint(QP[r0 * ALD + ks * 8 + q + 4]);
        qa[ks][3] = __float_as_uint(QP[(r0 + 8) * ALD + ks * 8 + q + 4]);
    }
    __syncthreads();

    float oc[8][4];
    #pragma unroll
    for (int nt = 0; nt < 8; nt++)
        #pragma unroll
        for (int e = 0; e < 4; e++) oc[nt][e] = 0.f;
    float m0 = -CUDART_INF_F, m1 = -CUDART_INF_F;
    float l0 = 0.f, l1 = 0.f;

    for (int kt = 0; kt < S_ / 64; kt++) {
        const int cur = kt & 1;
        cp_wait_all();
        __syncthreads();
        if (kt + 1 < S_ / 64) kv_load(1 - cur, kt + 1);

        const float* Kc = Ks + cur * AT;
        const float* Vc = Vs + cur * AT;

        float sc[8][4];
        #pragma unroll
        for (int nt = 0; nt < 8; nt++) {
            #pragma unroll
            for (int e = 0; e < 4; e++) sc[nt][e] = 0.f;
            #pragma unroll
            for (int ks = 0; ks < 8; ks++) {
                unsigned kb0 = __float_as_uint(Kc[(nt * 8 + g) * ALD + ks * 8 + q]);
                unsigned kb1 = __float_as_uint(Kc[(nt * 8 + g) * ALD + ks * 8 + q + 4]);
                mma8(sc[nt], qa[ks], kb0, kb1);
            }
        }

        float vx0 = -CUDART_INF_F, vx1 = -CUDART_INF_F;
        #pragma unroll
        for (int nt = 0; nt < 8; nt++) {
            float2 mf = *reinterpret_cast<const float2*>(
                mrow + kt * 64 + nt * 8 + 2 * q);
            sc[nt][0] = sc[nt][0] * 0.125f + mf.x;
            sc[nt][1] = sc[nt][1] * 0.125f + mf.y;
            sc[nt][2] = sc[nt][2] * 0.125f + mf.x;
            sc[nt][3] = sc[nt][3] * 0.125f + mf.y;
            vx0 = fmaxf(vx0, fmaxf(sc[nt][0], sc[nt][1]));
            vx1 = fmaxf(vx1, fmaxf(sc[nt][2], sc[nt][3]));
        }
        vx0 = fmaxf(vx0, __shfl_xor_sync(0xffffffffu, vx0, 1));
        vx0 = fmaxf(vx0, __shfl_xor_sync(0xffffffffu, vx0, 2));
        vx1 = fmaxf(vx1, __shfl_xor_sync(0xffffffffu, vx1, 1));
        vx1 = fmaxf(vx1, __shfl_xor_sync(0xffffffffu, vx1, 2));

        float mn0 = fmaxf(m0, vx0), mn1 = fmaxf(m1, vx1);
        float al0 = __expf(m0 - mn0), al1 = __expf(m1 - mn1);

        __syncwarp();
        float ps0 = 0.f, ps1 = 0.f;
        #pragma unroll
        for (int nt = 0; nt < 8; nt++) {
            float p0 = __expf(sc[nt][0] - mn0);
            float p1 = __expf(sc[nt][1] - mn0);
            float p2 = __expf(sc[nt][2] - mn1);
            float p3 = __expf(sc[nt][3] - mn1);
            ps0 += p0 + p1;
            ps1 += p2 + p3;
            float2 v01 = make_float2(f2tff(p0), f2tff(p1));
            *reinterpret_cast<float2*>(QP + r0 * ALD + nt * 8 + 2 * q) = v01;
            float2 v23 = make_float2(f2tff(p2), f2tff(p3));
            *reinterpret_cast<float2*>(QP + (r0 + 8) * ALD + nt * 8 + 2 * q) = v23;
        }
        ps0 += __shfl_xor_sync(0xffffffffu, ps0, 1);
        ps0 += __shfl_xor_sync(0xffffffffu, ps0, 2);
        ps1 += __shfl_xor_sync(0xffffffffu, ps1, 1);
        ps1 += __shfl_xor_sync(0xffffffffu, ps1, 2);
        l0 = l0 * al0 + ps0;
        l1 = l1 * al1 + ps1;
        m0 = mn0; m1 = mn1;

        #pragma unroll
        for (int nt = 0; nt < 8; nt++) {
            oc[nt][0] *= al0; oc[nt][1] *= al0;
            oc[nt][2] *= al1; oc[nt][3] *= al1;
        }

        __syncwarp();

        #pragma unroll
        for (int ks = 0; ks < 8; ks++) {
            unsigned pa[4];
            pa[0] = __float_as_uint(QP[r0 * ALD + ks * 8 + q]);
            pa[1] = __float_as_uint(QP[(r0 + 8) * ALD + ks * 8 + q]);
            pa[2] = __float_as_uint(QP[r0 * ALD + ks * 8 + q + 4]);
            pa[3] = __float_as_uint(QP[(r0 + 8) * ALD + ks * 8 + q + 4]);
            #pragma unroll
            for (int nt = 0; nt < 8; nt++) {
                unsigned vb0 = __float_as_uint(Vc[(ks * 8 + q) * ALD + nt * 8 + g]);
                unsigned vb1 = __float_as_uint(Vc[(ks * 8 + q + 4) * ALD + nt * 8 + g]);
                mma8(oc[nt], pa, vb0, vb1);
            }
        }
    }

    const float inv0 = 1.f / l0;
    const float inv1 = 1.f / l1;
    float* dst0 = ctx + (b * S_ + qt * 64 + r0) * H_ + h * DH_;
    float* dst1 = dst0 + 8 * H_;
    #pragma unroll
    for (int nt = 0; nt < 8; nt++) {
        float2 o01 = make_float2(f2tff(oc[nt][0] * inv0), f2tff(oc[nt][1] * inv0));
        *reinterpret_cast<float2*>(dst0 + nt * 8 + 2 * q) = o01;
        float2 o23 = make_float2(f2tff(oc[nt][2] * inv1), f2tff(oc[nt][3] * inv1));
        *reinterpret_cast<float2*>(dst1 + nt * 8 + 2 * q) = o23;
    }
}

// ---------------------------------------------------------------------------
// Launch
// ---------------------------------------------------------------------------
extern "C" void kernel_launch(void* const* d_in, const int* in_sizes, int n_in,
                              void* d_out, int out_size)
{
    const float* v  = (const float*)d_in[0];
    const float* k  = (const float*)d_in[1];
    const float* q  = (const float*)d_in[2];
    const unsigned char* mask_raw = (const unsigned char*)d_in[3];
    const float* Wq = (const float*)d_in[4];
    const float* bq = (const float*)d_in[5];
    const float* Wk = (const float*)d_in[6];
    const float* bk = (const float*)d_in[7];
    const float* Wv = (const float*)d_in[8];
    const float* bv = (const float*)d_in[9];
    const float* Wm = (const float*)d_in[10];
    const float* bm = (const float*)d_in[11];
    float* out = (float*)d_out;

    float *qh, *kh, *vh, *ctx, *mnorm;
    float *qc, *kc, *vc, *wq, *wk, *wv, *wm;
    cudaGetSymbolAddress((void**)&qh,  g_qh);
    cudaGetSymbolAddress((void**)&kh,  g_kh);
    cudaGetSymbolAddress((void**)&vh,  g_vh);
    cudaGetSymbolAddress((void**)&ctx, g_ctx);
    cudaGetSymbolAddress((void**)&mnorm, g_maskf);
    cudaGetSymbolAddress((void**)&qc, g_qc);
    cudaGetSymbolAddress((void**)&kc, g_kc);
    cudaGetSymbolAddress((void**)&vc, g_vc);
    cudaGetSymbolAddress((void**)&wq, g_wq);
    cudaGetSymbolAddress((void**)&wk, g_wk);
    cudaGetSymbolAddress((void**)&wv, g_wv);
    cudaGetSymbolAddress((void**)&wm, g_wm);

    cudaFuncSetAttribute(gemm3_kernel, cudaFuncAttributeMaxDynamicSharedMemorySize,
                         GEMM_SMEM);
    cudaFuncSetAttribute(attn_kernel, cudaFuncAttributeMaxDynamicSharedMemorySize,
                         ATTN_SMEM);

    // 0) mask + tf32 pre-rounding of all GEMM inputs
    mask_norm_kernel<<<1, 256>>>(mask_raw, mnorm);
    const int big4 = (M_ * K_) / 4, small4 = (H_ * H_) / 4;
    cvt_tf32_kernel<<<(big4 + 255) / 256, 256>>>(q, qc, big4);
    cvt_tf32_kernel<<<(big4 + 255) / 256, 256>>>(k, kc, big4);
    cvt_tf32_kernel<<<(big4 + 255) / 256, 256>>>(v, vc, big4);
    cvt_tf32_kernel<<<(small4 + 255) / 256, 256>>>(Wq, wq, small4);
    cvt_tf32_kernel<<<(small4 + 255) / 256, 256>>>(Wk, wk, small4);
    cvt_tf32_kernel<<<(small4 + 255) / 256, 256>>>(Wv, wv, small4);
    cvt_tf32_kernel<<<(small4 + 255) / 256, 256>>>(Wm, wm, small4);

    // 1) fused QKV projections into split-head layout (outputs tf32-rounded)
    dim3 gproj(N_ / BN, M_ / BM, 3);
    gemm3_kernel<<<gproj, GEMM_THREADS, GEMM_SMEM>>>(qc, wq, bq, qh,
                                                     kc, wk, bk, kh,
                                                     vc, wv, bv, vh, 1);

    // 2) attention -> merged ctx (tf32-rounded)
    dim3 gattn(B_ * NH_, S_ / 64);
    attn_kernel<<<gattn, 128, ATTN_SMEM>>>(qh, kh, vh, mnorm, ctx);

    // 3) output projection -> d_out (raw fp32)
    dim3 gout(N_ / BN, M_ / BM, 1);
    gemm3_kernel<<<gout, GEMM_THREADS, GEMM_SMEM>>>(ctx, wm, bm, out,
                                                    ctx, wm, bm, out,
                                                    ctx, wm, bm, out, 0);
}

// round 7
// speedup vs baseline: 4.0463x; 1.9140x over previous
#include <cuda_runtime.h>
#include <cuda_fp16.h>
#include <math_constants.h>

#define B_   8
#define S_   1024
#define H_   1024
#define NH_  16
#define DH_  64
#define M_   (B_ * S_)   // 8192
#define N_   H_
#define K_   H_

// Scratch: device globals (no cudaMalloc allowed)
__device__ __half g_qh[B_ * NH_ * S_ * DH_];   // [B,NH,S,DH]
__device__ __half g_kh[B_ * NH_ * S_ * DH_];   // [B,NH,S,DH]
__device__ __half g_vh[B_ * NH_ * DH_ * S_];   // [B,NH,DH,S]  (transposed!)
__device__ __half g_ctx[B_ * S_ * H_];         // merged [B,S,H]
__device__ float  g_maskf[B_ * S_];            // additive mask: 0 or -1e9
// fp16 copies of inputs
__device__ __half g_qc[M_ * K_];
__device__ __half g_kc[M_ * K_];
__device__ __half g_vc[M_ * K_];
__device__ __half g_wq[H_ * H_];
__device__ __half g_wk[H_ * H_];
__device__ __half g_wv[H_ * H_];
__device__ __half g_wm[H_ * H_];

// ---------------------------------------------------------------------------
// PTX helpers
// ---------------------------------------------------------------------------
__device__ __forceinline__ void mma16(float c[4], const unsigned a[4],
                                      unsigned b0, unsigned b1) {
    asm volatile(
        "mma.sync.aligned.m16n8k16.row.col.f32.f16.f16.f32 "
        "{%0,%1,%2,%3}, {%4,%5,%6,%7}, {%8,%9}, {%0,%1,%2,%3};"
        : "+f"(c[0]), "+f"(c[1]), "+f"(c[2]), "+f"(c[3])
        : "r"(a[0]), "r"(a[1]), "r"(a[2]), "r"(a[3]), "r"(b0), "r"(b1));
}
__device__ __forceinline__ void cp16h(__half* smem, const __half* g) {
    unsigned s = (unsigned)__cvta_generic_to_shared(smem);
    asm volatile("cp.async.cg.shared.global [%0], [%1], 16;" :: "r"(s), "l"(g)
                 : "memory");
}
__device__ __forceinline__ void cp_commit() {
    asm volatile("cp.async.commit_group;" ::: "memory");
}
__device__ __forceinline__ void cp_wait_all() {
    asm volatile("cp.async.wait_group 0;" ::: "memory");
}
__device__ __forceinline__ unsigned ldu(const __half* p) {
    return *reinterpret_cast<const unsigned*>(p);
}

// ---------------------------------------------------------------------------
// fp32 -> fp16 conversion (4 elements / thread)
// ---------------------------------------------------------------------------
__global__ void cvt_h_kernel(const float* __restrict__ in,
                             __half* __restrict__ out, int n4)
{
    int i = blockIdx.x * blockDim.x + threadIdx.x;
    if (i < n4) {
        float4 v = reinterpret_cast<const float4*>(in)[i];
        __half2 h0 = __floats2half2_rn(v.x, v.y);
        __half2 h1 = __floats2half2_rn(v.z, v.w);
        uint2 o;
        o.x = *reinterpret_cast<unsigned*>(&h0);
        o.y = *reinterpret_cast<unsigned*>(&h1);
        reinterpret_cast<uint2*>(out)[i] = o;
    }
}

// ---------------------------------------------------------------------------
// Mask dtype detection + normalization -> additive float mask (0 / -1e9).
// ---------------------------------------------------------------------------
__global__ void mask_norm_kernel(const unsigned char* __restrict__ raw,
                                 float* __restrict__ outm)
{
    __shared__ int cnt[4];
    const int tid = threadIdx.x;
    if (tid < 4) cnt[tid] = 0;
    __syncthreads();

    int loc[4] = {0, 0, 0, 0};
    for (int i = tid; i < B_ * S_; i += blockDim.x)
        if (raw[i]) loc[i & 3]++;
    #pragma unroll
    for (int r = 0; r < 4; r++)
        if (loc[r]) atomicAdd(&cnt[r], loc[r]);
    __syncthreads();

    const int c0 = cnt[0], c1 = cnt[1], c2 = cnt[2], c3 = cnt[3];
    int mode;                       // 0 = uint8, 1 = int32, 2 = float32
    if (c0 > 0 && c1 == 0 && c2 == 0 && c3 == 0)       mode = 1;
    else if (c0 == 0 && c1 == 0 && (c2 > 0 || c3 > 0)) mode = 2;
    else                                               mode = 0;

    if (mode == 0) {
        for (int i = tid; i < B_ * S_; i += blockDim.x)
            outm[i] = raw[i] ? -1e9f : 0.f;
    } else if (mode == 1) {
        const int* p = (const int*)raw;
        for (int i = tid; i < B_ * S_; i += blockDim.x)
            outm[i] = p[i] ? -1e9f : 0.f;
    } else {
        const float* p = (const float*)raw;
        for (int i = tid; i < B_ * S_; i += blockDim.x)
            outm[i] = (p[i] != 0.0f) ? -1e9f : 0.f;
    }
}

// ---------------------------------------------------------------------------
// GEMM: C = A[M,K] @ W[N,K]^T + bias, fp16 mma.m16n8k16, fp32 accumulate.
// 4 warps, 64x64 warp tile, register-resident A fragments, BK=64, 2 stages.
// split_heads=1: z in {0,1} -> half [B,NH,S,DH]; z==2 -> half [B,NH,DH,S].
// split_heads=0: fp32 row-major [M,N].
// ---------------------------------------------------------------------------
constexpr int BM = 128, BN = 128, BK = 64;
constexpr int GEMM_THREADS = 128;
constexpr int GLD = 72;                              // 64 + 8 pad (halves)
constexpr int STG_HALFS = 2 * BM * GLD;              // A+W per stage = 18432
constexpr int GEMM_SMEM  = 2 * STG_HALFS * (int)sizeof(__half);  // 73728 B

__global__ __launch_bounds__(GEMM_THREADS, 2)
void gemm3_kernel(const __half* __restrict__ A0, const __half* __restrict__ W0,
                  const float* __restrict__ b0, void* __restrict__ o0,
                  const __half* __restrict__ A1, const __half* __restrict__ W1,
                  const float* __restrict__ b1, void* __restrict__ o1,
                  const __half* __restrict__ A2, const __half* __restrict__ W2,
                  const float* __restrict__ b2, void* __restrict__ o2,
                  int split_heads)
{
    extern __shared__ __half gsmh[];

    const __half* A; const __half* W; const float* bias; void* out;
    if (blockIdx.z == 0)      { A = A0; W = W0; bias = b0; out = o0; }
    else if (blockIdx.z == 1) { A = A1; W = W1; bias = b1; out = o1; }
    else                      { A = A2; W = W2; bias = b2; out = o2; }

    const int tid  = threadIdx.x;
    const int warp = tid >> 5;
    const int lane = tid & 31;
    const int g    = lane >> 2;
    const int q    = lane & 3;
    const int wm   = (warp >> 1) * 64;
    const int wn   = (warp & 1) * 64;
    const int bm   = blockIdx.y * BM;
    const int bn   = blockIdx.x * BN;

    // acc per m16n8 tile: c0=C[g][2q], c1=C[g][2q+1], c2=C[g+8][2q], c3=C[g+8][2q+1]
    float acc[4][8][4];
    #pragma unroll
    for (int ni = 0; ni < 8; ni++) {
        float2 bv = *reinterpret_cast<const float2*>(bias + bn + wn + ni * 8 + 2 * q);
        #pragma unroll
        for (int mi = 0; mi < 4; mi++) {
            acc[mi][ni][0] = bv.x; acc[mi][ni][1] = bv.y;
            acc[mi][ni][2] = bv.x; acc[mi][ni][3] = bv.y;
        }
    }

    const __half* Ap = A + (size_t)bm * K_;
    const __half* Wp = W + (size_t)bn * K_;

    auto preload = [&](int st, int k0) {
        __half* As = gsmh + st * STG_HALFS;
        __half* Ws = As + BM * GLD;
        // 128 rows x 64 halves = 8 chunks/row; 1024 chunks per matrix
        #pragma unroll
        for (int i = 0; i < 8; i++) {
            int idx = tid + i * GEMM_THREADS;      // 0..1023
            int r = idx >> 3;
            int c = (idx & 7) << 3;                // half offset
            cp16h(As + r * GLD + c, Ap + r * K_ + k0 + c);
            cp16h(Ws + r * GLD + c, Wp + r * K_ + k0 + c);
        }
        cp_commit();
    };

    preload(0, 0);

    for (int it = 0; it < K_ / BK; it++) {
        int cur = it & 1;
        cp_wait_all();
        __syncthreads();
        if (it + 1 < K_ / BK) preload(1 - cur, (it + 1) * BK);

        const __half* As = gsmh + cur * STG_HALFS;
        const __half* Ws = As + BM * GLD;

        #pragma unroll
        for (int kk = 0; kk < BK; kk += 16) {
            unsigned af[4][4];
            #pragma unroll
            for (int mi = 0; mi < 4; mi++) {
                const __half* ab = As + (wm + mi * 16 + g) * GLD + kk + 2 * q;
                af[mi][0] = ldu(ab);
                af[mi][1] = ldu(ab + 8 * GLD);
                af[mi][2] = ldu(ab + 8);
                af[mi][3] = ldu(ab + 8 * GLD + 8);
            }
            #pragma unroll
            for (int ni = 0; ni < 8; ni++) {
                const __half* bb = Ws + (wn + ni * 8 + g) * GLD + kk + 2 * q;
                unsigned b0v = ldu(bb);
                unsigned b1v = ldu(bb + 8);
                #pragma unroll
                for (int mi = 0; mi < 4; mi++)
                    mma16(acc[mi][ni], af[mi], b0v, b1v);
            }
        }
    }

    // Epilogue
    #pragma unroll
    for (int mi = 0; mi < 4; mi++) {
        #pragma unroll
        for (int ni = 0; ni < 8; ni++) {
            int row = bm + wm + mi * 16 + g;
            int col = bn + wn + ni * 8 + 2 * q;
            if (split_heads) {
                int b = row >> 10;
                int s = row & (S_ - 1);
                int h = col >> 6;
                int d = col & (DH_ - 1);
                __half* oh = (__half*)out;
                if (blockIdx.z < 2) {
                    // [B,NH,S,DH]
                    __half* dst = oh + (((b * NH_ + h) * S_) + s) * DH_ + d;
                    *reinterpret_cast<__half2*>(dst) =
                        __floats2half2_rn(acc[mi][ni][0], acc[mi][ni][1]);
                    *reinterpret_cast<__half2*>(dst + 8 * DH_) =
                        __floats2half2_rn(acc[mi][ni][2], acc[mi][ni][3]);
                } else {
                    // V transposed: [B,NH,DH,S]
                    __half* base = oh + ((b * NH_ + h) * DH_ + d) * S_ + s;
                    base[0]          = __float2half_rn(acc[mi][ni][0]);
                    base[S_]         = __float2half_rn(acc[mi][ni][1]);
                    base[8]          = __float2half_rn(acc[mi][ni][2]);
                    base[S_ + 8]     = __float2half_rn(acc[mi][ni][3]);
                }
            } else {
                float* dst = (float*)out + (size_t)row * N_ + col;
                *reinterpret_cast<float2*>(dst) =
                    make_float2(acc[mi][ni][0], acc[mi][ni][1]);
                *reinterpret_cast<float2*>(dst + 8 * N_) =
                    make_float2(acc[mi][ni][2], acc[mi][ni][3]);
            }
        }
    }
}

// ---------------------------------------------------------------------------
// Flash attention, fp16 mma.m16n8k16, fp32 softmax/accumulate.
// 4 warps; warp w owns Q rows [16w,16w+16). V pre-transposed: [B,NH,DH,S].
// ---------------------------------------------------------------------------
constexpr int ALD = 72;                      // halves per row (64 + 8 pad)
constexpr int AT  = 64 * ALD;                // halves per tile
constexpr int ATTN_SMEM = 5 * AT * (int)sizeof(__half);   // 46080 B

__global__ __launch_bounds__(128, 2)
void attn_kernel(const __half* __restrict__ qh, const __half* __restrict__ kh,
                 const __half* __restrict__ vh,
                 const float* __restrict__ maskf,
                 __half* __restrict__ ctx)
{
    extern __shared__ __half smh[];
    __half* QP = smh;            // Q tile, later reused for P
    __half* Ks = smh + AT;       // [2][64][ALD]
    __half* Vs = smh + 3 * AT;   // [2][64][ALD]  rows = d, cols = key

    const int bh = blockIdx.x;
    const int qt = blockIdx.y;
    const int b  = bh >> 4;
    const int h  = bh & (NH_ - 1);
    const int tid  = threadIdx.x;
    const int w    = tid >> 5;
    const int lane = tid & 31;
    const int g    = lane >> 2;
    const int q    = lane & 3;
    const int r0   = w * 16 + g;

    const __half* Qg = qh + ((size_t)bh * S_ + qt * 64) * DH_;
    const __half* Kg = kh + (size_t)bh * S_ * DH_;
    const __half* Vg = vh + (size_t)bh * DH_ * S_;   // rows d, cols s
    const float* mrow = maskf + b * S_;

    // Load Q tile: 64 rows x 64 halves = 512 x 16B chunks
    #pragma unroll
    for (int i = 0; i < 4; i++) {
        int idx = tid + i * 128;      // 0..511
        int r = idx >> 3;
        int c = (idx & 7) << 3;
        *reinterpret_cast<uint4*>(QP + r * ALD + c) =
            *reinterpret_cast<const uint4*>(Qg + r * DH_ + c);
    }
    __syncthreads();

    auto kv_load = [&](int st, int kt) {
        #pragma unroll
        for (int i = 0; i < 4; i++) {
            int idx = tid + i * 128;
            int r = idx >> 3;
            int c = (idx & 7) << 3;
            cp16h(Ks + st * AT + r * ALD + c, Kg + (kt * 64 + r) * DH_ + c);
            cp16h(Vs + st * AT + r * ALD + c, Vg + r * S_ + kt * 64 + c);
        }
        cp_commit();
    };
    kv_load(0, 0);

    // Persistent Q fragments: 4 k16-steps
    unsigned qa[4][4];
    #pragma unroll
    for (int ks = 0; ks < 4; ks++) {
        const __half* qb = QP + r0 * ALD + ks * 16 + 2 * q;
        qa[ks][0] = ldu(qb);
        qa[ks][1] = ldu(qb + 8 * ALD);
        qa[ks][2] = ldu(qb + 8);
        qa[ks][3] = ldu(qb + 8 * ALD + 8);
    }
    __syncthreads();   // all Q reads done before QP reused for P

    float oc[8][4];
    #pragma unroll
    for (int nt = 0; nt < 8; nt++)
        #pragma unroll
        for (int e = 0; e < 4; e++) oc[nt][e] = 0.f;
    float m0 = -CUDART_INF_F, m1 = -CUDART_INF_F;
    float l0 = 0.f, l1 = 0.f;

    for (int kt = 0; kt < S_ / 64; kt++) {
        const int cur = kt & 1;
        cp_wait_all();
        __syncthreads();
        if (kt + 1 < S_ / 64) kv_load(1 - cur, kt + 1);

        const __half* Kc = Ks + cur * AT;
        const __half* Vc = Vs + cur * AT;

        // S = Q @ K^T
        float sc[8][4];
        #pragma unroll
        for (int nt = 0; nt < 8; nt++) {
            #pragma unroll
            for (int e = 0; e < 4; e++) sc[nt][e] = 0.f;
            #pragma unroll
            for (int ks = 0; ks < 4; ks++) {
                const __half* kb = Kc + (nt * 8 + g) * ALD + ks * 16 + 2 * q;
                mma16(sc[nt], qa[ks], ldu(kb), ldu(kb + 8));
            }
        }

        // scale + additive mask + row max
        float vx0 = -CUDART_INF_F, vx1 = -CUDART_INF_F;
        #pragma unroll
        for (int nt = 0; nt < 8; nt++) {
            float2 mf = *reinterpret_cast<const float2*>(
                mrow + kt * 64 + nt * 8 + 2 * q);
            sc[nt][0] = sc[nt][0] * 0.125f + mf.x;
            sc[nt][1] = sc[nt][1] * 0.125f + mf.y;
            sc[nt][2] = sc[nt][2] * 0.125f + mf.x;
            sc[nt][3] = sc[nt][3] * 0.125f + mf.y;
            vx0 = fmaxf(vx0, fmaxf(sc[nt][0], sc[nt][1]));
            vx1 = fmaxf(vx1, fmaxf(sc[nt][2], sc[nt][3]));
        }
        vx0 = fmaxf(vx0, __shfl_xor_sync(0xffffffffu, vx0, 1));
        vx0 = fmaxf(vx0, __shfl_xor_sync(0xffffffffu, vx0, 2));
        vx1 = fmaxf(vx1, __shfl_xor_sync(0xffffffffu, vx1, 1));
        vx1 = fmaxf(vx1, __shfl_xor_sync(0xffffffffu, vx1, 2));

        float mn0 = fmaxf(m0, vx0), mn1 = fmaxf(m1, vx1);
        float al0 = __expf(m0 - mn0), al1 = __expf(m1 - mn1);

        __syncwarp();   // prior PV reads of QP done before P overwrite
        float ps0 = 0.f, ps1 = 0.f;
        #pragma unroll
        for (int nt = 0; nt < 8; nt++) {
            float p0 = __expf(sc[nt][0] - mn0);
            float p1 = __expf(sc[nt][1] - mn0);
            float p2 = __expf(sc[nt][2] - mn1);
            float p3 = __expf(sc[nt][3] - mn1);
            ps0 += p0 + p1;
            ps1 += p2 + p3;
            *reinterpret_cast<__half2*>(QP + r0 * ALD + nt * 8 + 2 * q) =
                __floats2half2_rn(p0, p1);
            *reinterpret_cast<__half2*>(QP + (r0 + 8) * ALD + nt * 8 + 2 * q) =
                __floats2half2_rn(p2, p3);
        }
        ps0 += __shfl_xor_sync(0xffffffffu, ps0, 1);
        ps0 += __shfl_xor_sync(0xffffffffu, ps0, 2);
        ps1 += __shfl_xor_sync(0xffffffffu, ps1, 1);
        ps1 += __shfl_xor_sync(0xffffffffu, ps1, 2);
        l0 = l0 * al0 + ps0;
        l1 = l1 * al1 + ps1;
        m0 = mn0; m1 = mn1;

        #pragma unroll
        for (int nt = 0; nt < 8; nt++) {
            oc[nt][0] *= al0; oc[nt][1] *= al0;
            oc[nt][2] *= al1; oc[nt][3] *= al1;
        }

        __syncwarp();   // P visible to warp

        // O += P @ V   (V transposed in smem: rows d, cols key)
        #pragma unroll
        for (int ks = 0; ks < 4; ks++) {
            unsigned pa[4];
            const __half* pb = QP + r0 * ALD + ks * 16 + 2 * q;
            pa[0] = ldu(pb);
            pa[1] = ldu(pb + 8 * ALD);
            pa[2] = ldu(pb + 8);
            pa[3] = ldu(pb + 8 * ALD + 8);
            #pragma unroll
            for (int nt = 0; nt < 8; nt++) {
                const __half* vb = Vc + (nt * 8 + g) * ALD + ks * 16 + 2 * q;
                mma16(oc[nt], pa, ldu(vb), ldu(vb + 8));
            }
        }
    }

    // Normalize + write merged ctx [B,S,H] (half)
    const float inv0 = 1.f / l0;
    const float inv1 = 1.f / l1;
    __half* dst0 = ctx + ((size_t)(b * S_ + qt * 64 + r0)) * H_ + h * DH_;
    __half* dst1 = dst0 + 8 * H_;
    #pragma unroll
    for (int nt = 0; nt < 8; nt++) {
        *reinterpret_cast<__half2*>(dst0 + nt * 8 + 2 * q) =
            __floats2half2_rn(oc[nt][0] * inv0, oc[nt][1] * inv0);
        *reinterpret_cast<__half2*>(dst1 + nt * 8 + 2 * q) =
            __floats2half2_rn(oc[nt][2] * inv1, oc[nt][3] * inv1);
    }
}

// ---------------------------------------------------------------------------
// Launch
// ---------------------------------------------------------------------------
extern "C" void kernel_launch(void* const* d_in, const int* in_sizes, int n_in,
                              void* d_out, int out_size)
{
    const float* v  = (const float*)d_in[0];
    const float* k  = (const float*)d_in[1];
    const float* q  = (const float*)d_in[2];
    const unsigned char* mask_raw = (const unsigned char*)d_in[3];
    const float* Wq = (const float*)d_in[4];
    const float* bq = (const float*)d_in[5];
    const float* Wk = (const float*)d_in[6];
    const float* bk = (const float*)d_in[7];
    const float* Wv = (const float*)d_in[8];
    const float* bv = (const float*)d_in[9];
    const float* Wm = (const float*)d_in[10];
    const float* bm = (const float*)d_in[11];
    float* out = (float*)d_out;

    __half *qh, *kh, *vh, *ctx;
    __half *qc, *kc, *vc, *wq, *wk, *wv, *wm;
    float *mnorm;
    cudaGetSymbolAddress((void**)&qh,  g_qh);
    cudaGetSymbolAddress((void**)&kh,  g_kh);
    cudaGetSymbolAddress((void**)&vh,  g_vh);
    cudaGetSymbolAddress((void**)&ctx, g_ctx);
    cudaGetSymbolAddress((void**)&mnorm, g_maskf);
    cudaGetSymbolAddress((void**)&qc, g_qc);
    cudaGetSymbolAddress((void**)&kc, g_kc);
    cudaGetSymbolAddress((void**)&vc, g_vc);
    cudaGetSymbolAddress((void**)&wq, g_wq);
    cudaGetSymbolAddress((void**)&wk, g_wk);
    cudaGetSymbolAddress((void**)&wv, g_wv);
    cudaGetSymbolAddress((void**)&wm, g_wm);

    cudaFuncSetAttribute(gemm3_kernel, cudaFuncAttributeMaxDynamicSharedMemorySize,
                         GEMM_SMEM);
    cudaFuncSetAttribute(attn_kernel, cudaFuncAttributeMaxDynamicSharedMemorySize,
                         ATTN_SMEM);

    // 0) mask + fp16 conversion of all GEMM inputs
    mask_norm_kernel<<<1, 256>>>(mask_raw, mnorm);
    const int big4 = (M_ * K_) / 4, small4 = (H_ * H_) / 4;
    cvt_h_kernel<<<(big4 + 255) / 256, 256>>>(q, qc, big4);
    cvt_h_kernel<<<(big4 + 255) / 256, 256>>>(k, kc, big4);
    cvt_h_kernel<<<(big4 + 255) / 256, 256>>>(v, vc, big4);
    cvt_h_kernel<<<(small4 + 255) / 256, 256>>>(Wq, wq, small4);
    cvt_h_kernel<<<(small4 + 255) / 256, 256>>>(Wk, wk, small4);
    cvt_h_kernel<<<(small4 + 255) / 256, 256>>>(Wv, wv, small4);
    cvt_h_kernel<<<(small4 + 255) / 256, 256>>>(Wm, wm, small4);

    // 1) fused QKV projections (Q,K split-head; V split-head transposed)
    dim3 gproj(N_ / BN, M_ / BM, 3);
    gemm3_kernel<<<gproj, GEMM_THREADS, GEMM_SMEM>>>(qc, wq, bq, qh,
                                                     kc, wk, bk, kh,
                                                     vc, wv, bv, vh, 1);

    // 2) attention -> merged ctx (half)
    dim3 gattn(B_ * NH_, S_ / 64);
    attn_kernel<<<gattn, 128, ATTN_SMEM>>>(qh, kh, vh, mnorm, ctx);

    // 3) output projection -> d_out (fp32)
    dim3 gout(N_ / BN, M_ / BM, 1);
    gemm3_kernel<<<gout, GEMM_THREADS, GEMM_SMEM>>>(ctx, wm, bm, out,
                                                    ctx, wm, bm, out,
                                                    ctx, wm, bm, out, 0);
}

// round 13
// speedup vs baseline: 4.4460x; 1.0988x over previous
#include <cuda_runtime.h>
#include <cuda_fp16.h>
#include <math_constants.h>

#define B_   8
#define S_   1024
#define H_   1024
#define NH_  16
#define DH_  64
#define M_   (B_ * S_)   // 8192
#define N_   H_
#define K_   H_

// Scratch: device globals (no cudaMalloc allowed)
__device__ __half g_qh[B_ * NH_ * S_ * DH_];   // [B,NH,S,DH]
__device__ __half g_kh[B_ * NH_ * S_ * DH_];   // [B,NH,S,DH]
__device__ __half g_vh[B_ * NH_ * DH_ * S_];   // [B,NH,DH,S]  (transposed!)
__device__ __half g_ctx[B_ * S_ * H_];         // merged [B,S,H]
__device__ float  g_maskf[B_ * S_];            // additive mask: 0 or -1e9
// fp16 copies of inputs
__device__ __half g_qc[M_ * K_];
__device__ __half g_kc[M_ * K_];
__device__ __half g_vc[M_ * K_];
__device__ __half g_wq[H_ * H_];
__device__ __half g_wk[H_ * H_];
__device__ __half g_wv[H_ * H_];
__device__ __half g_wm[H_ * H_];

// ---------------------------------------------------------------------------
// PTX helpers (mma.sync / cp.async / ldmatrix only — NO tcgen05: the harness
// builds PTX for target sm_103 which rejects accelerated-feature instrs)
// ---------------------------------------------------------------------------
__device__ __forceinline__ void mma16(float c[4], const unsigned a[4],
                                      unsigned b0, unsigned b1) {
    asm volatile(
        "mma.sync.aligned.m16n8k16.row.col.f32.f16.f16.f32 "
        "{%0,%1,%2,%3}, {%4,%5,%6,%7}, {%8,%9}, {%0,%1,%2,%3};"
        : "+f"(c[0]), "+f"(c[1]), "+f"(c[2]), "+f"(c[3])
        : "r"(a[0]), "r"(a[1]), "r"(a[2]), "r"(a[3]), "r"(b0), "r"(b1));
}
__device__ __forceinline__ void ldsm4(unsigned r[4], unsigned sa) {
    asm volatile("ldmatrix.sync.aligned.m8n8.x4.shared.b16 {%0,%1,%2,%3}, [%4];"
                 : "=r"(r[0]), "=r"(r[1]), "=r"(r[2]), "=r"(r[3]) : "r"(sa));
}
__device__ __forceinline__ void cp16h(__half* smem, const __half* g) {
    unsigned s = (unsigned)__cvta_generic_to_shared(smem);
    asm volatile("cp.async.cg.shared.global [%0], [%1], 16;" :: "r"(s), "l"(g)
                 : "memory");
}
__device__ __forceinline__ void cp_commit() {
    asm volatile("cp.async.commit_group;" ::: "memory");
}
__device__ __forceinline__ void cp_wait_all() {
    asm volatile("cp.async.wait_group 0;" ::: "memory");
}
__device__ __forceinline__ unsigned smem_u32(const void* p) {
    return (unsigned)__cvta_generic_to_shared(p);
}

// ---------------------------------------------------------------------------
// Fused fp32 -> fp16 conversion for all 7 tensors (one launch).
// Chunk = 4 floats. Segments: q,k,v (BIG each) then Wq,Wk,Wv,Wm (SMALL each).
// ---------------------------------------------------------------------------
constexpr int BIG4   = (M_ * K_) / 4;     // 2097152
constexpr int SMALL4 = (H_ * H_) / 4;     // 262144
constexpr int CVT_TOTAL = 3 * BIG4 + 4 * SMALL4;

__global__ void cvt_all_kernel(const float* __restrict__ q,
                               const float* __restrict__ k,
                               const float* __restrict__ v,
                               const float* __restrict__ wq,
                               const float* __restrict__ wk,
                               const float* __restrict__ wv,
                               const float* __restrict__ wm,
                               __half* __restrict__ qo, __half* __restrict__ ko,
                               __half* __restrict__ vo, __half* __restrict__ wqo,
                               __half* __restrict__ wko, __half* __restrict__ wvo,
                               __half* __restrict__ wmo)
{
    int i = blockIdx.x * blockDim.x + threadIdx.x;
    if (i >= CVT_TOTAL) return;
    const float* in; __half* out; int off;
    if (i < 3 * BIG4) {
        int s = i / BIG4;
        off = i - s * BIG4;
        in  = (s == 0) ? q : (s == 1) ? k : v;
        out = (s == 0) ? qo : (s == 1) ? ko : vo;
    } else {
        int j = i - 3 * BIG4;
        int s = j / SMALL4;
        off = j - s * SMALL4;
        in  = (s == 0) ? wq : (s == 1) ? wk : (s == 2) ? wv : wm;
        out = (s == 0) ? wqo : (s == 1) ? wko : (s == 2) ? wvo : wmo;
    }
    float4 vv = reinterpret_cast<const float4*>(in)[off];
    __half2 h0 = __floats2half2_rn(vv.x, vv.y);
    __half2 h1 = __floats2half2_rn(vv.z, vv.w);
    uint2 o;
    o.x = *reinterpret_cast<unsigned*>(&h0);
    o.y = *reinterpret_cast<unsigned*>(&h1);
    reinterpret_cast<uint2*>(out)[off] = o;
}

// ---------------------------------------------------------------------------
// Mask dtype detection + normalization -> additive float mask (0 / -1e9).
// ---------------------------------------------------------------------------
__global__ void mask_norm_kernel(const unsigned char* __restrict__ raw,
                                 float* __restrict__ outm)
{
    __shared__ int cnt[4];
    const int tid = threadIdx.x;
    if (tid < 4) cnt[tid] = 0;
    __syncthreads();

    int loc[4] = {0, 0, 0, 0};
    for (int i = tid; i < B_ * S_; i += blockDim.x)
        if (raw[i]) loc[i & 3]++;
    #pragma unroll
    for (int r = 0; r < 4; r++)
        if (loc[r]) atomicAdd(&cnt[r], loc[r]);
    __syncthreads();

    const int c0 = cnt[0], c1 = cnt[1], c2 = cnt[2], c3 = cnt[3];
    int mode;
    if (c0 > 0 && c1 == 0 && c2 == 0 && c3 == 0)       mode = 1;
    else if (c0 == 0 && c1 == 0 && (c2 > 0 || c3 > 0)) mode = 2;
    else                                               mode = 0;

    if (mode == 0) {
        for (int i = tid; i < B_ * S_; i += blockDim.x)
            outm[i] = raw[i] ? -1e9f : 0.f;
    } else if (mode == 1) {
        const int* p = (const int*)raw;
        for (int i = tid; i < B_ * S_; i += blockDim.x)
            outm[i] = p[i] ? -1e9f : 0.f;
    } else {
        const float* p = (const float*)raw;
        for (int i = tid; i < B_ * S_; i += blockDim.x)
            outm[i] = (p[i] != 0.0f) ? -1e9f : 0.f;
    }
}

// ---------------------------------------------------------------------------
// GEMM: C = A[M,K] @ W[N,K]^T + bias, fp16 mma.m16n8k16, fp32 accumulate.
// 4 warps, 64x64 warp tile, ldmatrix.x4 fragment loads, BK=64, 2 stages.
// ---------------------------------------------------------------------------
constexpr int BM = 128, BN = 128, BK = 64;
constexpr int GEMM_THREADS = 128;
constexpr int GLD = 72;                              // 64 + 8 pad (halves)
constexpr int STG_HALFS = 2 * BM * GLD;              // A+W per stage
constexpr int GEMM_SMEM  = 2 * STG_HALFS * (int)sizeof(__half);  // 73728 B

__global__ __launch_bounds__(GEMM_THREADS, 2)
void gemm3_kernel(const __half* __restrict__ A0, const __half* __restrict__ W0,
                  const float* __restrict__ b0, void* __restrict__ o0,
                  const __half* __restrict__ A1, const __half* __restrict__ W1,
                  const float* __restrict__ b1, void* __restrict__ o1,
                  const __half* __restrict__ A2, const __half* __restrict__ W2,
                  const float* __restrict__ b2, void* __restrict__ o2,
                  int split_heads)
{
    extern __shared__ __half gsmh[];

    const __half* A; const __half* W; const float* bias; void* out;
    if (blockIdx.z == 0)      { A = A0; W = W0; bias = b0; out = o0; }
    else if (blockIdx.z == 1) { A = A1; W = W1; bias = b1; out = o1; }
    else                      { A = A2; W = W2; bias = b2; out = o2; }

    const int tid  = threadIdx.x;
    const int warp = tid >> 5;
    const int lane = tid & 31;
    const int g    = lane >> 2;
    const int q    = lane & 3;
    const int wm   = (warp >> 1) * 64;
    const int wn   = (warp & 1) * 64;
    const int bm   = blockIdx.y * BM;
    const int bn   = blockIdx.x * BN;

    // ldmatrix lane-address components
    const int a_row = (lane & 7) + ((lane >> 3) & 1) * 8;   // A: m0,m1 rows; m2,m3 k+8
    const int a_k   = (lane >> 4) * 8;
    const int b_row = (lane & 7) + (lane >> 4) * 8;         // B: m0,m1 tile0; m2,m3 tile1
    const int b_k   = ((lane >> 3) & 1) * 8;

    float acc[4][8][4];
    #pragma unroll
    for (int ni = 0; ni < 8; ni++) {
        float2 bv = *reinterpret_cast<const float2*>(bias + bn + wn + ni * 8 + 2 * q);
        #pragma unroll
        for (int mi = 0; mi < 4; mi++) {
            acc[mi][ni][0] = bv.x; acc[mi][ni][1] = bv.y;
            acc[mi][ni][2] = bv.x; acc[mi][ni][3] = bv.y;
        }
    }

    const __half* Ap = A + (size_t)bm * K_;
    const __half* Wp = W + (size_t)bn * K_;

    auto preload = [&](int st, int k0) {
        __half* As = gsmh + st * STG_HALFS;
        __half* Ws = As + BM * GLD;
        #pragma unroll
        for (int i = 0; i < 8; i++) {
            int idx = tid + i * GEMM_THREADS;      // 0..1023
            int r = idx >> 3;
            int c = (idx & 7) << 3;
            cp16h(As + r * GLD + c, Ap + r * K_ + k0 + c);
            cp16h(Ws + r * GLD + c, Wp + r * K_ + k0 + c);
        }
        cp_commit();
    };

    preload(0, 0);

    for (int it = 0; it < K_ / BK; it++) {
        int cur = it & 1;
        cp_wait_all();
        __syncthreads();
        if (it + 1 < K_ / BK) preload(1 - cur, (it + 1) * BK);

        const __half* As = gsmh + cur * STG_HALFS;
        const __half* Ws = As + BM * GLD;
        const unsigned As_u = smem_u32(As);
        const unsigned Ws_u = smem_u32(Ws);

        #pragma unroll
        for (int kk = 0; kk < BK; kk += 16) {
            unsigned af[4][4];
            #pragma unroll
            for (int mi = 0; mi < 4; mi++)
                ldsm4(af[mi], As_u + ((wm + mi * 16 + a_row) * GLD + kk + a_k) * 2);
            #pragma unroll
            for (int np = 0; np < 4; np++) {
                unsigned bf[4];
                ldsm4(bf, Ws_u + ((wn + np * 16 + b_row) * GLD + kk + b_k) * 2);
                #pragma unroll
                for (int mi = 0; mi < 4; mi++) {
                    mma16(acc[mi][2 * np],     af[mi], bf[0], bf[1]);
                    mma16(acc[mi][2 * np + 1], af[mi], bf[2], bf[3]);
                }
            }
        }
    }

    // Epilogue: per tile, rows g and g+8, cols 2q,2q+1
    #pragma unroll
    for (int mi = 0; mi < 4; mi++) {
        #pragma unroll
        for (int ni = 0; ni < 8; ni++) {
            int row = bm + wm + mi * 16 + g;
            int col = bn + wn + ni * 8 + 2 * q;
            if (split_heads) {
                int b = row >> 10;
                int s = row & (S_ - 1);
                int h = col >> 6;
                int d = col & (DH_ - 1);
                __half* oh = (__half*)out;
                if (blockIdx.z < 2) {
                    __half* dst = oh + (((size_t)(b * NH_ + h) * S_) + s) * DH_ + d;
                    *reinterpret_cast<__half2*>(dst) =
                        __floats2half2_rn(acc[mi][ni][0], acc[mi][ni][1]);
                    *reinterpret_cast<__half2*>(dst + 8 * DH_) =
                        __floats2half2_rn(acc[mi][ni][2], acc[mi][ni][3]);
                } else {
                    // V transposed: [B,NH,DH,S]
                    __half* base = oh + ((size_t)(b * NH_ + h) * DH_ + d) * S_ + s;
                    base[0]      = __float2half_rn(acc[mi][ni][0]);
                    base[S_]     = __float2half_rn(acc[mi][ni][1]);
                    base[8]      = __float2half_rn(acc[mi][ni][2]);
                    base[S_ + 8] = __float2half_rn(acc[mi][ni][3]);
                }
            } else {
                float* dst = (float*)out + (size_t)row * N_ + col;
                *reinterpret_cast<float2*>(dst) =
                    make_float2(acc[mi][ni][0], acc[mi][ni][1]);
                *reinterpret_cast<float2*>(dst + 8 * N_) =
                    make_float2(acc[mi][ni][2], acc[mi][ni][3]);
            }
        }
    }
}

// ---------------------------------------------------------------------------
// Flash attention, fp16 mma.m16n8k16 + ldmatrix, fp32 softmax/accumulate.
// 4 warps; warp w owns Q rows [16w,16w+16). V pre-transposed: [B,NH,DH,S].
// ---------------------------------------------------------------------------
constexpr int ALD = 72;                      // halves per row (64 + 8 pad)
constexpr int AT  = 64 * ALD;
constexpr int ATTN_SMEM = 5 * AT * (int)sizeof(__half);   // 46080 B

__global__ __launch_bounds__(128, 2)
void attn_kernel(const __half* __restrict__ qh, const __half* __restrict__ kh,
                 const __half* __restrict__ vh,
                 const float* __restrict__ maskf,
                 __half* __restrict__ ctx)
{
    extern __shared__ __half smh[];
    __half* QP = smh;            // Q tile, later reused for P
    __half* Ks = smh + AT;       // [2][64][ALD]
    __half* Vs = smh + 3 * AT;   // [2][64][ALD]  rows = d, cols = key

    const int bh = blockIdx.x;
    const int qt = blockIdx.y;
    const int b  = bh >> 4;
    const int h  = bh & (NH_ - 1);
    const int tid  = threadIdx.x;
    const int w    = tid >> 5;
    const int lane = tid & 31;
    const int g    = lane >> 2;
    const int q    = lane & 3;
    const int r0   = w * 16 + g;

    const int a_row = (lane & 7) + ((lane >> 3) & 1) * 8;
    const int a_k   = (lane >> 4) * 8;
    const int b_row = (lane & 7) + (lane >> 4) * 8;
    const int b_k   = ((lane >> 3) & 1) * 8;

    const __half* Qg = qh + ((size_t)bh * S_ + qt * 64) * DH_;
    const __half* Kg = kh + (size_t)bh * S_ * DH_;
    const __half* Vg = vh + (size_t)bh * DH_ * S_;
    const float* mrow = maskf + b * S_;

    #pragma unroll
    for (int i = 0; i < 4; i++) {
        int idx = tid + i * 128;
        int r = idx >> 3;
        int c = (idx & 7) << 3;
        *reinterpret_cast<uint4*>(QP + r * ALD + c) =
            *reinterpret_cast<const uint4*>(Qg + r * DH_ + c);
    }
    __syncthreads();

    auto kv_load = [&](int st, int kt) {
        #pragma unroll
        for (int i = 0; i < 4; i++) {
            int idx = tid + i * 128;
            int r = idx >> 3;
            int c = (idx & 7) << 3;
            cp16h(Ks + st * AT + r * ALD + c, Kg + (kt * 64 + r) * DH_ + c);
            cp16h(Vs + st * AT + r * ALD + c, Vg + r * S_ + kt * 64 + c);
        }
        cp_commit();
    };
    kv_load(0, 0);

    const unsigned QP_u = smem_u32(QP);

    // Persistent Q fragments via ldmatrix
    unsigned qa[4][4];
    #pragma unroll
    for (int ks = 0; ks < 4; ks++)
        ldsm4(qa[ks], QP_u + ((w * 16 + a_row) * ALD + ks * 16 + a_k) * 2);
    __syncthreads();   // all Q reads done before QP reused for P

    float oc[8][4];
    #pragma unroll
    for (int nt = 0; nt < 8; nt++)
        #pragma unroll
        for (int e = 0; e < 4; e++) oc[nt][e] = 0.f;
    float m0 = -CUDART_INF_F, m1 = -CUDART_INF_F;
    float l0 = 0.f, l1 = 0.f;

    for (int kt = 0; kt < S_ / 64; kt++) {
        const int cur = kt & 1;
        cp_wait_all();
        __syncthreads();
        if (kt + 1 < S_ / 64) kv_load(1 - cur, kt + 1);

        const unsigned Kc_u = smem_u32(Ks + cur * AT);
        const unsigned Vc_u = smem_u32(Vs + cur * AT);

        // S = Q @ K^T  (ldmatrix B-fragments: 2 n-tiles per x4)
        float sc[8][4];
        #pragma unroll
        for (int nt = 0; nt < 8; nt++)
            #pragma unroll
            for (int e = 0; e < 4; e++) sc[nt][e] = 0.f;
        #pragma unroll
        for (int ks = 0; ks < 4; ks++) {
            #pragma unroll
            for (int np = 0; np < 4; np++) {
                unsigned kf[4];
                ldsm4(kf, Kc_u + ((np * 16 + b_row) * ALD + ks * 16 + b_k) * 2);
                mma16(sc[2 * np],     qa[ks], kf[0], kf[1]);
                mma16(sc[2 * np + 1], qa[ks], kf[2], kf[3]);
            }
        }

        // scale + additive mask + row max
        float vx0 = -CUDART_INF_F, vx1 = -CUDART_INF_F;
        #pragma unroll
        for (int nt = 0; nt < 8; nt++) {
            float2 mf = *reinterpret_cast<const float2*>(
                mrow + kt * 64 + nt * 8 + 2 * q);
            sc[nt][0] = sc[nt][0] * 0.125f + mf.x;
            sc[nt][1] = sc[nt][1] * 0.125f + mf.y;
            sc[nt][2] = sc[nt][2] * 0.125f + mf.x;
            sc[nt][3] = sc[nt][3] * 0.125f + mf.y;
            vx0 = fmaxf(vx0, fmaxf(sc[nt][0], sc[nt][1]));
            vx1 = fmaxf(vx1, fmaxf(sc[nt][2], sc[nt][3]));
        }
        vx0 = fmaxf(vx0, __shfl_xor_sync(0xffffffffu, vx0, 1));
        vx0 = fmaxf(vx0, __shfl_xor_sync(0xffffffffu, vx0, 2));
        vx1 = fmaxf(vx1, __shfl_xor_sync(0xffffffffu, vx1, 1));
        vx1 = fmaxf(vx1, __shfl_xor_sync(0xffffffffu, vx1, 2));

        float mn0 = fmaxf(m0, vx0), mn1 = fmaxf(m1, vx1);
        float al0 = __expf(m0 - mn0), al1 = __expf(m1 - mn1);

        __syncwarp();   // prior PV ldmatrix reads of QP done before P overwrite
        float ps0 = 0.f, ps1 = 0.f;
        #pragma unroll
        for (int nt = 0; nt < 8; nt++) {
            float p0 = __expf(sc[nt][0] - mn0);
            float p1 = __expf(sc[nt][1] - mn0);
            float p2 = __expf(sc[nt][2] - mn1);
            float p3 = __expf(sc[nt][3] - mn1);
            ps0 += p0 + p1;
            ps1 += p2 + p3;
            *reinterpret_cast<__half2*>(QP + r0 * ALD + nt * 8 + 2 * q) =
                __floats2half2_rn(p0, p1);
            *reinterpret_cast<__half2*>(QP + (r0 + 8) * ALD + nt * 8 + 2 * q) =
                __floats2half2_rn(p2, p3);
        }
        ps0 += __shfl_xor_sync(0xffffffffu, ps0, 1);
        ps0 += __shfl_xor_sync(0xffffffffu, ps0, 2);
        ps1 += __shfl_xor_sync(0xffffffffu, ps1, 1);
        ps1 += __shfl_xor_sync(0xffffffffu, ps1, 2);
        l0 = l0 * al0 + ps0;
        l1 = l1 * al1 + ps1;
        m0 = mn0; m1 = mn1;

        #pragma unroll
        for (int nt = 0; nt < 8; nt++) {
            oc[nt][0] *= al0; oc[nt][1] *= al0;
            oc[nt][2] *= al1; oc[nt][3] *= al1;
        }

        __syncwarp();   // P visible to warp before ldmatrix loads

        // O += P @ V   (P a-fragments + V b-fragments via ldmatrix)
        #pragma unroll
        for (int ks = 0; ks < 4; ks++) {
            unsigned pa[4];
            ldsm4(pa, QP_u + ((w * 16 + a_row) * ALD + ks * 16 + a_k) * 2);
            #pragma unroll
            for (int np = 0; np < 4; np++) {
                unsigned vf[4];
                ldsm4(vf, Vc_u + ((np * 16 + b_row) * ALD + ks * 16 + b_k) * 2);
                mma16(oc[2 * np],     pa, vf[0], vf[1]);
                mma16(oc[2 * np + 1], pa, vf[2], vf[3]);
            }
        }
    }

    // Normalize + write merged ctx [B,S,H] (half)
    const float inv0 = 1.f / l0;
    const float inv1 = 1.f / l1;
    __half* dst0 = ctx + ((size_t)(b * S_ + qt * 64 + r0)) * H_ + h * DH_;
    __half* dst1 = dst0 + 8 * H_;
    #pragma unroll
    for (int nt = 0; nt < 8; nt++) {
        *reinterpret_cast<__half2*>(dst0 + nt * 8 + 2 * q) =
            __floats2half2_rn(oc[nt][0] * inv0, oc[nt][1] * inv0);
        *reinterpret_cast<__half2*>(dst1 + nt * 8 + 2 * q) =
            __floats2half2_rn(oc[nt][2] * inv1, oc[nt][3] * inv1);
    }
}

// ---------------------------------------------------------------------------
// Launch
// ---------------------------------------------------------------------------
extern "C" void kernel_launch(void* const* d_in, const int* in_sizes, int n_in,
                              void* d_out, int out_size)
{
    const float* v  = (const float*)d_in[0];
    const float* k  = (const float*)d_in[1];
    const float* q  = (const float*)d_in[2];
    const unsigned char* mask_raw = (const unsigned char*)d_in[3];
    const float* Wq = (const float*)d_in[4];
    const float* bq = (const float*)d_in[5];
    const float* Wk = (const float*)d_in[6];
    const float* bk = (const float*)d_in[7];
    const float* Wv = (const float*)d_in[8];
    const float* bv = (const float*)d_in[9];
    const float* Wm = (const float*)d_in[10];
    const float* bm = (const float*)d_in[11];
    float* out = (float*)d_out;

    __half *qh, *kh, *vh, *ctx;
    __half *qc, *kc, *vc, *wq, *wk, *wv, *wm;
    float *mnorm;
    cudaGetSymbolAddress((void**)&qh,  g_qh);
    cudaGetSymbolAddress((void**)&kh,  g_kh);
    cudaGetSymbolAddress((void**)&vh,  g_vh);
    cudaGetSymbolAddress((void**)&ctx, g_ctx);
    cudaGetSymbolAddress((void**)&mnorm, g_maskf);
    cudaGetSymbolAddress((void**)&qc, g_qc);
    cudaGetSymbolAddress((void**)&kc, g_kc);
    cudaGetSymbolAddress((void**)&vc, g_vc);
    cudaGetSymbolAddress((void**)&wq, g_wq);
    cudaGetSymbolAddress((void**)&wk, g_wk);
    cudaGetSymbolAddress((void**)&wv, g_wv);
    cudaGetSymbolAddress((void**)&wm, g_wm);

    cudaFuncSetAttribute(gemm3_kernel, cudaFuncAttributeMaxDynamicSharedMemorySize,
                         GEMM_SMEM);
    cudaFuncSetAttribute(attn_kernel, cudaFuncAttributeMaxDynamicSharedMemorySize,
                         ATTN_SMEM);

    // 0) mask + fused fp16 conversion of all GEMM inputs
    mask_norm_kernel<<<1, 256>>>(mask_raw, mnorm);
    cvt_all_kernel<<<(CVT_TOTAL + 255) / 256, 256>>>(q, k, v, Wq, Wk, Wv, Wm,
                                                     qc, kc, vc, wq, wk, wv, wm);

    // 1) fused QKV projections (Q,K split-head; V split-head transposed)
    dim3 gproj(N_ / BM, M_ / BM, 3);
    gemm3_kernel<<<gproj, GEMM_THREADS, GEMM_SMEM>>>(qc, wq, bq, qh,
                                                     kc, wk, bk, kh,
                                                     vc, wv, bv, vh, 1);

    // 2) attention -> merged ctx (half)
    dim3 gattn(B_ * NH_, S_ / 64);
    attn_kernel<<<gattn, 128, ATTN_SMEM>>>(qh, kh, vh, mnorm, ctx);

    // 3) output projection -> d_out (fp32)
    dim3 gout(N_ / BM, M_ / BM, 1);
    gemm3_kernel<<<gout, GEMM_THREADS, GEMM_SMEM>>>(ctx, wm, bm, out,
                                                    ctx, wm, bm, out,
                                                    ctx, wm, bm, out, 0);
}

// round 15
// speedup vs baseline: 4.5484x; 1.0230x over previous
#include <cuda_runtime.h>
#include <cuda_fp16.h>
#include <math_constants.h>

#define B_   8
#define S_   1024
#define H_   1024
#define NH_  16
#define DH_  64
#define M_   (B_ * S_)   // 8192
#define N_   H_
#define K_   H_

// Scratch: device globals (no cudaMalloc allowed)
__device__ __half g_qh[B_ * NH_ * S_ * DH_];   // [B,NH,S,DH]
__device__ __half g_kh[B_ * NH_ * S_ * DH_];   // [B,NH,S,DH]
__device__ __half g_vh[B_ * NH_ * DH_ * S_];   // [B,NH,DH,S]  (transposed!)
__device__ __half g_ctx[B_ * S_ * H_];         // merged [B,S,H]
__device__ float  g_maskf[B_ * S_];            // additive mask: 0 or -1e9
// fp16 copies of inputs
__device__ __half g_qc[M_ * K_];
__device__ __half g_kc[M_ * K_];
__device__ __half g_vc[M_ * K_];
__device__ __half g_wq[H_ * H_];
__device__ __half g_wk[H_ * H_];
__device__ __half g_wv[H_ * H_];
__device__ __half g_wm[H_ * H_];

// ---------------------------------------------------------------------------
// PTX helpers (mma.sync / cp.async / ldmatrix only — NO tcgen05 on this
// toolchain: PTX targets sm_103 which rejects accelerated-feature instrs)
// ---------------------------------------------------------------------------
__device__ __forceinline__ void mma16(float c[4], const unsigned a[4],
                                      unsigned b0, unsigned b1) {
    asm volatile(
        "mma.sync.aligned.m16n8k16.row.col.f32.f16.f16.f32 "
        "{%0,%1,%2,%3}, {%4,%5,%6,%7}, {%8,%9}, {%0,%1,%2,%3};"
        : "+f"(c[0]), "+f"(c[1]), "+f"(c[2]), "+f"(c[3])
        : "r"(a[0]), "r"(a[1]), "r"(a[2]), "r"(a[3]), "r"(b0), "r"(b1));
}
__device__ __forceinline__ void ldsm4(unsigned r[4], unsigned sa) {
    asm volatile("ldmatrix.sync.aligned.m8n8.x4.shared.b16 {%0,%1,%2,%3}, [%4];"
                 : "=r"(r[0]), "=r"(r[1]), "=r"(r[2]), "=r"(r[3]) : "r"(sa));
}
__device__ __forceinline__ void cp16h(__half* smem, const __half* g) {
    unsigned s = (unsigned)__cvta_generic_to_shared(smem);
    asm volatile("cp.async.cg.shared.global [%0], [%1], 16;" :: "r"(s), "l"(g)
                 : "memory");
}
__device__ __forceinline__ void cp_commit() {
    asm volatile("cp.async.commit_group;" ::: "memory");
}
__device__ __forceinline__ void cp_wait_all() {
    asm volatile("cp.async.wait_group 0;" ::: "memory");
}
__device__ __forceinline__ unsigned smem_u32(const void* p) {
    return (unsigned)__cvta_generic_to_shared(p);
}
__device__ __forceinline__ unsigned packh2(float a, float b) {
    __half2 h = __floats2half2_rn(a, b);
    return *reinterpret_cast<unsigned*>(&h);
}

// ---------------------------------------------------------------------------
// Fused fp32 -> fp16 conversion for all 7 tensors (one launch).
// ---------------------------------------------------------------------------
constexpr int BIG4   = (M_ * K_) / 4;
constexpr int SMALL4 = (H_ * H_) / 4;
constexpr int CVT_TOTAL = 3 * BIG4 + 4 * SMALL4;

__global__ void cvt_all_kernel(const float* __restrict__ q,
                               const float* __restrict__ k,
                               const float* __restrict__ v,
                               const float* __restrict__ wq,
                               const float* __restrict__ wk,
                               const float* __restrict__ wv,
                               const float* __restrict__ wm,
                               __half* __restrict__ qo, __half* __restrict__ ko,
                               __half* __restrict__ vo, __half* __restrict__ wqo,
                               __half* __restrict__ wko, __half* __restrict__ wvo,
                               __half* __restrict__ wmo)
{
    int i = blockIdx.x * blockDim.x + threadIdx.x;
    if (i >= CVT_TOTAL) return;
    const float* in; __half* out; int off;
    if (i < 3 * BIG4) {
        int s = i / BIG4;
        off = i - s * BIG4;
        in  = (s == 0) ? q : (s == 1) ? k : v;
        out = (s == 0) ? qo : (s == 1) ? ko : vo;
    } else {
        int j = i - 3 * BIG4;
        int s = j / SMALL4;
        off = j - s * SMALL4;
        in  = (s == 0) ? wq : (s == 1) ? wk : (s == 2) ? wv : wm;
        out = (s == 0) ? wqo : (s == 1) ? wko : (s == 2) ? wvo : wmo;
    }
    float4 vv = reinterpret_cast<const float4*>(in)[off];
    __half2 h0 = __floats2half2_rn(vv.x, vv.y);
    __half2 h1 = __floats2half2_rn(vv.z, vv.w);
    uint2 o;
    o.x = *reinterpret_cast<unsigned*>(&h0);
    o.y = *reinterpret_cast<unsigned*>(&h1);
    reinterpret_cast<uint2*>(out)[off] = o;
}

// ---------------------------------------------------------------------------
// Mask dtype detection + normalization -> additive float mask (0 / -1e9).
// ---------------------------------------------------------------------------
__global__ void mask_norm_kernel(const unsigned char* __restrict__ raw,
                                 float* __restrict__ outm)
{
    __shared__ int cnt[4];
    const int tid = threadIdx.x;
    if (tid < 4) cnt[tid] = 0;
    __syncthreads();

    int loc[4] = {0, 0, 0, 0};
    for (int i = tid; i < B_ * S_; i += blockDim.x)
        if (raw[i]) loc[i & 3]++;
    #pragma unroll
    for (int r = 0; r < 4; r++)
        if (loc[r]) atomicAdd(&cnt[r], loc[r]);
    __syncthreads();

    const int c0 = cnt[0], c1 = cnt[1], c2 = cnt[2], c3 = cnt[3];
    int mode;
    if (c0 > 0 && c1 == 0 && c2 == 0 && c3 == 0)       mode = 1;
    else if (c0 == 0 && c1 == 0 && (c2 > 0 || c3 > 0)) mode = 2;
    else                                               mode = 0;

    if (mode == 0) {
        for (int i = tid; i < B_ * S_; i += blockDim.x)
            outm[i] = raw[i] ? -1e9f : 0.f;
    } else if (mode == 1) {
        const int* p = (const int*)raw;
        for (int i = tid; i < B_ * S_; i += blockDim.x)
            outm[i] = p[i] ? -1e9f : 0.f;
    } else {
        const float* p = (const float*)raw;
        for (int i = tid; i < B_ * S_; i += blockDim.x)
            outm[i] = (p[i] != 0.0f) ? -1e9f : 0.f;
    }
}

// ---------------------------------------------------------------------------
// GEMM: C = A[M,K] @ W[N,K]^T + bias, fp16 mma.m16n8k16, fp32 accumulate.
// 4 warps, 64x64 warp tile, ldmatrix.x4 fragment loads, BK=64, 2 stages.
// ---------------------------------------------------------------------------
constexpr int BM = 128, BN = 128, BK = 64;
constexpr int GEMM_THREADS = 128;
constexpr int GLD = 72;
constexpr int STG_HALFS = 2 * BM * GLD;
constexpr int GEMM_SMEM  = 2 * STG_HALFS * (int)sizeof(__half);  // 73728 B

__global__ __launch_bounds__(GEMM_THREADS, 2)
void gemm3_kernel(const __half* __restrict__ A0, const __half* __restrict__ W0,
                  const float* __restrict__ b0, void* __restrict__ o0,
                  const __half* __restrict__ A1, const __half* __restrict__ W1,
                  const float* __restrict__ b1, void* __restrict__ o1,
                  const __half* __restrict__ A2, const __half* __restrict__ W2,
                  const float* __restrict__ b2, void* __restrict__ o2,
                  int split_heads)
{
    extern __shared__ __half gsmh[];

    const __half* A; const __half* W; const float* bias; void* out;
    if (blockIdx.z == 0)      { A = A0; W = W0; bias = b0; out = o0; }
    else if (blockIdx.z == 1) { A = A1; W = W1; bias = b1; out = o1; }
    else                      { A = A2; W = W2; bias = b2; out = o2; }

    const int tid  = threadIdx.x;
    const int warp = tid >> 5;
    const int lane = tid & 31;
    const int g    = lane >> 2;
    const int q    = lane & 3;
    const int wm   = (warp >> 1) * 64;
    const int wn   = (warp & 1) * 64;
    const int bm   = blockIdx.y * BM;
    const int bn   = blockIdx.x * BN;

    const int a_row = (lane & 7) + ((lane >> 3) & 1) * 8;
    const int a_k   = (lane >> 4) * 8;
    const int b_row = (lane & 7) + (lane >> 4) * 8;
    const int b_k   = ((lane >> 3) & 1) * 8;

    float acc[4][8][4];
    #pragma unroll
    for (int ni = 0; ni < 8; ni++) {
        float2 bv = *reinterpret_cast<const float2*>(bias + bn + wn + ni * 8 + 2 * q);
        #pragma unroll
        for (int mi = 0; mi < 4; mi++) {
            acc[mi][ni][0] = bv.x; acc[mi][ni][1] = bv.y;
            acc[mi][ni][2] = bv.x; acc[mi][ni][3] = bv.y;
        }
    }

    const __half* Ap = A + (size_t)bm * K_;
    const __half* Wp = W + (size_t)bn * K_;

    auto preload = [&](int st, int k0) {
        __half* As = gsmh + st * STG_HALFS;
        __half* Ws = As + BM * GLD;
        #pragma unroll
        for (int i = 0; i < 8; i++) {
            int idx = tid + i * GEMM_THREADS;
            int r = idx >> 3;
            int c = (idx & 7) << 3;
            cp16h(As + r * GLD + c, Ap + r * K_ + k0 + c);
            cp16h(Ws + r * GLD + c, Wp + r * K_ + k0 + c);
        }
        cp_commit();
    };

    preload(0, 0);

    for (int it = 0; it < K_ / BK; it++) {
        int cur = it & 1;
        cp_wait_all();
        __syncthreads();
        if (it + 1 < K_ / BK) preload(1 - cur, (it + 1) * BK);

        const __half* As = gsmh + cur * STG_HALFS;
        const __half* Ws = As + BM * GLD;
        const unsigned As_u = smem_u32(As);
        const unsigned Ws_u = smem_u32(Ws);

        #pragma unroll
        for (int kk = 0; kk < BK; kk += 16) {
            unsigned af[4][4];
            #pragma unroll
            for (int mi = 0; mi < 4; mi++)
                ldsm4(af[mi], As_u + ((wm + mi * 16 + a_row) * GLD + kk + a_k) * 2);
            #pragma unroll
            for (int np = 0; np < 4; np++) {
                unsigned bf[4];
                ldsm4(bf, Ws_u + ((wn + np * 16 + b_row) * GLD + kk + b_k) * 2);
                #pragma unroll
                for (int mi = 0; mi < 4; mi++) {
                    mma16(acc[mi][2 * np],     af[mi], bf[0], bf[1]);
                    mma16(acc[mi][2 * np + 1], af[mi], bf[2], bf[3]);
                }
            }
        }
    }

    #pragma unroll
    for (int mi = 0; mi < 4; mi++) {
        #pragma unroll
        for (int ni = 0; ni < 8; ni++) {
            int row = bm + wm + mi * 16 + g;
            int col = bn + wn + ni * 8 + 2 * q;
            if (split_heads) {
                int b = row >> 10;
                int s = row & (S_ - 1);
                int h = col >> 6;
                int d = col & (DH_ - 1);
                __half* oh = (__half*)out;
                if (blockIdx.z < 2) {
                    __half* dst = oh + (((size_t)(b * NH_ + h) * S_) + s) * DH_ + d;
                    *reinterpret_cast<__half2*>(dst) =
                        __floats2half2_rn(acc[mi][ni][0], acc[mi][ni][1]);
                    *reinterpret_cast<__half2*>(dst + 8 * DH_) =
                        __floats2half2_rn(acc[mi][ni][2], acc[mi][ni][3]);
                } else {
                    __half* base = oh + ((size_t)(b * NH_ + h) * DH_ + d) * S_ + s;
                    base[0]      = __float2half_rn(acc[mi][ni][0]);
                    base[S_]     = __float2half_rn(acc[mi][ni][1]);
                    base[8]      = __float2half_rn(acc[mi][ni][2]);
                    base[S_ + 8] = __float2half_rn(acc[mi][ni][3]);
                }
            } else {
                float* dst = (float*)out + (size_t)row * N_ + col;
                *reinterpret_cast<float2*>(dst) =
                    make_float2(acc[mi][ni][0], acc[mi][ni][1]);
                *reinterpret_cast<float2*>(dst + 8 * N_) =
                    make_float2(acc[mi][ni][2], acc[mi][ni][3]);
            }
        }
    }
}

// ---------------------------------------------------------------------------
// Flash attention, fp16 mma + ldmatrix. P stays in REGISTERS:
// S-accumulator layout (c0,c1=row g cols 2q,2q+1; c2,c3=row g+8) IS the
// A-fragment layout for PV step ks (pa[0..3] from sc[2ks],sc[2ks+1]).
// No P smem round-trip, no __syncwarp.
// ---------------------------------------------------------------------------
constexpr int ALD = 72;
constexpr int AT  = 64 * ALD;
constexpr int ATTN_SMEM = 5 * AT * (int)sizeof(__half);   // 46080 B

__global__ __launch_bounds__(128, 2)
void attn_kernel(const __half* __restrict__ qh, const __half* __restrict__ kh,
                 const __half* __restrict__ vh,
                 const float* __restrict__ maskf,
                 __half* __restrict__ ctx)
{
    extern __shared__ __half smh[];
    __half* QP = smh;            // Q staging only
    __half* Ks = smh + AT;       // [2][64][ALD]
    __half* Vs = smh + 3 * AT;   // [2][64][ALD]  rows = d, cols = key

    const int bh = blockIdx.x;
    const int qt = blockIdx.y;
    const int b  = bh >> 4;
    const int h  = bh & (NH_ - 1);
    const int tid  = threadIdx.x;
    const int w    = tid >> 5;
    const int lane = tid & 31;
    const int g    = lane >> 2;
    const int q    = lane & 3;
    const int r0   = w * 16 + g;

    const int a_row = (lane & 7) + ((lane >> 3) & 1) * 8;
    const int a_k   = (lane >> 4) * 8;
    const int b_row = (lane & 7) + (lane >> 4) * 8;
    const int b_k   = ((lane >> 3) & 1) * 8;

    const __half* Qg = qh + ((size_t)bh * S_ + qt * 64) * DH_;
    const __half* Kg = kh + (size_t)bh * S_ * DH_;
    const __half* Vg = vh + (size_t)bh * DH_ * S_;
    const float* mrow = maskf + b * S_;

    #pragma unroll
    for (int i = 0; i < 4; i++) {
        int idx = tid + i * 128;
        int r = idx >> 3;
        int c = (idx & 7) << 3;
        *reinterpret_cast<uint4*>(QP + r * ALD + c) =
            *reinterpret_cast<const uint4*>(Qg + r * DH_ + c);
    }
    __syncthreads();

    auto kv_load = [&](int st, int kt) {
        #pragma unroll
        for (int i = 0; i < 4; i++) {
            int idx = tid + i * 128;
            int r = idx >> 3;
            int c = (idx & 7) << 3;
            cp16h(Ks + st * AT + r * ALD + c, Kg + (kt * 64 + r) * DH_ + c);
            cp16h(Vs + st * AT + r * ALD + c, Vg + r * S_ + kt * 64 + c);
        }
        cp_commit();
    };
    kv_load(0, 0);

    const unsigned QP_u = smem_u32(QP);

    unsigned qa[4][4];
    #pragma unroll
    for (int ks = 0; ks < 4; ks++)
        ldsm4(qa[ks], QP_u + ((w * 16 + a_row) * ALD + ks * 16 + a_k) * 2);

    float oc[8][4];
    #pragma unroll
    for (int nt = 0; nt < 8; nt++)
        #pragma unroll
        for (int e = 0; e < 4; e++) oc[nt][e] = 0.f;
    float m0 = -CUDART_INF_F, m1 = -CUDART_INF_F;
    float l0 = 0.f, l1 = 0.f;

    for (int kt = 0; kt < S_ / 64; kt++) {
        const int cur = kt & 1;
        cp_wait_all();
        __syncthreads();
        if (kt + 1 < S_ / 64) kv_load(1 - cur, kt + 1);

        const unsigned Kc_u = smem_u32(Ks + cur * AT);
        const unsigned Vc_u = smem_u32(Vs + cur * AT);

        // S = Q @ K^T
        float sc[8][4];
        #pragma unroll
        for (int nt = 0; nt < 8; nt++)
            #pragma unroll
            for (int e = 0; e < 4; e++) sc[nt][e] = 0.f;
        #pragma unroll
        for (int ks = 0; ks < 4; ks++) {
            #pragma unroll
            for (int np = 0; np < 4; np++) {
                unsigned kf[4];
                ldsm4(kf, Kc_u + ((np * 16 + b_row) * ALD + ks * 16 + b_k) * 2);
                mma16(sc[2 * np],     qa[ks], kf[0], kf[1]);
                mma16(sc[2 * np + 1], qa[ks], kf[2], kf[3]);
            }
        }

        // scale + additive mask + row max
        float vx0 = -CUDART_INF_F, vx1 = -CUDART_INF_F;
        #pragma unroll
        for (int nt = 0; nt < 8; nt++) {
            float2 mf = *reinterpret_cast<const float2*>(
                mrow + kt * 64 + nt * 8 + 2 * q);
            sc[nt][0] = sc[nt][0] * 0.125f + mf.x;
            sc[nt][1] = sc[nt][1] * 0.125f + mf.y;
            sc[nt][2] = sc[nt][2] * 0.125f + mf.x;
            sc[nt][3] = sc[nt][3] * 0.125f + mf.y;
            vx0 = fmaxf(vx0, fmaxf(sc[nt][0], sc[nt][1]));
            vx1 = fmaxf(vx1, fmaxf(sc[nt][2], sc[nt][3]));
        }
        vx0 = fmaxf(vx0, __shfl_xor_sync(0xffffffffu, vx0, 1));
        vx0 = fmaxf(vx0, __shfl_xor_sync(0xffffffffu, vx0, 2));
        vx1 = fmaxf(vx1, __shfl_xor_sync(0xffffffffu, vx1, 1));
        vx1 = fmaxf(vx1, __shfl_xor_sync(0xffffffffu, vx1, 2));

        float mn0 = fmaxf(m0, vx0), mn1 = fmaxf(m1, vx1);
        float al0 = __expf(m0 - mn0), al1 = __expf(m1 - mn1);

        // exp in place (P stays in sc registers)
        float ps0 = 0.f, ps1 = 0.f;
        #pragma unroll
        for (int nt = 0; nt < 8; nt++) {
            sc[nt][0] = __expf(sc[nt][0] - mn0);
            sc[nt][1] = __expf(sc[nt][1] - mn0);
            sc[nt][2] = __expf(sc[nt][2] - mn1);
            sc[nt][3] = __expf(sc[nt][3] - mn1);
            ps0 += sc[nt][0] + sc[nt][1];
            ps1 += sc[nt][2] + sc[nt][3];
        }
        ps0 += __shfl_xor_sync(0xffffffffu, ps0, 1);
        ps0 += __shfl_xor_sync(0xffffffffu, ps0, 2);
        ps1 += __shfl_xor_sync(0xffffffffu, ps1, 1);
        ps1 += __shfl_xor_sync(0xffffffffu, ps1, 2);
        l0 = l0 * al0 + ps0;
        l1 = l1 * al1 + ps1;
        m0 = mn0; m1 = mn1;

        #pragma unroll
        for (int nt = 0; nt < 8; nt++) {
            oc[nt][0] *= al0; oc[nt][1] *= al0;
            oc[nt][2] *= al1; oc[nt][3] *= al1;
        }

        // O += P @ V  — P fragments packed directly from sc registers:
        // step ks uses sc[2ks] (cols 16ks+2q, rows g/g+8) and sc[2ks+1] (+8)
        #pragma unroll
        for (int ks = 0; ks < 4; ks++) {
            unsigned pa[4];
            pa[0] = packh2(sc[2 * ks][0],     sc[2 * ks][1]);
            pa[1] = packh2(sc[2 * ks][2],     sc[2 * ks][3]);
            pa[2] = packh2(sc[2 * ks + 1][0], sc[2 * ks + 1][1]);
            pa[3] = packh2(sc[2 * ks + 1][2], sc[2 * ks + 1][3]);
            #pragma unroll
            for (int np = 0; np < 4; np++) {
                unsigned vf[4];
                ldsm4(vf, Vc_u + ((np * 16 + b_row) * ALD + ks * 16 + b_k) * 2);
                mma16(oc[2 * np],     pa, vf[0], vf[1]);
                mma16(oc[2 * np + 1], pa, vf[2], vf[3]);
            }
        }
    }

    // Normalize + write merged ctx [B,S,H] (half)
    const float inv0 = 1.f / l0;
    const float inv1 = 1.f / l1;
    __half* dst0 = ctx + ((size_t)(b * S_ + qt * 64 + r0)) * H_ + h * DH_;
    __half* dst1 = dst0 + 8 * H_;
    #pragma unroll
    for (int nt = 0; nt < 8; nt++) {
        *reinterpret_cast<__half2*>(dst0 + nt * 8 + 2 * q) =
            __floats2half2_rn(oc[nt][0] * inv0, oc[nt][1] * inv0);
        *reinterpret_cast<__half2*>(dst1 + nt * 8 + 2 * q) =
            __floats2half2_rn(oc[nt][2] * inv1, oc[nt][3] * inv1);
    }
}

// ---------------------------------------------------------------------------
// Launch
// ---------------------------------------------------------------------------
extern "C" void kernel_launch(void* const* d_in, const int* in_sizes, int n_in,
                              void* d_out, int out_size)
{
    const float* v  = (const float*)d_in[0];
    const float* k  = (const float*)d_in[1];
    const float* q  = (const float*)d_in[2];
    const unsigned char* mask_raw = (const unsigned char*)d_in[3];
    const float* Wq = (const float*)d_in[4];
    const float* bq = (const float*)d_in[5];
    const float* Wk = (const float*)d_in[6];
    const float* bk = (const float*)d_in[7];
    const float* Wv = (const float*)d_in[8];
    const float* bv = (const float*)d_in[9];
    const float* Wm = (const float*)d_in[10];
    const float* bm = (const float*)d_in[11];
    float* out = (float*)d_out;

    __half *qh, *kh, *vh, *ctx;
    __half *qc, *kc, *vc, *wq, *wk, *wv, *wm;
    float *mnorm;
    cudaGetSymbolAddress((void**)&qh,  g_qh);
    cudaGetSymbolAddress((void**)&kh,  g_kh);
    cudaGetSymbolAddress((void**)&vh,  g_vh);
    cudaGetSymbolAddress((void**)&ctx, g_ctx);
    cudaGetSymbolAddress((void**)&mnorm, g_maskf);
    cudaGetSymbolAddress((void**)&qc, g_qc);
    cudaGetSymbolAddress((void**)&kc, g_kc);
    cudaGetSymbolAddress((void**)&vc, g_vc);
    cudaGetSymbolAddress((void**)&wq, g_wq);
    cudaGetSymbolAddress((void**)&wk, g_wk);
    cudaGetSymbolAddress((void**)&wv, g_wv);
    cudaGetSymbolAddress((void**)&wm, g_wm);

    cudaFuncSetAttribute(gemm3_kernel, cudaFuncAttributeMaxDynamicSharedMemorySize,
                         GEMM_SMEM);
    cudaFuncSetAttribute(attn_kernel, cudaFuncAttributeMaxDynamicSharedMemorySize,
                         ATTN_SMEM);

    // 0) mask + fused fp16 conversion of all GEMM inputs
    mask_norm_kernel<<<1, 256>>>(mask_raw, mnorm);
    cvt_all_kernel<<<(CVT_TOTAL + 255) / 256, 256>>>(q, k, v, Wq, Wk, Wv, Wm,
                                                     qc, kc, vc, wq, wk, wv, wm);

    // 1) fused QKV projections (Q,K split-head; V split-head transposed)
    dim3 gproj(N_ / BM, M_ / BM, 3);
    gemm3_kernel<<<gproj, GEMM_THREADS, GEMM_SMEM>>>(qc, wq, bq, qh,
                                                     kc, wk, bk, kh,
                                                     vc, wv, bv, vh, 1);

    // 2) attention -> merged ctx (half)
    dim3 gattn(B_ * NH_, S_ / 64);
    attn_kernel<<<gattn, 128, ATTN_SMEM>>>(qh, kh, vh, mnorm, ctx);

    // 3) output projection -> d_out (fp32)
    dim3 gout(N_ / BM, M_ / BM, 1);
    gemm3_kernel<<<gout, GEMM_THREADS, GEMM_SMEM>>>(ctx, wm, bm, out,
                                                    ctx, wm, bm, out,
                                                    ctx, wm, bm, out, 0);
}

// round 16
// speedup vs baseline: 4.5698x; 1.0047x over previous
#include <cuda_runtime.h>
#include <cuda_fp16.h>
#include <math_constants.h>

#define B_   8
#define S_   1024
#define H_   1024
#define NH_  16
#define DH_  64
#define M_   (B_ * S_)   // 8192
#define N_   H_
#define K_   H_

// Scratch: device globals (no cudaMalloc allowed)
__device__ __half g_qh[B_ * NH_ * S_ * DH_];   // [B,NH,S,DH]
__device__ __half g_kh[B_ * NH_ * S_ * DH_];   // [B,NH,S,DH]
__device__ __half g_vh[B_ * NH_ * DH_ * S_];   // [B,NH,DH,S]  (transposed!)
__device__ __half g_ctx[B_ * S_ * H_];         // merged [B,S,H]
__device__ float  g_maskf[B_ * S_];            // additive mask in LOG2 domain
// fp16 copies of inputs
__device__ __half g_qc[M_ * K_];
__device__ __half g_kc[M_ * K_];
__device__ __half g_vc[M_ * K_];
__device__ __half g_wq[H_ * H_];
__device__ __half g_wk[H_ * H_];
__device__ __half g_wv[H_ * H_];
__device__ __half g_wm[H_ * H_];

#define LOG2E 1.4426950408889634f

// ---------------------------------------------------------------------------
// PTX helpers (mma.sync / cp.async / ldmatrix only — NO tcgen05 on this
// toolchain: PTX targets sm_103 which rejects accelerated-feature instrs)
// ---------------------------------------------------------------------------
__device__ __forceinline__ void mma16(float c[4], const unsigned a[4],
                                      unsigned b0, unsigned b1) {
    asm volatile(
        "mma.sync.aligned.m16n8k16.row.col.f32.f16.f16.f32 "
        "{%0,%1,%2,%3}, {%4,%5,%6,%7}, {%8,%9}, {%0,%1,%2,%3};"
        : "+f"(c[0]), "+f"(c[1]), "+f"(c[2]), "+f"(c[3])
        : "r"(a[0]), "r"(a[1]), "r"(a[2]), "r"(a[3]), "r"(b0), "r"(b1));
}
__device__ __forceinline__ void ldsm4(unsigned r[4], unsigned sa) {
    asm volatile("ldmatrix.sync.aligned.m8n8.x4.shared.b16 {%0,%1,%2,%3}, [%4];"
                 : "=r"(r[0]), "=r"(r[1]), "=r"(r[2]), "=r"(r[3]) : "r"(sa));
}
__device__ __forceinline__ void cp16h(__half* smem, const __half* g) {
    unsigned s = (unsigned)__cvta_generic_to_shared(smem);
    asm volatile("cp.async.cg.shared.global [%0], [%1], 16;" :: "r"(s), "l"(g)
                 : "memory");
}
__device__ __forceinline__ void cp_commit() {
    asm volatile("cp.async.commit_group;" ::: "memory");
}
__device__ __forceinline__ void cp_wait_all() {
    asm volatile("cp.async.wait_group 0;" ::: "memory");
}
__device__ __forceinline__ unsigned smem_u32(const void* p) {
    return (unsigned)__cvta_generic_to_shared(p);
}
__device__ __forceinline__ unsigned packh2(float a, float b) {
    __half2 h = __floats2half2_rn(a, b);
    return *reinterpret_cast<unsigned*>(&h);
}

// ---------------------------------------------------------------------------
// Fused fp32 -> fp16 conversion for all 7 tensors (one launch).
// ---------------------------------------------------------------------------
constexpr int BIG4   = (M_ * K_) / 4;
constexpr int SMALL4 = (H_ * H_) / 4;
constexpr int CVT_TOTAL = 3 * BIG4 + 4 * SMALL4;

__global__ void cvt_all_kernel(const float* __restrict__ q,
                               const float* __restrict__ k,
                               const float* __restrict__ v,
                               const float* __restrict__ wq,
                               const float* __restrict__ wk,
                               const float* __restrict__ wv,
                               const float* __restrict__ wm,
                               __half* __restrict__ qo, __half* __restrict__ ko,
                               __half* __restrict__ vo, __half* __restrict__ wqo,
                               __half* __restrict__ wko, __half* __restrict__ wvo,
                               __half* __restrict__ wmo)
{
    int i = blockIdx.x * blockDim.x + threadIdx.x;
    if (i >= CVT_TOTAL) return;
    const float* in; __half* out; int off;
    if (i < 3 * BIG4) {
        int s = i / BIG4;
        off = i - s * BIG4;
        in  = (s == 0) ? q : (s == 1) ? k : v;
        out = (s == 0) ? qo : (s == 1) ? ko : vo;
    } else {
        int j = i - 3 * BIG4;
        int s = j / SMALL4;
        off = j - s * SMALL4;
        in  = (s == 0) ? wq : (s == 1) ? wk : (s == 2) ? wv : wm;
        out = (s == 0) ? wqo : (s == 1) ? wko : (s == 2) ? wvo : wmo;
    }
    float4 vv = reinterpret_cast<const float4*>(in)[off];
    __half2 h0 = __floats2half2_rn(vv.x, vv.y);
    __half2 h1 = __floats2half2_rn(vv.z, vv.w);
    uint2 o;
    o.x = *reinterpret_cast<unsigned*>(&h0);
    o.y = *reinterpret_cast<unsigned*>(&h1);
    reinterpret_cast<uint2*>(out)[off] = o;
}

// ---------------------------------------------------------------------------
// Mask dtype detection + normalization -> additive mask in LOG2 domain
// (0 or -LOG2E*1e9), so softmax uses exp2 with no per-element mul.
// ---------------------------------------------------------------------------
__global__ void mask_norm_kernel(const unsigned char* __restrict__ raw,
                                 float* __restrict__ outm)
{
    __shared__ int cnt[4];
    const int tid = threadIdx.x;
    if (tid < 4) cnt[tid] = 0;
    __syncthreads();

    int loc[4] = {0, 0, 0, 0};
    for (int i = tid; i < B_ * S_; i += blockDim.x)
        if (raw[i]) loc[i & 3]++;
    #pragma unroll
    for (int r = 0; r < 4; r++)
        if (loc[r]) atomicAdd(&cnt[r], loc[r]);
    __syncthreads();

    const float MASKVAL = -LOG2E * 1e9f;
    const int c0 = cnt[0], c1 = cnt[1], c2 = cnt[2], c3 = cnt[3];
    int mode;
    if (c0 > 0 && c1 == 0 && c2 == 0 && c3 == 0)       mode = 1;
    else if (c0 == 0 && c1 == 0 && (c2 > 0 || c3 > 0)) mode = 2;
    else                                               mode = 0;

    if (mode == 0) {
        for (int i = tid; i < B_ * S_; i += blockDim.x)
            outm[i] = raw[i] ? MASKVAL : 0.f;
    } else if (mode == 1) {
        const int* p = (const int*)raw;
        for (int i = tid; i < B_ * S_; i += blockDim.x)
            outm[i] = p[i] ? MASKVAL : 0.f;
    } else {
        const float* p = (const float*)raw;
        for (int i = tid; i < B_ * S_; i += blockDim.x)
            outm[i] = (p[i] != 0.0f) ? MASKVAL : 0.f;
    }
}

// ---------------------------------------------------------------------------
// GEMM: C = A[M,K] @ W[N,K]^T + bias, fp16 mma.m16n8k16, fp32 accumulate.
// 4 warps, 64x64 warp tile, ldmatrix.x4 fragment loads, BK=64, 2 stages.
// (unchanged — control)
// ---------------------------------------------------------------------------
constexpr int BM = 128, BN = 128, BK = 64;
constexpr int GEMM_THREADS = 128;
constexpr int GLD = 72;
constexpr int STG_HALFS = 2 * BM * GLD;
constexpr int GEMM_SMEM  = 2 * STG_HALFS * (int)sizeof(__half);  // 73728 B

__global__ __launch_bounds__(GEMM_THREADS, 2)
void gemm3_kernel(const __half* __restrict__ A0, const __half* __restrict__ W0,
                  const float* __restrict__ b0, void* __restrict__ o0,
                  const __half* __restrict__ A1, const __half* __restrict__ W1,
                  const float* __restrict__ b1, void* __restrict__ o1,
                  const __half* __restrict__ A2, const __half* __restrict__ W2,
                  const float* __restrict__ b2, void* __restrict__ o2,
                  int split_heads)
{
    extern __shared__ __half gsmh[];

    const __half* A; const __half* W; const float* bias; void* out;
    if (blockIdx.z == 0)      { A = A0; W = W0; bias = b0; out = o0; }
    else if (blockIdx.z == 1) { A = A1; W = W1; bias = b1; out = o1; }
    else                      { A = A2; W = W2; bias = b2; out = o2; }

    const int tid  = threadIdx.x;
    const int warp = tid >> 5;
    const int lane = tid & 31;
    const int g    = lane >> 2;
    const int q    = lane & 3;
    const int wm   = (warp >> 1) * 64;
    const int wn   = (warp & 1) * 64;
    const int bm   = blockIdx.y * BM;
    const int bn   = blockIdx.x * BN;

    const int a_row = (lane & 7) + ((lane >> 3) & 1) * 8;
    const int a_k   = (lane >> 4) * 8;
    const int b_row = (lane & 7) + (lane >> 4) * 8;
    const int b_k   = ((lane >> 3) & 1) * 8;

    float acc[4][8][4];
    #pragma unroll
    for (int ni = 0; ni < 8; ni++) {
        float2 bv = *reinterpret_cast<const float2*>(bias + bn + wn + ni * 8 + 2 * q);
        #pragma unroll
        for (int mi = 0; mi < 4; mi++) {
            acc[mi][ni][0] = bv.x; acc[mi][ni][1] = bv.y;
            acc[mi][ni][2] = bv.x; acc[mi][ni][3] = bv.y;
        }
    }

    const __half* Ap = A + (size_t)bm * K_;
    const __half* Wp = W + (size_t)bn * K_;

    auto preload = [&](int st, int k0) {
        __half* As = gsmh + st * STG_HALFS;
        __half* Ws = As + BM * GLD;
        #pragma unroll
        for (int i = 0; i < 8; i++) {
            int idx = tid + i * GEMM_THREADS;
            int r = idx >> 3;
            int c = (idx & 7) << 3;
            cp16h(As + r * GLD + c, Ap + r * K_ + k0 + c);
            cp16h(Ws + r * GLD + c, Wp + r * K_ + k0 + c);
        }
        cp_commit();
    };

    preload(0, 0);

    for (int it = 0; it < K_ / BK; it++) {
        int cur = it & 1;
        cp_wait_all();
        __syncthreads();
        if (it + 1 < K_ / BK) preload(1 - cur, (it + 1) * BK);

        const __half* As = gsmh + cur * STG_HALFS;
        const __half* Ws = As + BM * GLD;
        const unsigned As_u = smem_u32(As);
        const unsigned Ws_u = smem_u32(Ws);

        #pragma unroll
        for (int kk = 0; kk < BK; kk += 16) {
            unsigned af[4][4];
            #pragma unroll
            for (int mi = 0; mi < 4; mi++)
                ldsm4(af[mi], As_u + ((wm + mi * 16 + a_row) * GLD + kk + a_k) * 2);
            #pragma unroll
            for (int np = 0; np < 4; np++) {
                unsigned bf[4];
                ldsm4(bf, Ws_u + ((wn + np * 16 + b_row) * GLD + kk + b_k) * 2);
                #pragma unroll
                for (int mi = 0; mi < 4; mi++) {
                    mma16(acc[mi][2 * np],     af[mi], bf[0], bf[1]);
                    mma16(acc[mi][2 * np + 1], af[mi], bf[2], bf[3]);
                }
            }
        }
    }

    #pragma unroll
    for (int mi = 0; mi < 4; mi++) {
        #pragma unroll
        for (int ni = 0; ni < 8; ni++) {
            int row = bm + wm + mi * 16 + g;
            int col = bn + wn + ni * 8 + 2 * q;
            if (split_heads) {
                int b = row >> 10;
                int s = row & (S_ - 1);
                int h = col >> 6;
                int d = col & (DH_ - 1);
                __half* oh = (__half*)out;
                if (blockIdx.z < 2) {
                    __half* dst = oh + (((size_t)(b * NH_ + h) * S_) + s) * DH_ + d;
                    *reinterpret_cast<__half2*>(dst) =
                        __floats2half2_rn(acc[mi][ni][0], acc[mi][ni][1]);
                    *reinterpret_cast<__half2*>(dst + 8 * DH_) =
                        __floats2half2_rn(acc[mi][ni][2], acc[mi][ni][3]);
                } else {
                    __half* base = oh + ((size_t)(b * NH_ + h) * DH_ + d) * S_ + s;
                    base[0]      = __float2half_rn(acc[mi][ni][0]);
                    base[S_]     = __float2half_rn(acc[mi][ni][1]);
                    base[8]      = __float2half_rn(acc[mi][ni][2]);
                    base[S_ + 8] = __float2half_rn(acc[mi][ni][3]);
                }
            } else {
                float* dst = (float*)out + (size_t)row * N_ + col;
                *reinterpret_cast<float2*>(dst) =
                    make_float2(acc[mi][ni][0], acc[mi][ni][1]);
                *reinterpret_cast<float2*>(dst + 8 * N_) =
                    make_float2(acc[mi][ni][2], acc[mi][ni][3]);
            }
        }
    }
}

// ---------------------------------------------------------------------------
// Flash attention, fp16 mma + ldmatrix, register-resident P, exp2-domain
// softmax (scale/mask pre-multiplied by log2e). launch_bounds(128,3):
// regs 158*128*3 = 60.7K < 64K RF; smem 46KB*3 = 138KB < 228KB -> 3 CTAs/SM.
// ---------------------------------------------------------------------------
constexpr int ALD = 72;
constexpr int AT  = 64 * ALD;
constexpr int ATTN_SMEM = 5 * AT * (int)sizeof(__half);   // 46080 B

__global__ __launch_bounds__(128, 3)
void attn_kernel(const __half* __restrict__ qh, const __half* __restrict__ kh,
                 const __half* __restrict__ vh,
                 const float* __restrict__ maskf,
                 __half* __restrict__ ctx)
{
    extern __shared__ __half smh[];
    __half* QP = smh;            // Q staging only
    __half* Ks = smh + AT;       // [2][64][ALD]
    __half* Vs = smh + 3 * AT;   // [2][64][ALD]  rows = d, cols = key

    const int bh = blockIdx.x;
    const int qt = blockIdx.y;
    const int b  = bh >> 4;
    const int h  = bh & (NH_ - 1);
    const int tid  = threadIdx.x;
    const int w    = tid >> 5;
    const int lane = tid & 31;
    const int g    = lane >> 2;
    const int q    = lane & 3;
    const int r0   = w * 16 + g;

    const int a_row = (lane & 7) + ((lane >> 3) & 1) * 8;
    const int a_k   = (lane >> 4) * 8;
    const int b_row = (lane & 7) + (lane >> 4) * 8;
    const int b_k   = ((lane >> 3) & 1) * 8;

    const __half* Qg = qh + ((size_t)bh * S_ + qt * 64) * DH_;
    const __half* Kg = kh + (size_t)bh * S_ * DH_;
    const __half* Vg = vh + (size_t)bh * DH_ * S_;
    const float* mrow = maskf + b * S_;

    #pragma unroll
    for (int i = 0; i < 4; i++) {
        int idx = tid + i * 128;
        int r = idx >> 3;
        int c = (idx & 7) << 3;
        *reinterpret_cast<uint4*>(QP + r * ALD + c) =
            *reinterpret_cast<const uint4*>(Qg + r * DH_ + c);
    }
    __syncthreads();

    auto kv_load = [&](int st, int kt) {
        #pragma unroll
        for (int i = 0; i < 4; i++) {
            int idx = tid + i * 128;
            int r = idx >> 3;
            int c = (idx & 7) << 3;
            cp16h(Ks + st * AT + r * ALD + c, Kg + (kt * 64 + r) * DH_ + c);
            cp16h(Vs + st * AT + r * ALD + c, Vg + r * S_ + kt * 64 + c);
        }
        cp_commit();
    };
    kv_load(0, 0);

    const unsigned QP_u = smem_u32(QP);

    unsigned qa[4][4];
    #pragma unroll
    for (int ks = 0; ks < 4; ks++)
        ldsm4(qa[ks], QP_u + ((w * 16 + a_row) * ALD + ks * 16 + a_k) * 2);

    float oc[8][4];
    #pragma unroll
    for (int nt = 0; nt < 8; nt++)
        #pragma unroll
        for (int e = 0; e < 4; e++) oc[nt][e] = 0.f;
    float m0 = -CUDART_INF_F, m1 = -CUDART_INF_F;   // log2-domain row maxima
    float l0 = 0.f, l1 = 0.f;

    const float SCALE2 = 0.125f * LOG2E;            // 1/sqrt(64) * log2(e)

    for (int kt = 0; kt < S_ / 64; kt++) {
        const int cur = kt & 1;
        cp_wait_all();
        __syncthreads();
        if (kt + 1 < S_ / 64) kv_load(1 - cur, kt + 1);

        const unsigned Kc_u = smem_u32(Ks + cur * AT);
        const unsigned Vc_u = smem_u32(Vs + cur * AT);

        // S = Q @ K^T
        float sc[8][4];
        #pragma unroll
        for (int nt = 0; nt < 8; nt++)
            #pragma unroll
            for (int e = 0; e < 4; e++) sc[nt][e] = 0.f;
        #pragma unroll
        for (int ks = 0; ks < 4; ks++) {
            #pragma unroll
            for (int np = 0; np < 4; np++) {
                unsigned kf[4];
                ldsm4(kf, Kc_u + ((np * 16 + b_row) * ALD + ks * 16 + b_k) * 2);
                mma16(sc[2 * np],     qa[ks], kf[0], kf[1]);
                mma16(sc[2 * np + 1], qa[ks], kf[2], kf[3]);
            }
        }

        // scale (log2 domain) + additive mask + row max
        float vx0 = -CUDART_INF_F, vx1 = -CUDART_INF_F;
        #pragma unroll
        for (int nt = 0; nt < 8; nt++) {
            float2 mf = *reinterpret_cast<const float2*>(
                mrow + kt * 64 + nt * 8 + 2 * q);
            sc[nt][0] = sc[nt][0] * SCALE2 + mf.x;
            sc[nt][1] = sc[nt][1] * SCALE2 + mf.y;
            sc[nt][2] = sc[nt][2] * SCALE2 + mf.x;
            sc[nt][3] = sc[nt][3] * SCALE2 + mf.y;
            vx0 = fmaxf(vx0, fmaxf(sc[nt][0], sc[nt][1]));
            vx1 = fmaxf(vx1, fmaxf(sc[nt][2], sc[nt][3]));
        }
        vx0 = fmaxf(vx0, __shfl_xor_sync(0xffffffffu, vx0, 1));
        vx0 = fmaxf(vx0, __shfl_xor_sync(0xffffffffu, vx0, 2));
        vx1 = fmaxf(vx1, __shfl_xor_sync(0xffffffffu, vx1, 1));
        vx1 = fmaxf(vx1, __shfl_xor_sync(0xffffffffu, vx1, 2));

        float mn0 = fmaxf(m0, vx0), mn1 = fmaxf(m1, vx1);
        float al0 = exp2f(m0 - mn0), al1 = exp2f(m1 - mn1);

        // exp2 in place (P stays in sc registers)
        float ps0 = 0.f, ps1 = 0.f;
        #pragma unroll
        for (int nt = 0; nt < 8; nt++) {
            sc[nt][0] = exp2f(sc[nt][0] - mn0);
            sc[nt][1] = exp2f(sc[nt][1] - mn0);
            sc[nt][2] = exp2f(sc[nt][2] - mn1);
            sc[nt][3] = exp2f(sc[nt][3] - mn1);
            ps0 += sc[nt][0] + sc[nt][1];
            ps1 += sc[nt][2] + sc[nt][3];
        }
        ps0 += __shfl_xor_sync(0xffffffffu, ps0, 1);
        ps0 += __shfl_xor_sync(0xffffffffu, ps0, 2);
        ps1 += __shfl_xor_sync(0xffffffffu, ps1, 1);
        ps1 += __shfl_xor_sync(0xffffffffu, ps1, 2);
        l0 = l0 * al0 + ps0;
        l1 = l1 * al1 + ps1;
        m0 = mn0; m1 = mn1;

        #pragma unroll
        for (int nt = 0; nt < 8; nt++) {
            oc[nt][0] *= al0; oc[nt][1] *= al0;
            oc[nt][2] *= al1; oc[nt][3] *= al1;
        }

        // O += P @ V  — P fragments packed directly from sc registers
        #pragma unroll
        for (int ks = 0; ks < 4; ks++) {
            unsigned pa[4];
            pa[0] = packh2(sc[2 * ks][0],     sc[2 * ks][1]);
            pa[1] = packh2(sc[2 * ks][2],     sc[2 * ks][3]);
            pa[2] = packh2(sc[2 * ks + 1][0], sc[2 * ks + 1][1]);
            pa[3] = packh2(sc[2 * ks + 1][2], sc[2 * ks + 1][3]);
            #pragma unroll
            for (int np = 0; np < 4; np++) {
                unsigned vf[4];
                ldsm4(vf, Vc_u + ((np * 16 + b_row) * ALD + ks * 16 + b_k) * 2);
                mma16(oc[2 * np],     pa, vf[0], vf[1]);
                mma16(oc[2 * np + 1], pa, vf[2], vf[3]);
            }
        }
    }

    // Normalize + write merged ctx [B,S,H] (half)
    const float inv0 = 1.f / l0;
    const float inv1 = 1.f / l1;
    __half* dst0 = ctx + ((size_t)(b * S_ + qt * 64 + r0)) * H_ + h * DH_;
    __half* dst1 = dst0 + 8 * H_;
    #pragma unroll
    for (int nt = 0; nt < 8; nt++) {
        *reinterpret_cast<__half2*>(dst0 + nt * 8 + 2 * q) =
            __floats2half2_rn(oc[nt][0] * inv0, oc[nt][1] * inv0);
        *reinterpret_cast<__half2*>(dst1 + nt * 8 + 2 * q) =
            __floats2half2_rn(oc[nt][2] * inv1, oc[nt][3] * inv1);
    }
}

// ---------------------------------------------------------------------------
// Launch
// ---------------------------------------------------------------------------
extern "C" void kernel_launch(void* const* d_in, const int* in_sizes, int n_in,
                              void* d_out, int out_size)
{
    const float* v  = (const float*)d_in[0];
    const float* k  = (const float*)d_in[1];
    const float* q  = (const float*)d_in[2];
    const unsigned char* mask_raw = (const unsigned char*)d_in[3];
    const float* Wq = (const float*)d_in[4];
    const float* bq = (const float*)d_in[5];
    const float* Wk = (const float*)d_in[6];
    const float* bk = (const float*)d_in[7];
    const float* Wv = (const float*)d_in[8];
    const float* bv = (const float*)d_in[9];
    const float* Wm = (const float*)d_in[10];
    const float* bm = (const float*)d_in[11];
    float* out = (float*)d_out;

    __half *qh, *kh, *vh, *ctx;
    __half *qc, *kc, *vc, *wq, *wk, *wv, *wm;
    float *mnorm;
    cudaGetSymbolAddress((void**)&qh,  g_qh);
    cudaGetSymbolAddress((void**)&kh,  g_kh);
    cudaGetSymbolAddress((void**)&vh,  g_vh);
    cudaGetSymbolAddress((void**)&ctx, g_ctx);
    cudaGetSymbolAddress((void**)&mnorm, g_maskf);
    cudaGetSymbolAddress((void**)&qc, g_qc);
    cudaGetSymbolAddress((void**)&kc, g_kc);
    cudaGetSymbolAddress((void**)&vc, g_vc);
    cudaGetSymbolAddress((void**)&wq, g_wq);
    cudaGetSymbolAddress((void**)&wk, g_wk);
    cudaGetSymbolAddress((void**)&wv, g_wv);
    cudaGetSymbolAddress((void**)&wm, g_wm);

    cudaFuncSetAttribute(gemm3_kernel, cudaFuncAttributeMaxDynamicSharedMemorySize,
                         GEMM_SMEM);
    cudaFuncSetAttribute(attn_kernel, cudaFuncAttributeMaxDynamicSharedMemorySize,
                         ATTN_SMEM);

    // 0) mask (log2 domain) + fused fp16 conversion of all GEMM inputs
    mask_norm_kernel<<<1, 256>>>(mask_raw, mnorm);
    cvt_all_kernel<<<(CVT_TOTAL + 255) / 256, 256>>>(q, k, v, Wq, Wk, Wv, Wm,
                                                     qc, kc, vc, wq, wk, wv, wm);

    // 1) fused QKV projections (Q,K split-head; V split-head transposed)
    dim3 gproj(N_ / BM, M_ / BM, 3);
    gemm3_kernel<<<gproj, GEMM_THREADS, GEMM_SMEM>>>(qc, wq, bq, qh,
                                                     kc, wk, bk, kh,
                                                     vc, wv, bv, vh, 1);

    // 2) attention -> merged ctx (half)
    dim3 gattn(B_ * NH_, S_ / 64);
    attn_kernel<<<gattn, 128, ATTN_SMEM>>>(qh, kh, vh, mnorm, ctx);

    // 3) output projection -> d_out (fp32)
    dim3 gout(N_ / BM, M_ / BM, 1);
    gemm3_kernel<<<gout, GEMM_THREADS, GEMM_SMEM>>>(ctx, wm, bm, out,
                                                    ctx, wm, bm, out,
                                                    ctx, wm, bm, out, 0);
}

// round 17
// speedup vs baseline: 4.5786x; 1.0019x over previous
#include <cuda_runtime.h>
#include <cuda_fp16.h>
#include <math_constants.h>

#define B_   8
#define S_   1024
#define H_   1024
#define NH_  16
#define DH_  64
#define M_   (B_ * S_)   // 8192
#define N_   H_
#define K_   H_

// Scratch: device globals (no cudaMalloc allowed)
__device__ __half g_qh[B_ * NH_ * S_ * DH_];   // [B,NH,S,DH]
__device__ __half g_kh[B_ * NH_ * S_ * DH_];   // [B,NH,S,DH]
__device__ __half g_vh[B_ * NH_ * DH_ * S_];   // [B,NH,DH,S]  (transposed!)
__device__ __half g_ctx[B_ * S_ * H_];         // merged [B,S,H]
__device__ float  g_maskf[B_ * S_];            // additive mask in LOG2 domain
// fp16 copies of inputs
__device__ __half g_qc[M_ * K_];
__device__ __half g_kc[M_ * K_];
__device__ __half g_vc[M_ * K_];
__device__ __half g_wq[H_ * H_];
__device__ __half g_wk[H_ * H_];
__device__ __half g_wv[H_ * H_];
__device__ __half g_wm[H_ * H_];

#define LOG2E 1.4426950408889634f

// ---------------------------------------------------------------------------
// PTX helpers (mma.sync / cp.async / ldmatrix only — NO tcgen05 on this
// toolchain: PTX targets sm_103 which rejects accelerated-feature instrs)
// ---------------------------------------------------------------------------
__device__ __forceinline__ void mma16(float c[4], const unsigned a[4],
                                      unsigned b0, unsigned b1) {
    asm volatile(
        "mma.sync.aligned.m16n8k16.row.col.f32.f16.f16.f32 "
        "{%0,%1,%2,%3}, {%4,%5,%6,%7}, {%8,%9}, {%0,%1,%2,%3};"
        : "+f"(c[0]), "+f"(c[1]), "+f"(c[2]), "+f"(c[3])
        : "r"(a[0]), "r"(a[1]), "r"(a[2]), "r"(a[3]), "r"(b0), "r"(b1));
}
__device__ __forceinline__ void ldsm4(unsigned r[4], unsigned sa) {
    asm volatile("ldmatrix.sync.aligned.m8n8.x4.shared.b16 {%0,%1,%2,%3}, [%4];"
                 : "=r"(r[0]), "=r"(r[1]), "=r"(r[2]), "=r"(r[3]) : "r"(sa));
}
__device__ __forceinline__ void cp16h(__half* smem, const __half* g) {
    unsigned s = (unsigned)__cvta_generic_to_shared(smem);
    asm volatile("cp.async.cg.shared.global [%0], [%1], 16;" :: "r"(s), "l"(g)
                 : "memory");
}
__device__ __forceinline__ void cp_commit() {
    asm volatile("cp.async.commit_group;" ::: "memory");
}
__device__ __forceinline__ void cp_wait_all() {
    asm volatile("cp.async.wait_group 0;" ::: "memory");
}
__device__ __forceinline__ unsigned smem_u32(const void* p) {
    return (unsigned)__cvta_generic_to_shared(p);
}
__device__ __forceinline__ unsigned packh2(float a, float b) {
    __half2 h = __floats2half2_rn(a, b);
    return *reinterpret_cast<unsigned*>(&h);
}

// ---------------------------------------------------------------------------
// Fused fp32 -> fp16 conversion for all 7 tensors (one launch).
// ---------------------------------------------------------------------------
constexpr int BIG4   = (M_ * K_) / 4;
constexpr int SMALL4 = (H_ * H_) / 4;
constexpr int CVT_TOTAL = 3 * BIG4 + 4 * SMALL4;

__global__ void cvt_all_kernel(const float* __restrict__ q,
                               const float* __restrict__ k,
                               const float* __restrict__ v,
                               const float* __restrict__ wq,
                               const float* __restrict__ wk,
                               const float* __restrict__ wv,
                               const float* __restrict__ wm,
                               __half* __restrict__ qo, __half* __restrict__ ko,
                               __half* __restrict__ vo, __half* __restrict__ wqo,
                               __half* __restrict__ wko, __half* __restrict__ wvo,
                               __half* __restrict__ wmo)
{
    int i = blockIdx.x * blockDim.x + threadIdx.x;
    if (i >= CVT_TOTAL) return;
    const float* in; __half* out; int off;
    if (i < 3 * BIG4) {
        int s = i / BIG4;
        off = i - s * BIG4;
        in  = (s == 0) ? q : (s == 1) ? k : v;
        out = (s == 0) ? qo : (s == 1) ? ko : vo;
    } else {
        int j = i - 3 * BIG4;
        int s = j / SMALL4;
        off = j - s * SMALL4;
        in  = (s == 0) ? wq : (s == 1) ? wk : (s == 2) ? wv : wm;
        out = (s == 0) ? wqo : (s == 1) ? wko : (s == 2) ? wvo : wmo;
    }
    float4 vv = reinterpret_cast<const float4*>(in)[off];
    __half2 h0 = __floats2half2_rn(vv.x, vv.y);
    __half2 h1 = __floats2half2_rn(vv.z, vv.w);
    uint2 o;
    o.x = *reinterpret_cast<unsigned*>(&h0);
    o.y = *reinterpret_cast<unsigned*>(&h1);
    reinterpret_cast<uint2*>(out)[off] = o;
}

// ---------------------------------------------------------------------------
// Mask dtype detection + normalization -> additive mask in LOG2 domain.
// ---------------------------------------------------------------------------
__global__ void mask_norm_kernel(const unsigned char* __restrict__ raw,
                                 float* __restrict__ outm)
{
    __shared__ int cnt[4];
    const int tid = threadIdx.x;
    if (tid < 4) cnt[tid] = 0;
    __syncthreads();

    int loc[4] = {0, 0, 0, 0};
    for (int i = tid; i < B_ * S_; i += blockDim.x)
        if (raw[i]) loc[i & 3]++;
    #pragma unroll
    for (int r = 0; r < 4; r++)
        if (loc[r]) atomicAdd(&cnt[r], loc[r]);
    __syncthreads();

    const float MASKVAL = -LOG2E * 1e9f;
    const int c0 = cnt[0], c1 = cnt[1], c2 = cnt[2], c3 = cnt[3];
    int mode;
    if (c0 > 0 && c1 == 0 && c2 == 0 && c3 == 0)       mode = 1;
    else if (c0 == 0 && c1 == 0 && (c2 > 0 || c3 > 0)) mode = 2;
    else                                               mode = 0;

    if (mode == 0) {
        for (int i = tid; i < B_ * S_; i += blockDim.x)
            outm[i] = raw[i] ? MASKVAL : 0.f;
    } else if (mode == 1) {
        const int* p = (const int*)raw;
        for (int i = tid; i < B_ * S_; i += blockDim.x)
            outm[i] = p[i] ? MASKVAL : 0.f;
    } else {
        const float* p = (const float*)raw;
        for (int i = tid; i < B_ * S_; i += blockDim.x)
            outm[i] = (p[i] != 0.0f) ? MASKVAL : 0.f;
    }
}

// ---------------------------------------------------------------------------
// GEMM: C = A[M,K] @ W[N,K]^T + bias, fp16 mma.m16n8k16, fp32 accumulate.
// (unchanged — control)
// ---------------------------------------------------------------------------
constexpr int BM = 128, BN = 128, BK = 64;
constexpr int GEMM_THREADS = 128;
constexpr int GLD = 72;
constexpr int STG_HALFS = 2 * BM * GLD;
constexpr int GEMM_SMEM  = 2 * STG_HALFS * (int)sizeof(__half);  // 73728 B

__global__ __launch_bounds__(GEMM_THREADS, 2)
void gemm3_kernel(const __half* __restrict__ A0, const __half* __restrict__ W0,
                  const float* __restrict__ b0, void* __restrict__ o0,
                  const __half* __restrict__ A1, const __half* __restrict__ W1,
                  const float* __restrict__ b1, void* __restrict__ o1,
                  const __half* __restrict__ A2, const __half* __restrict__ W2,
                  const float* __restrict__ b2, void* __restrict__ o2,
                  int split_heads)
{
    extern __shared__ __half gsmh[];

    const __half* A; const __half* W; const float* bias; void* out;
    if (blockIdx.z == 0)      { A = A0; W = W0; bias = b0; out = o0; }
    else if (blockIdx.z == 1) { A = A1; W = W1; bias = b1; out = o1; }
    else                      { A = A2; W = W2; bias = b2; out = o2; }

    const int tid  = threadIdx.x;
    const int warp = tid >> 5;
    const int lane = tid & 31;
    const int g    = lane >> 2;
    const int q    = lane & 3;
    const int wm   = (warp >> 1) * 64;
    const int wn   = (warp & 1) * 64;
    const int bm   = blockIdx.y * BM;
    const int bn   = blockIdx.x * BN;

    const int a_row = (lane & 7) + ((lane >> 3) & 1) * 8;
    const int a_k   = (lane >> 4) * 8;
    const int b_row = (lane & 7) + (lane >> 4) * 8;
    const int b_k   = ((lane >> 3) & 1) * 8;

    float acc[4][8][4];
    #pragma unroll
    for (int ni = 0; ni < 8; ni++) {
        float2 bv = *reinterpret_cast<const float2*>(bias + bn + wn + ni * 8 + 2 * q);
        #pragma unroll
        for (int mi = 0; mi < 4; mi++) {
            acc[mi][ni][0] = bv.x; acc[mi][ni][1] = bv.y;
            acc[mi][ni][2] = bv.x; acc[mi][ni][3] = bv.y;
        }
    }

    const __half* Ap = A + (size_t)bm * K_;
    const __half* Wp = W + (size_t)bn * K_;

    auto preload = [&](int st, int k0) {
        __half* As = gsmh + st * STG_HALFS;
        __half* Ws = As + BM * GLD;
        #pragma unroll
        for (int i = 0; i < 8; i++) {
            int idx = tid + i * GEMM_THREADS;
            int r = idx >> 3;
            int c = (idx & 7) << 3;
            cp16h(As + r * GLD + c, Ap + r * K_ + k0 + c);
            cp16h(Ws + r * GLD + c, Wp + r * K_ + k0 + c);
        }
        cp_commit();
    };

    preload(0, 0);

    for (int it = 0; it < K_ / BK; it++) {
        int cur = it & 1;
        cp_wait_all();
        __syncthreads();
        if (it + 1 < K_ / BK) preload(1 - cur, (it + 1) * BK);

        const __half* As = gsmh + cur * STG_HALFS;
        const __half* Ws = As + BM * GLD;
        const unsigned As_u = smem_u32(As);
        const unsigned Ws_u = smem_u32(Ws);

        #pragma unroll
        for (int kk = 0; kk < BK; kk += 16) {
            unsigned af[4][4];
            #pragma unroll
            for (int mi = 0; mi < 4; mi++)
                ldsm4(af[mi], As_u + ((wm + mi * 16 + a_row) * GLD + kk + a_k) * 2);
            #pragma unroll
            for (int np = 0; np < 4; np++) {
                unsigned bf[4];
                ldsm4(bf, Ws_u + ((wn + np * 16 + b_row) * GLD + kk + b_k) * 2);
                #pragma unroll
                for (int mi = 0; mi < 4; mi++) {
                    mma16(acc[mi][2 * np],     af[mi], bf[0], bf[1]);
                    mma16(acc[mi][2 * np + 1], af[mi], bf[2], bf[3]);
                }
            }
        }
    }

    #pragma unroll
    for (int mi = 0; mi < 4; mi++) {
        #pragma unroll
        for (int ni = 0; ni < 8; ni++) {
            int row = bm + wm + mi * 16 + g;
            int col = bn + wn + ni * 8 + 2 * q;
            if (split_heads) {
                int b = row >> 10;
                int s = row & (S_ - 1);
                int h = col >> 6;
                int d = col & (DH_ - 1);
                __half* oh = (__half*)out;
                if (blockIdx.z < 2) {
                    __half* dst = oh + (((size_t)(b * NH_ + h) * S_) + s) * DH_ + d;
                    *reinterpret_cast<__half2*>(dst) =
                        __floats2half2_rn(acc[mi][ni][0], acc[mi][ni][1]);
                    *reinterpret_cast<__half2*>(dst + 8 * DH_) =
                        __floats2half2_rn(acc[mi][ni][2], acc[mi][ni][3]);
                } else {
                    __half* base = oh + ((size_t)(b * NH_ + h) * DH_ + d) * S_ + s;
                    base[0]      = __float2half_rn(acc[mi][ni][0]);
                    base[S_]     = __float2half_rn(acc[mi][ni][1]);
                    base[8]      = __float2half_rn(acc[mi][ni][2]);
                    base[S_ + 8] = __float2half_rn(acc[mi][ni][3]);
                }
            } else {
                float* dst = (float*)out + (size_t)row * N_ + col;
                *reinterpret_cast<float2*>(dst) =
                    make_float2(acc[mi][ni][0], acc[mi][ni][1]);
                *reinterpret_cast<float2*>(dst + 8 * N_) =
                    make_float2(acc[mi][ni][2], acc[mi][ni][3]);
            }
        }
    }
}

// ---------------------------------------------------------------------------
// Flash attention: 128-row Q tile, 256 threads / 8 warps (warp w owns rows
// [16w,16w+16)), register-resident P, exp2 softmax. K/V tiles now serve 2x
// the Q rows -> half the KV global+LDSM traffic per FLOP.
// smem: Q 128x72 + 2x(64x72) K + 2x(64x72) V = 55296 B.
// ---------------------------------------------------------------------------
constexpr int ALD = 72;
constexpr int AQ  = 128 * ALD;               // Q staging (halves)
constexpr int AT  = 64 * ALD;                // K/V tile (halves)
constexpr int ATTN_THREADS = 256;
constexpr int ATTN_SMEM = (AQ + 4 * AT) * (int)sizeof(__half);   // 55296 B

__global__ __launch_bounds__(ATTN_THREADS)
void attn_kernel(const __half* __restrict__ qh, const __half* __restrict__ kh,
                 const __half* __restrict__ vh,
                 const float* __restrict__ maskf,
                 __half* __restrict__ ctx)
{
    extern __shared__ __half smh[];
    __half* QP = smh;            // Q staging (128 rows)
    __half* Ks = smh + AQ;       // [2][64][ALD]
    __half* Vs = smh + AQ + 2 * AT;   // [2][64][ALD]  rows = d, cols = key

    const int bh = blockIdx.x;
    const int qt = blockIdx.y;           // 128-row Q tile index (0..7)
    const int b  = bh >> 4;
    const int h  = bh & (NH_ - 1);
    const int tid  = threadIdx.x;
    const int w    = tid >> 5;           // 0..7
    const int lane = tid & 31;
    const int g    = lane >> 2;
    const int q    = lane & 3;
    const int r0   = w * 16 + g;         // Q row within 128-row tile

    const int a_row = (lane & 7) + ((lane >> 3) & 1) * 8;
    const int a_k   = (lane >> 4) * 8;
    const int b_row = (lane & 7) + (lane >> 4) * 8;
    const int b_k   = ((lane >> 3) & 1) * 8;

    const __half* Qg = qh + ((size_t)bh * S_ + qt * 128) * DH_;
    const __half* Kg = kh + (size_t)bh * S_ * DH_;
    const __half* Vg = vh + (size_t)bh * DH_ * S_;
    const float* mrow = maskf + b * S_;

    // Q stage: 128 rows x 8 chunks = 1024 chunks, 256 threads, 4 iters
    #pragma unroll
    for (int i = 0; i < 4; i++) {
        int idx = tid + i * ATTN_THREADS;
        int r = idx >> 3;
        int c = (idx & 7) << 3;
        *reinterpret_cast<uint4*>(QP + r * ALD + c) =
            *reinterpret_cast<const uint4*>(Qg + r * DH_ + c);
    }
    __syncthreads();

    // KV tile: 64 rows x 8 chunks = 512 chunks, 256 threads, 2 iters
    auto kv_load = [&](int st, int kt) {
        #pragma unroll
        for (int i = 0; i < 2; i++) {
            int idx = tid + i * ATTN_THREADS;
            int r = idx >> 3;
            int c = (idx & 7) << 3;
            cp16h(Ks + st * AT + r * ALD + c, Kg + (kt * 64 + r) * DH_ + c);
            cp16h(Vs + st * AT + r * ALD + c, Vg + r * S_ + kt * 64 + c);
        }
        cp_commit();
    };
    kv_load(0, 0);

    const unsigned QP_u = smem_u32(QP);

    unsigned qa[4][4];
    #pragma unroll
    for (int ks = 0; ks < 4; ks++)
        ldsm4(qa[ks], QP_u + ((w * 16 + a_row) * ALD + ks * 16 + a_k) * 2);

    float oc[8][4];
    #pragma unroll
    for (int nt = 0; nt < 8; nt++)
        #pragma unroll
        for (int e = 0; e < 4; e++) oc[nt][e] = 0.f;
    float m0 = -CUDART_INF_F, m1 = -CUDART_INF_F;
    float l0 = 0.f, l1 = 0.f;

    const float SCALE2 = 0.125f * LOG2E;

    for (int kt = 0; kt < S_ / 64; kt++) {
        const int cur = kt & 1;
        cp_wait_all();
        __syncthreads();
        if (kt + 1 < S_ / 64) kv_load(1 - cur, kt + 1);

        const unsigned Kc_u = smem_u32(Ks + cur * AT);
        const unsigned Vc_u = smem_u32(Vs + cur * AT);

        // S = Q @ K^T
        float sc[8][4];
        #pragma unroll
        for (int nt = 0; nt < 8; nt++)
            #pragma unroll
            for (int e = 0; e < 4; e++) sc[nt][e] = 0.f;
        #pragma unroll
        for (int ks = 0; ks < 4; ks++) {
            #pragma unroll
            for (int np = 0; np < 4; np++) {
                unsigned kf[4];
                ldsm4(kf, Kc_u + ((np * 16 + b_row) * ALD + ks * 16 + b_k) * 2);
                mma16(sc[2 * np],     qa[ks], kf[0], kf[1]);
                mma16(sc[2 * np + 1], qa[ks], kf[2], kf[3]);
            }
        }

        // scale (log2 domain) + additive mask + row max
        float vx0 = -CUDART_INF_F, vx1 = -CUDART_INF_F;
        #pragma unroll
        for (int nt = 0; nt < 8; nt++) {
            float2 mf = *reinterpret_cast<const float2*>(
                mrow + kt * 64 + nt * 8 + 2 * q);
            sc[nt][0] = sc[nt][0] * SCALE2 + mf.x;
            sc[nt][1] = sc[nt][1] * SCALE2 + mf.y;
            sc[nt][2] = sc[nt][2] * SCALE2 + mf.x;
            sc[nt][3] = sc[nt][3] * SCALE2 + mf.y;
            vx0 = fmaxf(vx0, fmaxf(sc[nt][0], sc[nt][1]));
            vx1 = fmaxf(vx1, fmaxf(sc[nt][2], sc[nt][3]));
        }
        vx0 = fmaxf(vx0, __shfl_xor_sync(0xffffffffu, vx0, 1));
        vx0 = fmaxf(vx0, __shfl_xor_sync(0xffffffffu, vx0, 2));
        vx1 = fmaxf(vx1, __shfl_xor_sync(0xffffffffu, vx1, 1));
        vx1 = fmaxf(vx1, __shfl_xor_sync(0xffffffffu, vx1, 2));

        float mn0 = fmaxf(m0, vx0), mn1 = fmaxf(m1, vx1);
        float al0 = exp2f(m0 - mn0), al1 = exp2f(m1 - mn1);

        float ps0 = 0.f, ps1 = 0.f;
        #pragma unroll
        for (int nt = 0; nt < 8; nt++) {
            sc[nt][0] = exp2f(sc[nt][0] - mn0);
            sc[nt][1] = exp2f(sc[nt][1] - mn0);
            sc[nt][2] = exp2f(sc[nt][2] - mn1);
            sc[nt][3] = exp2f(sc[nt][3] - mn1);
            ps0 += sc[nt][0] + sc[nt][1];
            ps1 += sc[nt][2] + sc[nt][3];
        }
        ps0 += __shfl_xor_sync(0xffffffffu, ps0, 1);
        ps0 += __shfl_xor_sync(0xffffffffu, ps0, 2);
        ps1 += __shfl_xor_sync(0xffffffffu, ps1, 1);
        ps1 += __shfl_xor_sync(0xffffffffu, ps1, 2);
        l0 = l0 * al0 + ps0;
        l1 = l1 * al1 + ps1;
        m0 = mn0; m1 = mn1;

        #pragma unroll
        for (int nt = 0; nt < 8; nt++) {
            oc[nt][0] *= al0; oc[nt][1] *= al0;
            oc[nt][2] *= al1; oc[nt][3] *= al1;
        }

        // O += P @ V  — P fragments packed directly from sc registers
        #pragma unroll
        for (int ks = 0; ks < 4; ks++) {
            unsigned pa[4];
            pa[0] = packh2(sc[2 * ks][0],     sc[2 * ks][1]);
            pa[1] = packh2(sc[2 * ks][2],     sc[2 * ks][3]);
            pa[2] = packh2(sc[2 * ks + 1][0], sc[2 * ks + 1][1]);
            pa[3] = packh2(sc[2 * ks + 1][2], sc[2 * ks + 1][3]);
            #pragma unroll
            for (int np = 0; np < 4; np++) {
                unsigned vf[4];
                ldsm4(vf, Vc_u + ((np * 16 + b_row) * ALD + ks * 16 + b_k) * 2);
                mma16(oc[2 * np],     pa, vf[0], vf[1]);
                mma16(oc[2 * np + 1], pa, vf[2], vf[3]);
            }
        }
    }

    // Normalize + write merged ctx [B,S,H] (half)
    const float inv0 = 1.f / l0;
    const float inv1 = 1.f / l1;
    __half* dst0 = ctx + ((size_t)(b * S_ + qt * 128 + r0)) * H_ + h * DH_;
    __half* dst1 = dst0 + 8 * H_;
    #pragma unroll
    for (int nt = 0; nt < 8; nt++) {
        *reinterpret_cast<__half2*>(dst0 + nt * 8 + 2 * q) =
            __floats2half2_rn(oc[nt][0] * inv0, oc[nt][1] * inv0);
        *reinterpret_cast<__half2*>(dst1 + nt * 8 + 2 * q) =
            __floats2half2_rn(oc[nt][2] * inv1, oc[nt][3] * inv1);
    }
}

// ---------------------------------------------------------------------------
// Launch
// ---------------------------------------------------------------------------
extern "C" void kernel_launch(void* const* d_in, const int* in_sizes, int n_in,
                              void* d_out, int out_size)
{
    const float* v  = (const float*)d_in[0];
    const float* k  = (const float*)d_in[1];
    const float* q  = (const float*)d_in[2];
    const unsigned char* mask_raw = (const unsigned char*)d_in[3];
    const float* Wq = (const float*)d_in[4];
    const float* bq = (const float*)d_in[5];
    const float* Wk = (const float*)d_in[6];
    const float* bk = (const float*)d_in[7];
    const float* Wv = (const float*)d_in[8];
    const float* bv = (const float*)d_in[9];
    const float* Wm = (const float*)d_in[10];
    const float* bm = (const float*)d_in[11];
    float* out = (float*)d_out;

    __half *qh, *kh, *vh, *ctx;
    __half *qc, *kc, *vc, *wq, *wk, *wv, *wm;
    float *mnorm;
    cudaGetSymbolAddress((void**)&qh,  g_qh);
    cudaGetSymbolAddress((void**)&kh,  g_kh);
    cudaGetSymbolAddress((void**)&vh,  g_vh);
    cudaGetSymbolAddress((void**)&ctx, g_ctx);
    cudaGetSymbolAddress((void**)&mnorm, g_maskf);
    cudaGetSymbolAddress((void**)&qc, g_qc);
    cudaGetSymbolAddress((void**)&kc, g_kc);
    cudaGetSymbolAddress((void**)&vc, g_vc);
    cudaGetSymbolAddress((void**)&wq, g_wq);
    cudaGetSymbolAddress((void**)&wk, g_wk);
    cudaGetSymbolAddress((void**)&wv, g_wv);
    cudaGetSymbolAddress((void**)&wm, g_wm);

    cudaFuncSetAttribute(gemm3_kernel, cudaFuncAttributeMaxDynamicSharedMemorySize,
                         GEMM_SMEM);
    cudaFuncSetAttribute(attn_kernel, cudaFuncAttributeMaxDynamicSharedMemorySize,
                         ATTN_SMEM);

    // 0) mask (log2 domain) + fused fp16 conversion of all GEMM inputs
    mask_norm_kernel<<<1, 256>>>(mask_raw, mnorm);
    cvt_all_kernel<<<(CVT_TOTAL + 255) / 256, 256>>>(q, k, v, Wq, Wk, Wv, Wm,
                                                     qc, kc, vc, wq, wk, wv, wm);

    // 1) fused QKV projections (Q,K split-head; V split-head transposed)
    dim3 gproj(N_ / BM, M_ / BM, 3);
    gemm3_kernel<<<gproj, GEMM_THREADS, GEMM_SMEM>>>(qc, wq, bq, qh,
                                                     kc, wk, bk, kh,
                                                     vc, wv, bv, vh, 1);

    // 2) attention -> merged ctx (half), 128-row Q tiles
    dim3 gattn(B_ * NH_, S_ / 128);
    attn_kernel<<<gattn, ATTN_THREADS, ATTN_SMEM>>>(qh, kh, vh, mnorm, ctx);

    // 3) output projection -> d_out (fp32)
    dim3 gout(N_ / BM, M_ / BM, 1);
    gemm3_kernel<<<gout, GEMM_THREADS, GEMM_SMEM>>>(ctx, wm, bm, out,
                                                    ctx, wm, bm, out,
                                                    ctx, wm, bm, out, 0);
}